// round 2
// baseline (speedup 1.0000x reference)
#include <cuda_runtime.h>
#include <math.h>

#define ROWS 4096      // BT * L
#define LSEQ 2048
#define DM   1024
#define DI   2048
#define NH   32
#define DS   64
#define CD   2176      // conv dim = DI + 2*DS
#define DIP  4256      // in_proj out dim
#define DFF  4096

// ---------------- scratch (device globals; no runtime allocation) -------------
__device__ float g_hln[(size_t)ROWS * DM];
__device__ float g_zx [(size_t)ROWS * DIP];
__device__ float g_xbc[(size_t)ROWS * CD];
__device__ float g_dt [(size_t)ROWS * NH];
__device__ float g_y  [(size_t)ROWS * DI];
__device__ float g_x1 [(size_t)ROWS * DM];
__device__ float g_h2 [(size_t)ROWS * DM];
__device__ float g_mid[(size_t)ROWS * DFF];

// ---------------- helpers -----------------------------------------------------
__device__ __forceinline__ void blockReduceSum2(float &a, float &b) {
    __shared__ float sa[8], sb2[8];
    int lane = threadIdx.x & 31, w = threadIdx.x >> 5;
#pragma unroll
    for (int o = 16; o > 0; o >>= 1) {
        a += __shfl_xor_sync(0xffffffffu, a, o);
        b += __shfl_xor_sync(0xffffffffu, b, o);
    }
    if (lane == 0) { sa[w] = a; sb2[w] = b; }
    __syncthreads();
    a = sa[lane & 7]; b = sb2[lane & 7];
#pragma unroll
    for (int o = 4; o > 0; o >>= 1) {
        a += __shfl_xor_sync(0xffffffffu, a, o);
        b += __shfl_xor_sync(0xffffffffu, b, o);
    }
}

// ---------------- layernorm ----------------------------------------------------
__global__ void ln_kernel(const float* __restrict__ in, const float* __restrict__ w,
                          const float* __restrict__ bias, float* __restrict__ outp)
{
    int r = blockIdx.x, tid = threadIdx.x;
    const float* xr = in + (size_t)r * DM;
    float v[4]; float s = 0.f, sq = 0.f;
#pragma unroll
    for (int i = 0; i < 4; i++) {
        v[i] = xr[tid + i * 256];
        s += v[i];
        sq = fmaf(v[i], v[i], sq);
    }
    blockReduceSum2(s, sq);
    float mu  = s * (1.f / DM);
    float var = sq * (1.f / DM) - mu * mu;
    float inv = rsqrtf(var + 1e-5f);
    float* orow = outp + (size_t)r * DM;
#pragma unroll
    for (int i = 0; i < 4; i++) {
        int c = tid + i * 256;
        orow[c] = (v[i] - mu) * inv * w[c] + bias[c];
    }
}

// ---------------- generic fp32 SGEMM: C[M,N] = A[M,K] * B[N,K]^T + epilogue ----
// EPI: 0 = none, 1 = +bias then exact GELU, 2 = +bias +res, 3 = +res
template<int EPI>
__global__ void __launch_bounds__(256, 2)
sgemm_kernel(const float* __restrict__ A, const float* __restrict__ B,
             float* __restrict__ C, int M, int N, int K,
             const float* __restrict__ bias, const float* __restrict__ res)
{
    __shared__ float As[16][132];
    __shared__ float Bs[16][132];
    const int tid = threadIdx.x;
    const int bm = blockIdx.y;
    const int bn = blockIdx.x;
    const int tx = tid & 15;
    const int ty = tid >> 4;
    const int lr = tid >> 2;            // 0..63
    const int lk = (tid & 3) * 4;       // 0,4,8,12

    const float* Ag = A + (size_t)(bm * 128 + lr) * K + lk;
    const int nrow0 = bn * 128 + lr;
    const float* Bg = B + (size_t)nrow0 * K + lk;
    const bool gb0 = (nrow0 < N);
    const bool gb1 = (nrow0 + 64 < N);

    float acc[8][8];
#pragma unroll
    for (int i = 0; i < 8; i++)
#pragma unroll
        for (int j = 0; j < 8; j++) acc[i][j] = 0.f;

    for (int k0 = 0; k0 < K; k0 += 16) {
        float4 a0 = *(const float4*)(Ag + k0);
        float4 a1 = *(const float4*)(Ag + (size_t)64 * K + k0);
        float4 b0 = gb0 ? *(const float4*)(Bg + k0) : make_float4(0.f, 0.f, 0.f, 0.f);
        float4 b1 = gb1 ? *(const float4*)(Bg + (size_t)64 * K + k0) : make_float4(0.f, 0.f, 0.f, 0.f);

        As[lk + 0][lr] = a0.x; As[lk + 1][lr] = a0.y; As[lk + 2][lr] = a0.z; As[lk + 3][lr] = a0.w;
        As[lk + 0][lr + 64] = a1.x; As[lk + 1][lr + 64] = a1.y; As[lk + 2][lr + 64] = a1.z; As[lk + 3][lr + 64] = a1.w;
        Bs[lk + 0][lr] = b0.x; Bs[lk + 1][lr] = b0.y; Bs[lk + 2][lr] = b0.z; Bs[lk + 3][lr] = b0.w;
        Bs[lk + 0][lr + 64] = b1.x; Bs[lk + 1][lr + 64] = b1.y; Bs[lk + 2][lr + 64] = b1.z; Bs[lk + 3][lr + 64] = b1.w;
        __syncthreads();

#pragma unroll
        for (int k = 0; k < 16; k++) {
            float ra[8], rb[8];
            *(float4*)&ra[0] = *(const float4*)&As[k][ty * 8];
            *(float4*)&ra[4] = *(const float4*)&As[k][ty * 8 + 4];
            *(float4*)&rb[0] = *(const float4*)&Bs[k][tx * 8];
            *(float4*)&rb[4] = *(const float4*)&Bs[k][tx * 8 + 4];
#pragma unroll
            for (int i = 0; i < 8; i++)
#pragma unroll
                for (int j = 0; j < 8; j++)
                    acc[i][j] = fmaf(ra[i], rb[j], acc[i][j]);
        }
        __syncthreads();
    }

    const int mBase = bm * 128 + ty * 8;
    const int nBase = bn * 128 + tx * 8;
#pragma unroll
    for (int i = 0; i < 8; i++) {
        int m = mBase + i;
        size_t off = (size_t)m * N;
#pragma unroll
        for (int j = 0; j < 8; j++) {
            int n = nBase + j;
            if (n < N) {
                float v = acc[i][j];
                if (EPI == 1) { v += bias[n]; v = 0.5f * v * (1.f + erff(v * 0.70710678118654752f)); }
                else if (EPI == 2) { v += bias[n] + res[off + n]; }
                else if (EPI == 3) { v += res[off + n]; }
                C[off + n] = v;
            }
        }
    }
}

// ---------------- dt = softplus(raw + dt_bias) ---------------------------------
__global__ void dt_kernel(const float* __restrict__ dtb)
{
    int idx = blockIdx.x * 256 + threadIdx.x;
    if (idx >= ROWS * NH) return;
    int r = idx >> 5, h = idx & 31;
    float u = g_zx[(size_t)r * DIP + (DI + CD) + h] + dtb[h];
    g_dt[idx] = (u > 20.f) ? u : log1pf(__expf(u));
}

// ---------------- causal depthwise conv (width 4) + SiLU -----------------------
__global__ void conv_kernel(const float* __restrict__ cw, const float* __restrict__ cb)
{
    int c = blockIdx.x * 128 + threadIdx.x;   // 0..2175
    int row = blockIdx.y;                      // 0..4095
    int l = row & (LSEQ - 1);
    float w0 = cw[c * 4 + 0], w1 = cw[c * 4 + 1], w2 = cw[c * 4 + 2], w3 = cw[c * 4 + 3];
    const float* col = g_zx + (size_t)row * DIP + DI + c;
    float acc = cb[c];
    acc = fmaf(col[0], w3, acc);
    if (l >= 1) acc = fmaf(*(col - DIP),     w2, acc);
    if (l >= 2) acc = fmaf(*(col - 2 * DIP), w1, acc);
    if (l >= 3) acc = fmaf(*(col - 3 * DIP), w0, acc);
    g_xbc[(size_t)row * CD + c] = acc / (1.f + __expf(-acc));
}

// ---------------- sequential SSM scan ------------------------------------------
// grid: 256 blocks = (b:2) x (h:32) x (p-chunk:4 of 16 rows); 128 threads:
// thread = (p_local: tid>>3 in [0,16), q: tid&7 owns 8 states)
__global__ void __launch_bounds__(128)
scan_kernel(const float* __restrict__ A_log, const float* __restrict__ Dvec)
{
    const int blk = blockIdx.x;
    const int b   = blk >> 7;
    const int rem = blk & 127;
    const int h   = rem >> 2;
    const int pc  = rem & 3;
    const int p0  = pc * 16;
    const int tid = threadIdx.x;
    const int q   = tid & 7;
    const int pl  = tid >> 3;

    const float Ah = -__expf(A_log[h]);
    const float Dh = Dvec[h];

    __shared__ float sB[32][64];
    __shared__ float sC[32][64];
    __shared__ float sX[32][16];
    __shared__ float sDt[32];
    __shared__ float sDA[32];
    __shared__ float sY[32][16];

    float hh[8];
#pragma unroll
    for (int i = 0; i < 8; i++) hh[i] = 0.f;

    const size_t rowBase = (size_t)b * LSEQ;

    for (int t0 = 0; t0 < LSEQ; t0 += 32) {
        for (int idx = tid; idx < 2048; idx += 128) {
            int t = idx >> 6, n = idx & 63;
            size_t ro = (rowBase + t0 + t) * (size_t)CD;
            sB[t][n] = g_xbc[ro + DI + n];
            sC[t][n] = g_xbc[ro + DI + DS + n];
        }
        for (int idx = tid; idx < 512; idx += 128) {
            int t = idx >> 4, p = idx & 15;
            sX[t][p] = g_xbc[(rowBase + t0 + t) * (size_t)CD + h * 64 + p0 + p];
        }
        if (tid < 32) {
            float d = g_dt[(rowBase + t0 + tid) * NH + h];
            sDt[tid] = d;
            sDA[tid] = __expf(d * Ah);
        }
        __syncthreads();

#pragma unroll 8
        for (int t = 0; t < 32; t++) {
            float dtv = sDt[t];
            float dav = sDA[t];
            float xv  = sX[t][pl];
            float s   = dtv * xv;
            float4 b0 = *(const float4*)&sB[t][q * 8];
            float4 b1 = *(const float4*)&sB[t][q * 8 + 4];
            float4 c0 = *(const float4*)&sC[t][q * 8];
            float4 c1 = *(const float4*)&sC[t][q * 8 + 4];
            float yv = 0.f;
            hh[0] = fmaf(hh[0], dav, s * b0.x); yv = fmaf(hh[0], c0.x, yv);
            hh[1] = fmaf(hh[1], dav, s * b0.y); yv = fmaf(hh[1], c0.y, yv);
            hh[2] = fmaf(hh[2], dav, s * b0.z); yv = fmaf(hh[2], c0.z, yv);
            hh[3] = fmaf(hh[3], dav, s * b0.w); yv = fmaf(hh[3], c0.w, yv);
            hh[4] = fmaf(hh[4], dav, s * b1.x); yv = fmaf(hh[4], c1.x, yv);
            hh[5] = fmaf(hh[5], dav, s * b1.y); yv = fmaf(hh[5], c1.y, yv);
            hh[6] = fmaf(hh[6], dav, s * b1.z); yv = fmaf(hh[6], c1.z, yv);
            hh[7] = fmaf(hh[7], dav, s * b1.w); yv = fmaf(hh[7], c1.w, yv);
            yv += __shfl_xor_sync(0xffffffffu, yv, 4);
            yv += __shfl_xor_sync(0xffffffffu, yv, 2);
            yv += __shfl_xor_sync(0xffffffffu, yv, 1);
            if (q == 0) sY[t][pl] = fmaf(Dh, xv, yv);
        }
        __syncthreads();
        for (int idx = tid; idx < 512; idx += 128) {
            int t = idx >> 4, p = idx & 15;
            g_y[(rowBase + t0 + t) * (size_t)DI + h * 64 + p0 + p] = sY[t][p];
        }
    }
}

// ---------------- y *= silu(z); RMSNorm * norm_w (in place on g_y) -------------
__global__ void gate_rms_kernel(const float* __restrict__ nw)
{
    int r = blockIdx.x, tid = threadIdx.x;
    float* yr = g_y + (size_t)r * DI;
    const float* zr = g_zx + (size_t)r * DIP;
    float v[8]; float ss = 0.f;
#pragma unroll
    for (int i = 0; i < 8; i++) {
        int c = tid + i * 256;
        float z = zr[c];
        float t = yr[c] * (z / (1.f + __expf(-z)));
        v[i] = t;
        ss = fmaf(t, t, ss);
    }
    float dummy = 0.f;
    blockReduceSum2(ss, dummy);
    float scale = rsqrtf(ss * (1.f / 2048.f) + 1e-5f);
#pragma unroll
    for (int i = 0; i < 8; i++) {
        int c = tid + i * 256;
        yr[c] = v[i] * scale * nw[c];
    }
}

// ---------------- launch --------------------------------------------------------
extern "C" void kernel_launch(void* const* d_in, const int* in_sizes, int n_in,
                              void* d_out, int out_size)
{
    const float* x       = (const float*)d_in[0];
    const float* ln1_w   = (const float*)d_in[1];
    const float* ln1_b   = (const float*)d_in[2];
    const float* in_proj = (const float*)d_in[3];
    const float* conv_w  = (const float*)d_in[4];
    const float* conv_b  = (const float*)d_in[5];
    const float* dt_bias = (const float*)d_in[6];
    const float* A_log   = (const float*)d_in[7];
    const float* Dv      = (const float*)d_in[8];
    const float* norm_w  = (const float*)d_in[9];
    const float* out_w   = (const float*)d_in[10];
    const float* ln2_w   = (const float*)d_in[11];
    const float* ln2_b   = (const float*)d_in[12];
    const float* mlp_w1  = (const float*)d_in[13];
    const float* mlp_b1  = (const float*)d_in[14];
    const float* mlp_w2  = (const float*)d_in[15];
    const float* mlp_b2  = (const float*)d_in[16];
    float* out = (float*)d_out;

    float *hln, *zx, *yb, *x1, *h2, *mid;
    cudaGetSymbolAddress((void**)&hln, g_hln);
    cudaGetSymbolAddress((void**)&zx,  g_zx);
    cudaGetSymbolAddress((void**)&yb,  g_y);
    cudaGetSymbolAddress((void**)&x1,  g_x1);
    cudaGetSymbolAddress((void**)&h2,  g_h2);
    cudaGetSymbolAddress((void**)&mid, g_mid);

    // 1) LN1
    ln_kernel<<<ROWS, 256>>>(x, ln1_w, ln1_b, hln);
    // 2) in_proj: [4096,1024] @ [4256,1024]^T -> zxbcdt
    sgemm_kernel<0><<<dim3(34, 32), 256>>>(hln, in_proj, zx, ROWS, DIP, DM, nullptr, nullptr);
    // 3) dt = softplus(raw + dt_bias)
    dt_kernel<<<(ROWS * NH) / 256, 256>>>(dt_bias);
    // 4) causal conv + silu -> g_xbc
    conv_kernel<<<dim3(17, ROWS), 128>>>(conv_w, conv_b);
    // 5) SSM scan (+ D*x fused) -> g_y
    scan_kernel<<<256, 128>>>(A_log, Dv);
    // 6) gate with silu(z), RMSNorm
    gate_rms_kernel<<<ROWS, 256>>>(norm_w);
    // 7) out_proj + residual(x) -> g_x1
    sgemm_kernel<3><<<dim3(8, 32), 256>>>(yb, out_w, x1, ROWS, DM, DI, nullptr, x);
    // 8) LN2
    ln_kernel<<<ROWS, 256>>>(x1, ln2_w, ln2_b, h2);
    // 9) MLP up + GELU
    sgemm_kernel<1><<<dim3(32, 32), 256>>>(h2, mlp_w1, mid, ROWS, DFF, DM, mlp_b1, nullptr);
    // 10) MLP down + bias + residual -> d_out
    sgemm_kernel<2><<<dim3(8, 32), 256>>>(mid, mlp_w2, out, ROWS, DM, DFF, mlp_b2, x1);
}

// round 4
// speedup vs baseline: 1.8515x; 1.8515x over previous
#include <cuda_runtime.h>
#include <cuda_bf16.h>
#include <math.h>
#include <cstdint>

#define ROWS 4096      // BT * L
#define LSEQ 2048
#define DM   1024
#define DI   2048
#define NH   32
#define DS   64
#define CD   2176      // conv dim = DI + 2*DS
#define DIP  4256      // in_proj out dim
#define DIPP 4352      // padded to 34*128
#define DFF  4096

// ---------------- scratch (device globals; no runtime allocation) -------------
__device__ float g_zx [(size_t)ROWS * DIP];
__device__ float g_xbc[(size_t)ROWS * CD];
__device__ float g_dt [(size_t)ROWS * NH];
__device__ float g_y  [(size_t)ROWS * DI];
__device__ float g_x1 [(size_t)ROWS * DM];

// bf16 split buffers (hi/lo)
__device__ __nv_bfloat16 a1h[(size_t)ROWS * DM],  a1l[(size_t)ROWS * DM];   // LN1 out
__device__ __nv_bfloat16 b1h[(size_t)DIPP * DM],  b1l[(size_t)DIPP * DM];   // in_proj w (padded)
__device__ __nv_bfloat16 a2h[(size_t)ROWS * DI],  a2l[(size_t)ROWS * DI];   // gated/rms y
__device__ __nv_bfloat16 b2h[(size_t)DM * DI],    b2l[(size_t)DM * DI];     // out_proj w
__device__ __nv_bfloat16 a3h[(size_t)ROWS * DM],  a3l[(size_t)ROWS * DM];   // LN2 out
__device__ __nv_bfloat16 b3h[(size_t)DFF * DM],   b3l[(size_t)DFF * DM];    // mlp_w1
__device__ __nv_bfloat16 a4h[(size_t)ROWS * DFF], a4l[(size_t)ROWS * DFF];  // gelu(mid)
__device__ __nv_bfloat16 b4h[(size_t)DM * DFF],   b4l[(size_t)DM * DFF];    // mlp_w2

// ================= helpers =====================================================
__device__ __forceinline__ uint32_t smem_u32(const void* p) {
    uint32_t a;
    asm("{ .reg .u64 t; cvta.to.shared.u64 t, %1; cvt.u32.u64 %0, t; }" : "=r"(a) : "l"(p));
    return a;
}
#define CP_ASYNC16(dst, src) \
    asm volatile("cp.async.cg.shared.global [%0], [%1], 16;" :: "r"(dst), "l"(src) : "memory")
#define CP_COMMIT() asm volatile("cp.async.commit_group;" ::: "memory")
#define CP_WAIT(n)  asm volatile("cp.async.wait_group %0;" :: "n"(n) : "memory")

#define LDSM_X4(r0, r1, r2, r3, addr) \
    asm volatile("ldmatrix.sync.aligned.m8n8.x4.shared.b16 {%0,%1,%2,%3}, [%4];" \
        : "=r"(r0), "=r"(r1), "=r"(r2), "=r"(r3) : "r"(addr))

#define MMA16816(d, a0, a1, a2, a3, b0, b1) \
    asm volatile("mma.sync.aligned.m16n8k16.row.col.f32.bf16.bf16.f32 " \
        "{%0,%1,%2,%3},{%4,%5,%6,%7},{%8,%9},{%0,%1,%2,%3};" \
        : "+f"((d)[0]), "+f"((d)[1]), "+f"((d)[2]), "+f"((d)[3]) \
        : "r"(a0), "r"(a1), "r"(a2), "r"(a3), "r"(b0), "r"(b1))

__device__ __forceinline__ void blockReduceSum2(float &a, float &b) {
    __shared__ float sa[8], sb2[8];
    int lane = threadIdx.x & 31, w = threadIdx.x >> 5;
#pragma unroll
    for (int o = 16; o > 0; o >>= 1) {
        a += __shfl_xor_sync(0xffffffffu, a, o);
        b += __shfl_xor_sync(0xffffffffu, b, o);
    }
    if (lane == 0) { sa[w] = a; sb2[w] = b; }
    __syncthreads();
    a = sa[lane & 7]; b = sb2[lane & 7];
#pragma unroll
    for (int o = 4; o > 0; o >>= 1) {
        a += __shfl_xor_sync(0xffffffffu, a, o);
        b += __shfl_xor_sync(0xffffffffu, b, o);
    }
}
__device__ __forceinline__ void split_store(float v, __nv_bfloat16* hi, __nv_bfloat16* lo, size_t off) {
    __nv_bfloat16 h = __float2bfloat16_rn(v);
    hi[off] = h;
    lo[off] = __float2bfloat16_rn(v - __bfloat162float(h));
}

// ---------------- weight split kernel ------------------------------------------
__global__ void wsplit_kernel(const float* __restrict__ src, __nv_bfloat16* __restrict__ hi,
                              __nv_bfloat16* __restrict__ lo, int n, int ntot)
{
    int i = blockIdx.x * 256 + threadIdx.x;
    if (i >= ntot) return;
    float v = (i < n) ? src[i] : 0.f;
    split_store(v, hi, lo, (size_t)i);
}

// ---------------- layernorm -> bf16 split --------------------------------------
__global__ void ln_kernel(const float* __restrict__ in, const float* __restrict__ w,
                          const float* __restrict__ bias,
                          __nv_bfloat16* __restrict__ ohi, __nv_bfloat16* __restrict__ olo)
{
    int r = blockIdx.x, tid = threadIdx.x;
    const float* xr = in + (size_t)r * DM;
    float v[4]; float s = 0.f, sq = 0.f;
#pragma unroll
    for (int i = 0; i < 4; i++) {
        v[i] = xr[tid + i * 256];
        s += v[i];
        sq = fmaf(v[i], v[i], sq);
    }
    blockReduceSum2(s, sq);
    float mu  = s * (1.f / DM);
    float var = sq * (1.f / DM) - mu * mu;
    float inv = rsqrtf(var + 1e-5f);
#pragma unroll
    for (int i = 0; i < 4; i++) {
        int c = tid + i * 256;
        float o = (v[i] - mu) * inv * w[c] + bias[c];
        split_store(o, ohi, olo, (size_t)r * DM + c);
    }
}

// ================= mma.sync split-bf16 GEMM ====================================
// C[M,N] = A[M,K] @ B[N,K]^T with A ~ Ahi+Alo, B ~ Bhi+Blo (3 MMA terms)
// CTA tile 128x128x32, 256 threads, warp tile 64x32.
// SMEM: per stage 4 matrices (Ah, Al, Bh, Bl), each 128 rows x 40 bf16 (80B skew).
// EPI: 0=store fp32; 3=+res; 2=+bias+res; 1=+bias, GELU -> bf16 split
#define SKEW 40
#define MATSZB (128 * SKEW * 2)          // 10240 bytes per matrix
#define STAGEB (4 * MATSZB)              // 40960 bytes per stage
#define GSMEM  (2 * STAGEB)              // 81920

template<int EPI>
__global__ void __launch_bounds__(256)
mma_gemm(const __nv_bfloat16* __restrict__ Ahi, const __nv_bfloat16* __restrict__ Alo,
         const __nv_bfloat16* __restrict__ Bhi, const __nv_bfloat16* __restrict__ Blo,
         int N, int K,
         float* __restrict__ C, const float* __restrict__ bias, const float* __restrict__ res,
         __nv_bfloat16* __restrict__ Ohi, __nv_bfloat16* __restrict__ Olo)
{
    extern __shared__ char smem[];
    const uint32_t sbase = smem_u32(smem);
    const int tid = threadIdx.x;
    const int l   = tid & 31;
    const int wid = tid >> 5;
    const int wr  = wid >> 2;           // 0..1 : warp row (64 rows each)
    const int wc  = wid & 3;            // 0..3 : warp col (32 cols each)
    const int bn  = blockIdx.x, bm = blockIdx.y;

    // tile base pointers (rows offset in)
    const __nv_bfloat16* base[4];
    base[0] = Ahi + (size_t)(bm * 128) * K;
    base[1] = Alo + (size_t)(bm * 128) * K;
    base[2] = Bhi + (size_t)(bn * 128) * K;
    base[3] = Blo + (size_t)(bn * 128) * K;

    // per-thread cp.async decomposition: 2048 16B-copies per stage, 8 per thread
    int cmat[8], crow[8], ccol[8];
    uint32_t cdst[8];
#pragma unroll
    for (int t = 0; t < 8; t++) {
        int idx = tid + (t << 8);
        cmat[t] = idx >> 9;
        crow[t] = (idx >> 2) & 127;
        ccol[t] = (idx & 3) * 8;
        cdst[t] = cmat[t] * MATSZB + (crow[t] * SKEW + ccol[t]) * 2;
    }

    const int NC = K >> 5;    // k chunks of 32

    // prologue: stage 0
#pragma unroll
    for (int t = 0; t < 8; t++)
        CP_ASYNC16(sbase + cdst[t], base[cmat[t]] + (size_t)crow[t] * K + ccol[t]);
    CP_COMMIT();

    float acc[4][4][4];
#pragma unroll
    for (int mi = 0; mi < 4; mi++)
#pragma unroll
        for (int ni = 0; ni < 4; ni++)
#pragma unroll
            for (int c = 0; c < 4; c++) acc[mi][ni][c] = 0.f;

    // lane offsets (bytes) within a matrix for ldmatrix addressing
    const uint32_t laneA = ((uint32_t)(l & 15) * SKEW + (l >> 4) * 8) * 2;
    const uint32_t laneB = (((uint32_t)(l & 7) + ((l >> 4) << 3)) * SKEW + ((l >> 3) & 1) * 8) * 2;
    const uint32_t aRow0 = (uint32_t)(wr * 64) * SKEW * 2;
    const uint32_t bRow0 = (uint32_t)(wc * 32) * SKEW * 2;

    for (int cch = 0; cch < NC; cch++) {
        if (cch + 1 < NC) {
            const int k0 = (cch + 1) << 5;
            const uint32_t sd = sbase + ((cch + 1) & 1) * STAGEB;
#pragma unroll
            for (int t = 0; t < 8; t++)
                CP_ASYNC16(sd + cdst[t], base[cmat[t]] + (size_t)crow[t] * K + k0 + ccol[t]);
            CP_COMMIT();
            CP_WAIT(1);
        } else {
            CP_WAIT(0);
        }
        __syncthreads();

        const uint32_t st = sbase + (cch & 1) * STAGEB;
#pragma unroll
        for (int kk = 0; kk < 2; kk++) {
            const uint32_t kOff = (uint32_t)(kk * 16) * 2;
            uint32_t ah[4][4], al[4][4], bh[2][4], bl[2][4];
#pragma unroll
            for (int mi = 0; mi < 4; mi++) {
                uint32_t ad = st + 0 * MATSZB + aRow0 + (uint32_t)(mi * 16) * SKEW * 2 + kOff + laneA;
                LDSM_X4(ah[mi][0], ah[mi][1], ah[mi][2], ah[mi][3], ad);
            }
#pragma unroll
            for (int ni = 0; ni < 2; ni++) {
                uint32_t bd = st + 2 * MATSZB + bRow0 + (uint32_t)(ni * 16) * SKEW * 2 + kOff + laneB;
                LDSM_X4(bh[ni][0], bh[ni][1], bh[ni][2], bh[ni][3], bd);
            }
#pragma unroll
            for (int mi = 0; mi < 4; mi++)
#pragma unroll
                for (int ni = 0; ni < 4; ni++) {
                    const uint32_t* bq = bh[ni >> 1];
                    int o = (ni & 1) * 2;
                    MMA16816(acc[mi][ni], ah[mi][0], ah[mi][1], ah[mi][2], ah[mi][3], bq[o], bq[o + 1]);
                }
#pragma unroll
            for (int ni = 0; ni < 2; ni++) {
                uint32_t bd = st + 3 * MATSZB + bRow0 + (uint32_t)(ni * 16) * SKEW * 2 + kOff + laneB;
                LDSM_X4(bl[ni][0], bl[ni][1], bl[ni][2], bl[ni][3], bd);
            }
#pragma unroll
            for (int mi = 0; mi < 4; mi++)
#pragma unroll
                for (int ni = 0; ni < 4; ni++) {
                    const uint32_t* bq = bl[ni >> 1];
                    int o = (ni & 1) * 2;
                    MMA16816(acc[mi][ni], ah[mi][0], ah[mi][1], ah[mi][2], ah[mi][3], bq[o], bq[o + 1]);
                }
#pragma unroll
            for (int mi = 0; mi < 4; mi++) {
                uint32_t ad = st + 1 * MATSZB + aRow0 + (uint32_t)(mi * 16) * SKEW * 2 + kOff + laneA;
                LDSM_X4(al[mi][0], al[mi][1], al[mi][2], al[mi][3], ad);
            }
#pragma unroll
            for (int mi = 0; mi < 4; mi++)
#pragma unroll
                for (int ni = 0; ni < 4; ni++) {
                    const uint32_t* bq = bh[ni >> 1];
                    int o = (ni & 1) * 2;
                    MMA16816(acc[mi][ni], al[mi][0], al[mi][1], al[mi][2], al[mi][3], bq[o], bq[o + 1]);
                }
        }
        __syncthreads();
    }

    // ---- epilogue: registers -> global directly ----
    const int rowb = bm * 128 + wr * 64 + (l >> 2);
    const int colb = bn * 128 + wc * 32 + (l & 3) * 2;
#pragma unroll
    for (int mi = 0; mi < 4; mi++) {
#pragma unroll
        for (int ni = 0; ni < 4; ni++) {
            int cc = colb + ni * 8;
            if (cc < N) {
#pragma unroll
                for (int h = 0; h < 2; h++) {
                    int rr = rowb + mi * 16 + h * 8;
                    size_t off = (size_t)rr * N + cc;
                    float v0 = acc[mi][ni][h * 2 + 0];
                    float v1 = acc[mi][ni][h * 2 + 1];
                    if (EPI == 0) {
                        *(float2*)(C + off) = make_float2(v0, v1);
                    } else if (EPI == 3) {
                        *(float2*)(C + off) = make_float2(v0 + res[off], v1 + res[off + 1]);
                    } else if (EPI == 2) {
                        *(float2*)(C + off) = make_float2(v0 + bias[cc] + res[off],
                                                          v1 + bias[cc + 1] + res[off + 1]);
                    } else {
                        v0 += bias[cc];
                        v1 += bias[cc + 1];
                        v0 = 0.5f * v0 * (1.f + erff(v0 * 0.70710678118654752f));
                        v1 = 0.5f * v1 * (1.f + erff(v1 * 0.70710678118654752f));
                        __nv_bfloat16 h0 = __float2bfloat16_rn(v0);
                        __nv_bfloat16 h1 = __float2bfloat16_rn(v1);
                        __nv_bfloat16 l0 = __float2bfloat16_rn(v0 - __bfloat162float(h0));
                        __nv_bfloat16 l1 = __float2bfloat16_rn(v1 - __bfloat162float(h1));
                        *(__nv_bfloat162*)(Ohi + off) = __nv_bfloat162(h0, h1);
                        *(__nv_bfloat162*)(Olo + off) = __nv_bfloat162(l0, l1);
                    }
                }
            }
        }
    }
}

// ---------------- dt = softplus(raw + dt_bias) ---------------------------------
__global__ void dt_kernel(const float* __restrict__ dtb)
{
    int idx = blockIdx.x * 256 + threadIdx.x;
    if (idx >= ROWS * NH) return;
    int r = idx >> 5, h = idx & 31;
    float u = g_zx[(size_t)r * DIP + (DI + CD) + h] + dtb[h];
    g_dt[idx] = (u > 20.f) ? u : log1pf(__expf(u));
}

// ---------------- causal depthwise conv (width 4) + SiLU -----------------------
__global__ void conv_kernel(const float* __restrict__ cw, const float* __restrict__ cb)
{
    int c = blockIdx.x * 128 + threadIdx.x;   // 0..2175
    int row = blockIdx.y;                      // 0..4095
    int l = row & (LSEQ - 1);
    float w0 = cw[c * 4 + 0], w1 = cw[c * 4 + 1], w2 = cw[c * 4 + 2], w3 = cw[c * 4 + 3];
    const float* col = g_zx + (size_t)row * DIP + DI + c;
    float acc = cb[c];
    acc = fmaf(col[0], w3, acc);
    if (l >= 1) acc = fmaf(*(col - DIP),     w2, acc);
    if (l >= 2) acc = fmaf(*(col - 2 * DIP), w1, acc);
    if (l >= 3) acc = fmaf(*(col - 3 * DIP), w0, acc);
    g_xbc[(size_t)row * CD + c] = acc / (1.f + __expf(-acc));
}

// ---------------- sequential SSM scan ------------------------------------------
__global__ void __launch_bounds__(128)
scan_kernel(const float* __restrict__ A_log, const float* __restrict__ Dvec)
{
    const int blk = blockIdx.x;
    const int b   = blk >> 7;
    const int rem = blk & 127;
    const int h   = rem >> 2;
    const int pc  = rem & 3;
    const int p0  = pc * 16;
    const int tid = threadIdx.x;
    const int q   = tid & 7;
    const int pl  = tid >> 3;

    const float Ah = -__expf(A_log[h]);
    const float Dh = Dvec[h];

    __shared__ float sB[32][64];
    __shared__ float sC[32][64];
    __shared__ float sX[32][16];
    __shared__ float sDt[32];
    __shared__ float sDA[32];
    __shared__ float sY[32][16];

    float hh[8];
#pragma unroll
    for (int i = 0; i < 8; i++) hh[i] = 0.f;

    const size_t rowBase = (size_t)b * LSEQ;

    for (int t0 = 0; t0 < LSEQ; t0 += 32) {
        for (int idx = tid; idx < 2048; idx += 128) {
            int t = idx >> 6, n = idx & 63;
            size_t ro = (rowBase + t0 + t) * (size_t)CD;
            sB[t][n] = g_xbc[ro + DI + n];
            sC[t][n] = g_xbc[ro + DI + DS + n];
        }
        for (int idx = tid; idx < 512; idx += 128) {
            int t = idx >> 4, p = idx & 15;
            sX[t][p] = g_xbc[(rowBase + t0 + t) * (size_t)CD + h * 64 + p0 + p];
        }
        if (tid < 32) {
            float d = g_dt[(rowBase + t0 + tid) * NH + h];
            sDt[tid] = d;
            sDA[tid] = __expf(d * Ah);
        }
        __syncthreads();

#pragma unroll 8
        for (int t = 0; t < 32; t++) {
            float dtv = sDt[t];
            float dav = sDA[t];
            float xv  = sX[t][pl];
            float s   = dtv * xv;
            float4 b0 = *(const float4*)&sB[t][q * 8];
            float4 b1 = *(const float4*)&sB[t][q * 8 + 4];
            float4 c0 = *(const float4*)&sC[t][q * 8];
            float4 c1 = *(const float4*)&sC[t][q * 8 + 4];
            float yv = 0.f;
            hh[0] = fmaf(hh[0], dav, s * b0.x); yv = fmaf(hh[0], c0.x, yv);
            hh[1] = fmaf(hh[1], dav, s * b0.y); yv = fmaf(hh[1], c0.y, yv);
            hh[2] = fmaf(hh[2], dav, s * b0.z); yv = fmaf(hh[2], c0.z, yv);
            hh[3] = fmaf(hh[3], dav, s * b0.w); yv = fmaf(hh[3], c0.w, yv);
            hh[4] = fmaf(hh[4], dav, s * b1.x); yv = fmaf(hh[4], c1.x, yv);
            hh[5] = fmaf(hh[5], dav, s * b1.y); yv = fmaf(hh[5], c1.y, yv);
            hh[6] = fmaf(hh[6], dav, s * b1.z); yv = fmaf(hh[6], c1.z, yv);
            hh[7] = fmaf(hh[7], dav, s * b1.w); yv = fmaf(hh[7], c1.w, yv);
            yv += __shfl_xor_sync(0xffffffffu, yv, 4);
            yv += __shfl_xor_sync(0xffffffffu, yv, 2);
            yv += __shfl_xor_sync(0xffffffffu, yv, 1);
            if (q == 0) sY[t][pl] = fmaf(Dh, xv, yv);
        }
        __syncthreads();
        for (int idx = tid; idx < 512; idx += 128) {
            int t = idx >> 4, p = idx & 15;
            g_y[(rowBase + t0 + t) * (size_t)DI + h * 64 + p0 + p] = sY[t][p];
        }
    }
}

// ---------------- y *= silu(z); RMSNorm * norm_w -> bf16 split -----------------
__global__ void gate_rms_kernel(const float* __restrict__ nw)
{
    int r = blockIdx.x, tid = threadIdx.x;
    const float* yr = g_y + (size_t)r * DI;
    const float* zr = g_zx + (size_t)r * DIP;
    float v[8]; float ss = 0.f;
#pragma unroll
    for (int i = 0; i < 8; i++) {
        int c = tid + i * 256;
        float z = zr[c];
        float t = yr[c] * (z / (1.f + __expf(-z)));
        v[i] = t;
        ss = fmaf(t, t, ss);
    }
    float dummy = 0.f;
    blockReduceSum2(ss, dummy);
    float scale = rsqrtf(ss * (1.f / 2048.f) + 1e-5f);
#pragma unroll
    for (int i = 0; i < 8; i++) {
        int c = tid + i * 256;
        split_store(v[i] * scale * nw[c], a2h, a2l, (size_t)r * DI + c);
    }
}

// ---------------- launch --------------------------------------------------------
extern "C" void kernel_launch(void* const* d_in, const int* in_sizes, int n_in,
                              void* d_out, int out_size)
{
    const float* x       = (const float*)d_in[0];
    const float* ln1_w   = (const float*)d_in[1];
    const float* ln1_b   = (const float*)d_in[2];
    const float* in_proj = (const float*)d_in[3];
    const float* conv_w  = (const float*)d_in[4];
    const float* conv_b  = (const float*)d_in[5];
    const float* dt_bias = (const float*)d_in[6];
    const float* A_log   = (const float*)d_in[7];
    const float* Dv      = (const float*)d_in[8];
    const float* norm_w  = (const float*)d_in[9];
    const float* out_w   = (const float*)d_in[10];
    const float* ln2_w   = (const float*)d_in[11];
    const float* ln2_b   = (const float*)d_in[12];
    const float* mlp_w1  = (const float*)d_in[13];
    const float* mlp_b1  = (const float*)d_in[14];
    const float* mlp_w2  = (const float*)d_in[15];
    const float* mlp_b2  = (const float*)d_in[16];
    float* out = (float*)d_out;

    static bool attr_done = false;
    if (!attr_done) {
        cudaFuncSetAttribute(mma_gemm<0>, cudaFuncAttributeMaxDynamicSharedMemorySize, GSMEM);
        cudaFuncSetAttribute(mma_gemm<1>, cudaFuncAttributeMaxDynamicSharedMemorySize, GSMEM);
        cudaFuncSetAttribute(mma_gemm<2>, cudaFuncAttributeMaxDynamicSharedMemorySize, GSMEM);
        cudaFuncSetAttribute(mma_gemm<3>, cudaFuncAttributeMaxDynamicSharedMemorySize, GSMEM);
        attr_done = true;
    }

    float *zx, *x1;
    cudaGetSymbolAddress((void**)&zx,  g_zx);
    cudaGetSymbolAddress((void**)&x1,  g_x1);
    __nv_bfloat16 *pa1h, *pa1l, *pb1h, *pb1l, *pa2h, *pa2l, *pb2h, *pb2l;
    __nv_bfloat16 *pa3h, *pa3l, *pb3h, *pb3l, *pa4h, *pa4l, *pb4h, *pb4l;
    cudaGetSymbolAddress((void**)&pa1h, a1h); cudaGetSymbolAddress((void**)&pa1l, a1l);
    cudaGetSymbolAddress((void**)&pb1h, b1h); cudaGetSymbolAddress((void**)&pb1l, b1l);
    cudaGetSymbolAddress((void**)&pa2h, a2h); cudaGetSymbolAddress((void**)&pa2l, a2l);
    cudaGetSymbolAddress((void**)&pb2h, b2h); cudaGetSymbolAddress((void**)&pb2l, b2l);
    cudaGetSymbolAddress((void**)&pa3h, a3h); cudaGetSymbolAddress((void**)&pa3l, a3l);
    cudaGetSymbolAddress((void**)&pb3h, b3h); cudaGetSymbolAddress((void**)&pb3l, b3l);
    cudaGetSymbolAddress((void**)&pa4h, a4h); cudaGetSymbolAddress((void**)&pa4l, a4l);
    cudaGetSymbolAddress((void**)&pb4h, b4h); cudaGetSymbolAddress((void**)&pb4l, b4l);

    // weight splits (every call; deterministic)
    wsplit_kernel<<<(DIPP * DM + 255) / 256, 256>>>(in_proj, pb1h, pb1l, DIP * DM, DIPP * DM);
    wsplit_kernel<<<(DM * DI + 255) / 256, 256>>>(out_w, pb2h, pb2l, DM * DI, DM * DI);
    wsplit_kernel<<<(DFF * DM + 255) / 256, 256>>>(mlp_w1, pb3h, pb3l, DFF * DM, DFF * DM);
    wsplit_kernel<<<(DM * DFF + 255) / 256, 256>>>(mlp_w2, pb4h, pb4l, DM * DFF, DM * DFF);

    // 1) LN1 -> a1 (bf16 split)
    ln_kernel<<<ROWS, 256>>>(x, ln1_w, ln1_b, pa1h, pa1l);
    // 2) in_proj: [4096,1024] @ [4256,1024]^T -> zx (fp32)
    mma_gemm<0><<<dim3(DIPP / 128, ROWS / 128), 256, GSMEM>>>(pa1h, pa1l, pb1h, pb1l, DIP, DM,
                                                              zx, nullptr, nullptr, nullptr, nullptr);
    // 3) dt
    dt_kernel<<<(ROWS * NH) / 256, 256>>>(dt_bias);
    // 4) conv + silu
    conv_kernel<<<dim3(17, ROWS), 128>>>(conv_w, conv_b);
    // 5) scan
    scan_kernel<<<256, 128>>>(A_log, Dv);
    // 6) gate + rms -> a2 (bf16 split)
    gate_rms_kernel<<<ROWS, 256>>>(norm_w);
    // 7) out_proj + residual(x) -> x1 (fp32)
    mma_gemm<3><<<dim3(DM / 128, ROWS / 128), 256, GSMEM>>>(pa2h, pa2l, pb2h, pb2l, DM, DI,
                                                            x1, nullptr, x, nullptr, nullptr);
    // 8) LN2 -> a3 (bf16 split)
    ln_kernel<<<ROWS, 256>>>(x1, ln2_w, ln2_b, pa3h, pa3l);
    // 9) MLP up + bias + GELU -> a4 (bf16 split)
    mma_gemm<1><<<dim3(DFF / 128, ROWS / 128), 256, GSMEM>>>(pa3h, pa3l, pb3h, pb3l, DFF, DM,
                                                             nullptr, mlp_b1, nullptr, pa4h, pa4l);
    // 10) MLP down + bias + residual(x1) -> out
    mma_gemm<2><<<dim3(DM / 128, ROWS / 128), 256, GSMEM>>>(pa4h, pa4l, pb4h, pb4l, DM, DFF,
                                                            out, mlp_b2, x1, nullptr, nullptr);
}

// round 6
// speedup vs baseline: 1.9085x; 1.0308x over previous
#include <cuda_runtime.h>
#include <cuda_bf16.h>
#include <math.h>
#include <cstdint>

#define ROWS 4096      // BT * L
#define LSEQ 2048
#define DM   1024
#define DI   2048
#define NH   32
#define DS   64
#define CD   2176      // conv dim = DI + 2*DS
#define DIP  4256      // in_proj out dim
#define DIPP 4352      // padded to 34*128
#define DFF  4096

// ---------------- scratch (device globals; no runtime allocation) -------------
__device__ float g_zx [(size_t)ROWS * DIP];
__device__ float g_xbc[(size_t)ROWS * CD];
__device__ float g_dt [(size_t)ROWS * NH];
__device__ float g_y  [(size_t)ROWS * DI];
__device__ float g_x1 [(size_t)ROWS * DM];

// bf16 split buffers (hi/lo)
__device__ __nv_bfloat16 a1h[(size_t)ROWS * DM],  a1l[(size_t)ROWS * DM];   // LN1 out
__device__ __nv_bfloat16 b1h[(size_t)DIPP * DM],  b1l[(size_t)DIPP * DM];   // in_proj w (padded)
__device__ __nv_bfloat16 a2h[(size_t)ROWS * DI],  a2l[(size_t)ROWS * DI];   // gated/rms y
__device__ __nv_bfloat16 b2h[(size_t)DM * DI],    b2l[(size_t)DM * DI];     // out_proj w
__device__ __nv_bfloat16 a3h[(size_t)ROWS * DM],  a3l[(size_t)ROWS * DM];   // LN2 out
__device__ __nv_bfloat16 b3h[(size_t)DFF * DM],   b3l[(size_t)DFF * DM];    // mlp_w1
__device__ __nv_bfloat16 a4h[(size_t)ROWS * DFF], a4l[(size_t)ROWS * DFF];  // gelu(mid)
__device__ __nv_bfloat16 b4h[(size_t)DM * DFF],   b4l[(size_t)DM * DFF];    // mlp_w2

// ================= helpers =====================================================
__device__ __forceinline__ uint32_t smem_u32(const void* p) {
    uint32_t a;
    asm("{ .reg .u64 t; cvta.to.shared.u64 t, %1; cvt.u32.u64 %0, t; }" : "=r"(a) : "l"(p));
    return a;
}
#define CP_ASYNC16(dst, src) \
    asm volatile("cp.async.cg.shared.global [%0], [%1], 16;" :: "r"(dst), "l"(src) : "memory")
#define CP_COMMIT() asm volatile("cp.async.commit_group;" ::: "memory")
#define CP_WAIT(n)  asm volatile("cp.async.wait_group %0;" :: "n"(n) : "memory")

#define LDSM_X4(r0, r1, r2, r3, addr) \
    asm volatile("ldmatrix.sync.aligned.m8n8.x4.shared.b16 {%0,%1,%2,%3}, [%4];" \
        : "=r"(r0), "=r"(r1), "=r"(r2), "=r"(r3) : "r"(addr))

#define MMA16816(d, a0, a1, a2, a3, b0, b1) \
    asm volatile("mma.sync.aligned.m16n8k16.row.col.f32.bf16.bf16.f32 " \
        "{%0,%1,%2,%3},{%4,%5,%6,%7},{%8,%9},{%0,%1,%2,%3};" \
        : "+f"((d)[0]), "+f"((d)[1]), "+f"((d)[2]), "+f"((d)[3]) \
        : "r"(a0), "r"(a1), "r"(a2), "r"(a3), "r"(b0), "r"(b1))

__device__ __forceinline__ void blockReduceSum2(float &a, float &b) {
    __shared__ float sa[8], sb2[8];
    int lane = threadIdx.x & 31, w = threadIdx.x >> 5;
#pragma unroll
    for (int o = 16; o > 0; o >>= 1) {
        a += __shfl_xor_sync(0xffffffffu, a, o);
        b += __shfl_xor_sync(0xffffffffu, b, o);
    }
    if (lane == 0) { sa[w] = a; sb2[w] = b; }
    __syncthreads();
    a = sa[lane & 7]; b = sb2[lane & 7];
#pragma unroll
    for (int o = 4; o > 0; o >>= 1) {
        a += __shfl_xor_sync(0xffffffffu, a, o);
        b += __shfl_xor_sync(0xffffffffu, b, o);
    }
}
__device__ __forceinline__ void split_store(float v, __nv_bfloat16* hi, __nv_bfloat16* lo, size_t off) {
    __nv_bfloat16 h = __float2bfloat16_rn(v);
    hi[off] = h;
    lo[off] = __float2bfloat16_rn(v - __bfloat162float(h));
}

// ---------------- weight split kernel ------------------------------------------
__global__ void wsplit_kernel(const float* __restrict__ src, __nv_bfloat16* __restrict__ hi,
                              __nv_bfloat16* __restrict__ lo, int n, int ntot)
{
    int i = blockIdx.x * 256 + threadIdx.x;
    if (i >= ntot) return;
    float v = (i < n) ? src[i] : 0.f;
    split_store(v, hi, lo, (size_t)i);
}

// dual weight split: two sources back to back (for mlp_w1, mlp_w2)
__global__ void wsplit2_kernel(const float* __restrict__ s1, __nv_bfloat16* __restrict__ h1,
                               __nv_bfloat16* __restrict__ l1, int n1,
                               const float* __restrict__ s2, __nv_bfloat16* __restrict__ h2,
                               __nv_bfloat16* __restrict__ l2, int n2)
{
    int i = blockIdx.x * 256 + threadIdx.x;
    if (i < n1) split_store(s1[i], h1, l1, (size_t)i);
    else if (i < n1 + n2) { int j = i - n1; split_store(s2[j], h2, l2, (size_t)j); }
}

// ---------------- layernorm -> bf16 split --------------------------------------
__global__ void ln_kernel(const float* __restrict__ in, const float* __restrict__ w,
                          const float* __restrict__ bias,
                          __nv_bfloat16* __restrict__ ohi, __nv_bfloat16* __restrict__ olo)
{
    int r = blockIdx.x, tid = threadIdx.x;
    const float* xr = in + (size_t)r * DM;
    float v[4]; float s = 0.f, sq = 0.f;
#pragma unroll
    for (int i = 0; i < 4; i++) {
        v[i] = xr[tid + i * 256];
        s += v[i];
        sq = fmaf(v[i], v[i], sq);
    }
    blockReduceSum2(s, sq);
    float mu  = s * (1.f / DM);
    float var = sq * (1.f / DM) - mu * mu;
    float inv = rsqrtf(var + 1e-5f);
#pragma unroll
    for (int i = 0; i < 4; i++) {
        int c = tid + i * 256;
        float o = (v[i] - mu) * inv * w[c] + bias[c];
        split_store(o, ohi, olo, (size_t)r * DM + c);
    }
}

// ================= mma.sync split-bf16 GEMM, 3-stage pipeline ==================
// C[M,N] = A[M,K] @ B[N,K]^T with A ~ Ahi+Alo, B ~ Bhi+Blo (3 MMA terms)
// CTA tile 128x128x32, 256 threads, warp tile 64x32.
#define SKEW 40
#define MATSZB (128 * SKEW * 2)          // 10240 bytes per matrix
#define STAGEB (4 * MATSZB)              // 40960 bytes per stage
#define NSTAGE 3
#define GSMEM  (NSTAGE * STAGEB)         // 122880

template<int EPI>
__global__ void __launch_bounds__(256)
mma_gemm(const __nv_bfloat16* __restrict__ Ahi, const __nv_bfloat16* __restrict__ Alo,
         const __nv_bfloat16* __restrict__ Bhi, const __nv_bfloat16* __restrict__ Blo,
         int N, int K,
         float* __restrict__ C, const float* __restrict__ bias, const float* __restrict__ res,
         __nv_bfloat16* __restrict__ Ohi, __nv_bfloat16* __restrict__ Olo)
{
    extern __shared__ char smem[];
    const uint32_t sbase = smem_u32(smem);
    const int tid = threadIdx.x;
    const int l   = tid & 31;
    const int wid = tid >> 5;
    const int wr  = wid >> 2;           // 0..1 : warp row (64 rows each)
    const int wc  = wid & 3;            // 0..3 : warp col (32 cols each)
    const int bn  = blockIdx.x, bm = blockIdx.y;

    // tile base pointers
    const __nv_bfloat16* base[4];
    base[0] = Ahi + (size_t)(bm * 128) * K;
    base[1] = Alo + (size_t)(bm * 128) * K;
    base[2] = Bhi + (size_t)(bn * 128) * K;
    base[3] = Blo + (size_t)(bn * 128) * K;

    // per-thread cp.async decomposition: 2048 16B-copies per stage, 8 per thread
    const __nv_bfloat16* csrc[8];
    uint32_t cdst[8];
#pragma unroll
    for (int t = 0; t < 8; t++) {
        int idx = tid + (t << 8);
        int mat = idx >> 9;
        int row = (idx >> 2) & 127;
        int col = (idx & 3) * 8;
        cdst[t] = mat * MATSZB + (row * SKEW + col) * 2;
        csrc[t] = base[mat] + (size_t)row * K + col;
    }

    const int NC = K >> 5;    // k chunks of 32

    // prologue: stages 0,1
#pragma unroll
    for (int t = 0; t < 8; t++) CP_ASYNC16(sbase + cdst[t], csrc[t]);
    CP_COMMIT();
#pragma unroll
    for (int t = 0; t < 8; t++) CP_ASYNC16(sbase + STAGEB + cdst[t], csrc[t] + 32);
    CP_COMMIT();

    float acc[4][4][4];
#pragma unroll
    for (int mi = 0; mi < 4; mi++)
#pragma unroll
        for (int ni = 0; ni < 4; ni++)
#pragma unroll
            for (int c = 0; c < 4; c++) acc[mi][ni][c] = 0.f;

    // lane offsets (bytes) within a matrix for ldmatrix addressing
    const uint32_t laneA = ((uint32_t)(l & 15) * SKEW + (l >> 4) * 8) * 2;
    const uint32_t laneB = (((uint32_t)(l & 7) + ((l >> 4) << 3)) * SKEW + ((l >> 3) & 1) * 8) * 2;
    const uint32_t aRow0 = (uint32_t)(wr * 64) * SKEW * 2;
    const uint32_t bRow0 = (uint32_t)(wc * 32) * SKEW * 2;

    int sc = 0;               // stage of current chunk
    for (int cch = 0; cch < NC; cch++) {
        if (cch < NC - 1) { CP_WAIT(1); } else { CP_WAIT(0); }
        __syncthreads();

        // issue chunk cch+2 into stage (sc+2)%3 (it was consumed in chunk cch-1)
        if (cch + 2 < NC) {
            int sn = sc + 2; if (sn >= NSTAGE) sn -= NSTAGE;
            const uint32_t sd = sbase + sn * STAGEB;
            const int k0 = (cch + 2) << 5;
#pragma unroll
            for (int t = 0; t < 8; t++) CP_ASYNC16(sd + cdst[t], csrc[t] + k0);
            CP_COMMIT();
        }

        const uint32_t st = sbase + sc * STAGEB;
#pragma unroll
        for (int kk = 0; kk < 2; kk++) {
            const uint32_t kOff = (uint32_t)(kk * 16) * 2;
            uint32_t ah[4][4], al[4][4], bh[2][4], bl[2][4];
#pragma unroll
            for (int mi = 0; mi < 4; mi++) {
                uint32_t ad = st + 0 * MATSZB + aRow0 + (uint32_t)(mi * 16) * SKEW * 2 + kOff + laneA;
                LDSM_X4(ah[mi][0], ah[mi][1], ah[mi][2], ah[mi][3], ad);
            }
#pragma unroll
            for (int ni = 0; ni < 2; ni++) {
                uint32_t bd = st + 2 * MATSZB + bRow0 + (uint32_t)(ni * 16) * SKEW * 2 + kOff + laneB;
                LDSM_X4(bh[ni][0], bh[ni][1], bh[ni][2], bh[ni][3], bd);
            }
#pragma unroll
            for (int mi = 0; mi < 4; mi++)
#pragma unroll
                for (int ni = 0; ni < 4; ni++) {
                    const uint32_t* bq = bh[ni >> 1];
                    int o = (ni & 1) * 2;
                    MMA16816(acc[mi][ni], ah[mi][0], ah[mi][1], ah[mi][2], ah[mi][3], bq[o], bq[o + 1]);
                }
#pragma unroll
            for (int ni = 0; ni < 2; ni++) {
                uint32_t bd = st + 3 * MATSZB + bRow0 + (uint32_t)(ni * 16) * SKEW * 2 + kOff + laneB;
                LDSM_X4(bl[ni][0], bl[ni][1], bl[ni][2], bl[ni][3], bd);
            }
#pragma unroll
            for (int mi = 0; mi < 4; mi++)
#pragma unroll
                for (int ni = 0; ni < 4; ni++) {
                    const uint32_t* bq = bl[ni >> 1];
                    int o = (ni & 1) * 2;
                    MMA16816(acc[mi][ni], ah[mi][0], ah[mi][1], ah[mi][2], ah[mi][3], bq[o], bq[o + 1]);
                }
#pragma unroll
            for (int mi = 0; mi < 4; mi++) {
                uint32_t ad = st + 1 * MATSZB + aRow0 + (uint32_t)(mi * 16) * SKEW * 2 + kOff + laneA;
                LDSM_X4(al[mi][0], al[mi][1], al[mi][2], al[mi][3], ad);
            }
#pragma unroll
            for (int mi = 0; mi < 4; mi++)
#pragma unroll
                for (int ni = 0; ni < 4; ni++) {
                    const uint32_t* bq = bh[ni >> 1];
                    int o = (ni & 1) * 2;
                    MMA16816(acc[mi][ni], al[mi][0], al[mi][1], al[mi][2], al[mi][3], bq[o], bq[o + 1]);
                }
        }
        sc++; if (sc >= NSTAGE) sc = 0;
    }

    // ---- epilogue: registers -> global directly ----
    const int rowb = bm * 128 + wr * 64 + (l >> 2);
    const int colb = bn * 128 + wc * 32 + (l & 3) * 2;
#pragma unroll
    for (int mi = 0; mi < 4; mi++) {
#pragma unroll
        for (int ni = 0; ni < 4; ni++) {
            int cc = colb + ni * 8;
            if (cc < N) {
#pragma unroll
                for (int h = 0; h < 2; h++) {
                    int rr = rowb + mi * 16 + h * 8;
                    size_t off = (size_t)rr * N + cc;
                    float v0 = acc[mi][ni][h * 2 + 0];
                    float v1 = acc[mi][ni][h * 2 + 1];
                    if (EPI == 0) {
                        *(float2*)(C + off) = make_float2(v0, v1);
                    } else if (EPI == 3) {
                        *(float2*)(C + off) = make_float2(v0 + res[off], v1 + res[off + 1]);
                    } else if (EPI == 2) {
                        *(float2*)(C + off) = make_float2(v0 + bias[cc] + res[off],
                                                          v1 + bias[cc + 1] + res[off + 1]);
                    } else {
                        v0 += bias[cc];
                        v1 += bias[cc + 1];
                        v0 = 0.5f * v0 * (1.f + erff(v0 * 0.70710678118654752f));
                        v1 = 0.5f * v1 * (1.f + erff(v1 * 0.70710678118654752f));
                        __nv_bfloat16 h0 = __float2bfloat16_rn(v0);
                        __nv_bfloat16 h1 = __float2bfloat16_rn(v1);
                        __nv_bfloat16 l0 = __float2bfloat16_rn(v0 - __bfloat162float(h0));
                        __nv_bfloat16 l1 = __float2bfloat16_rn(v1 - __bfloat162float(h1));
                        *(__nv_bfloat162*)(Ohi + off) = __nv_bfloat162(h0, h1);
                        *(__nv_bfloat162*)(Olo + off) = __nv_bfloat162(l0, l1);
                    }
                }
            }
        }
    }
}

// ---------------- dt = softplus(raw + dt_bias) ---------------------------------
__global__ void dt_kernel(const float* __restrict__ dtb)
{
    int idx = blockIdx.x * 256 + threadIdx.x;
    if (idx >= ROWS * NH) return;
    int r = idx >> 5, h = idx & 31;
    float u = g_zx[(size_t)r * DIP + (DI + CD) + h] + dtb[h];
    g_dt[idx] = (u > 20.f) ? u : log1pf(__expf(u));
}

// ---------------- tiled causal depthwise conv (width 4) + SiLU -----------------
// block: 128 threads = 128 channels; 32 rows per block; smem tile 35 x 128
__global__ void __launch_bounds__(128)
conv_kernel(const float* __restrict__ cw, const float* __restrict__ cb)
{
    __shared__ float sx[35][128];
    const int tid = threadIdx.x;
    const int c   = blockIdx.x * 128 + tid;     // 0..2175
    const int r0  = blockIdx.y * 32;            // global row base

    // load rows r0-3 .. r0+31 for this channel block
    for (int idx = tid; idx < 35 * 128; idx += 128) {
        int i   = idx >> 7;          // 0..34
        int col = idx & 127;
        int g   = r0 - 3 + i;
        sx[i][col] = (g >= 0) ? g_zx[(size_t)g * DIP + DI + blockIdx.x * 128 + col] : 0.f;
    }
    __syncthreads();

    const float w0 = cw[c * 4 + 0], w1 = cw[c * 4 + 1], w2 = cw[c * 4 + 2], w3 = cw[c * 4 + 3];
    const float bias = cb[c];
#pragma unroll 4
    for (int i = 0; i < 32; i++) {
        int row = r0 + i;
        int l = row & (LSEQ - 1);
        float acc = bias;
        acc = fmaf(sx[i + 3][tid], w3, acc);
        if (l >= 1) acc = fmaf(sx[i + 2][tid], w2, acc);
        if (l >= 2) acc = fmaf(sx[i + 1][tid], w1, acc);
        if (l >= 3) acc = fmaf(sx[i + 0][tid], w0, acc);
        g_xbc[(size_t)row * CD + c] = acc / (1.f + __expf(-acc));
    }
}

// ---------------- sequential SSM scan ------------------------------------------
__global__ void __launch_bounds__(128)
scan_kernel(const float* __restrict__ A_log, const float* __restrict__ Dvec)
{
    const int blk = blockIdx.x;
    const int b   = blk >> 7;
    const int rem = blk & 127;
    const int h   = rem >> 2;
    const int pc  = rem & 3;
    const int p0  = pc * 16;
    const int tid = threadIdx.x;
    const int q   = tid & 7;
    const int pl  = tid >> 3;

    const float Ah = -__expf(A_log[h]);
    const float Dh = Dvec[h];

    __shared__ float sB[32][64];
    __shared__ float sC[32][64];
    __shared__ float sX[32][16];
    __shared__ float sDt[32];
    __shared__ float sDA[32];
    __shared__ float sY[32][16];

    float hh[8];
#pragma unroll
    for (int i = 0; i < 8; i++) hh[i] = 0.f;

    const size_t rowBase = (size_t)b * LSEQ;

    for (int t0 = 0; t0 < LSEQ; t0 += 32) {
        for (int idx = tid; idx < 2048; idx += 128) {
            int t = idx >> 6, n = idx & 63;
            size_t ro = (rowBase + t0 + t) * (size_t)CD;
            sB[t][n] = g_xbc[ro + DI + n];
            sC[t][n] = g_xbc[ro + DI + DS + n];
        }
        for (int idx = tid; idx < 512; idx += 128) {
            int t = idx >> 4, p = idx & 15;
            sX[t][p] = g_xbc[(rowBase + t0 + t) * (size_t)CD + h * 64 + p0 + p];
        }
        if (tid < 32) {
            float d = g_dt[(rowBase + t0 + tid) * NH + h];
            sDt[tid] = d;
            sDA[tid] = __expf(d * Ah);
        }
        __syncthreads();

#pragma unroll 8
        for (int t = 0; t < 32; t++) {
            float dtv = sDt[t];
            float dav = sDA[t];
            float xv  = sX[t][pl];
            float s   = dtv * xv;
            float4 b0 = *(const float4*)&sB[t][q * 8];
            float4 b1 = *(const float4*)&sB[t][q * 8 + 4];
            float4 c0 = *(const float4*)&sC[t][q * 8];
            float4 c1 = *(const float4*)&sC[t][q * 8 + 4];
            float yv = 0.f;
            hh[0] = fmaf(hh[0], dav, s * b0.x); yv = fmaf(hh[0], c0.x, yv);
            hh[1] = fmaf(hh[1], dav, s * b0.y); yv = fmaf(hh[1], c0.y, yv);
            hh[2] = fmaf(hh[2], dav, s * b0.z); yv = fmaf(hh[2], c0.z, yv);
            hh[3] = fmaf(hh[3], dav, s * b0.w); yv = fmaf(hh[3], c0.w, yv);
            hh[4] = fmaf(hh[4], dav, s * b1.x); yv = fmaf(hh[4], c1.x, yv);
            hh[5] = fmaf(hh[5], dav, s * b1.y); yv = fmaf(hh[5], c1.y, yv);
            hh[6] = fmaf(hh[6], dav, s * b1.z); yv = fmaf(hh[6], c1.z, yv);
            hh[7] = fmaf(hh[7], dav, s * b1.w); yv = fmaf(hh[7], c1.w, yv);
            yv += __shfl_xor_sync(0xffffffffu, yv, 4);
            yv += __shfl_xor_sync(0xffffffffu, yv, 2);
            yv += __shfl_xor_sync(0xffffffffu, yv, 1);
            if (q == 0) sY[t][pl] = fmaf(Dh, xv, yv);
        }
        __syncthreads();
        for (int idx = tid; idx < 512; idx += 128) {
            int t = idx >> 4, p = idx & 15;
            g_y[(rowBase + t0 + t) * (size_t)DI + h * 64 + p0 + p] = sY[t][p];
        }
    }
}

// ---------------- y *= silu(z); RMSNorm * norm_w -> bf16 split -----------------
__global__ void gate_rms_kernel(const float* __restrict__ nw)
{
    int r = blockIdx.x, tid = threadIdx.x;
    const float* yr = g_y + (size_t)r * DI;
    const float* zr = g_zx + (size_t)r * DIP;
    float v[8]; float ss = 0.f;
#pragma unroll
    for (int i = 0; i < 8; i++) {
        int c = tid + i * 256;
        float z = zr[c];
        float t = yr[c] * (z / (1.f + __expf(-z)));
        v[i] = t;
        ss = fmaf(t, t, ss);
    }
    float dummy = 0.f;
    blockReduceSum2(ss, dummy);
    float scale = rsqrtf(ss * (1.f / 2048.f) + 1e-5f);
#pragma unroll
    for (int i = 0; i < 8; i++) {
        int c = tid + i * 256;
        split_store(v[i] * scale * nw[c], a2h, a2l, (size_t)r * DI + c);
    }
}

// ---------------- launch --------------------------------------------------------
extern "C" void kernel_launch(void* const* d_in, const int* in_sizes, int n_in,
                              void* d_out, int out_size)
{
    const float* x       = (const float*)d_in[0];
    const float* ln1_w   = (const float*)d_in[1];
    const float* ln1_b   = (const float*)d_in[2];
    const float* in_proj = (const float*)d_in[3];
    const float* conv_w  = (const float*)d_in[4];
    const float* conv_b  = (const float*)d_in[5];
    const float* dt_bias = (const float*)d_in[6];
    const float* A_log   = (const float*)d_in[7];
    const float* Dv      = (const float*)d_in[8];
    const float* norm_w  = (const float*)d_in[9];
    const float* out_w   = (const float*)d_in[10];
    const float* ln2_w   = (const float*)d_in[11];
    const float* ln2_b   = (const float*)d_in[12];
    const float* mlp_w1  = (const float*)d_in[13];
    const float* mlp_b1  = (const float*)d_in[14];
    const float* mlp_w2  = (const float*)d_in[15];
    const float* mlp_b2  = (const float*)d_in[16];
    float* out = (float*)d_out;

    static bool attr_done = false;
    if (!attr_done) {
        cudaFuncSetAttribute(mma_gemm<0>, cudaFuncAttributeMaxDynamicSharedMemorySize, GSMEM);
        cudaFuncSetAttribute(mma_gemm<1>, cudaFuncAttributeMaxDynamicSharedMemorySize, GSMEM);
        cudaFuncSetAttribute(mma_gemm<2>, cudaFuncAttributeMaxDynamicSharedMemorySize, GSMEM);
        cudaFuncSetAttribute(mma_gemm<3>, cudaFuncAttributeMaxDynamicSharedMemorySize, GSMEM);
        attr_done = true;
    }

    float *zx, *x1;
    cudaGetSymbolAddress((void**)&zx,  g_zx);
    cudaGetSymbolAddress((void**)&x1,  g_x1);
    __nv_bfloat16 *pa1h, *pa1l, *pb1h, *pb1l, *pa2h, *pa2l, *pb2h, *pb2l;
    __nv_bfloat16 *pa3h, *pa3l, *pb3h, *pb3l, *pa4h, *pa4l, *pb4h, *pb4l;
    cudaGetSymbolAddress((void**)&pa1h, a1h); cudaGetSymbolAddress((void**)&pa1l, a1l);
    cudaGetSymbolAddress((void**)&pb1h, b1h); cudaGetSymbolAddress((void**)&pb1l, b1l);
    cudaGetSymbolAddress((void**)&pa2h, a2h); cudaGetSymbolAddress((void**)&pa2l, a2l);
    cudaGetSymbolAddress((void**)&pb2h, b2h); cudaGetSymbolAddress((void**)&pb2l, b2l);
    cudaGetSymbolAddress((void**)&pa3h, a3h); cudaGetSymbolAddress((void**)&pa3l, a3l);
    cudaGetSymbolAddress((void**)&pb3h, b3h); cudaGetSymbolAddress((void**)&pb3l, b3l);
    cudaGetSymbolAddress((void**)&pa4h, a4h); cudaGetSymbolAddress((void**)&pa4l, a4l);
    cudaGetSymbolAddress((void**)&pb4h, b4h); cudaGetSymbolAddress((void**)&pb4l, b4l);

    // 1) in_proj weight split
    wsplit_kernel<<<(DIPP * DM + 255) / 256, 256>>>(in_proj, pb1h, pb1l, DIP * DM, DIPP * DM);
    // 2) LN1 -> a1 (bf16 split)
    ln_kernel<<<ROWS, 256>>>(x, ln1_w, ln1_b, pa1h, pa1l);
    // 3) out_proj weight split
    wsplit_kernel<<<(DM * DI + 255) / 256, 256>>>(out_w, pb2h, pb2l, DM * DI, DM * DI);
    // 4) in_proj GEMM: [4096,1024] @ [4256,1024]^T -> zx (fp32)   <-- ncu capture slot
    mma_gemm<0><<<dim3(DIPP / 128, ROWS / 128), 256, GSMEM>>>(pa1h, pa1l, pb1h, pb1l, DIP, DM,
                                                              zx, nullptr, nullptr, nullptr, nullptr);
    // 5) mlp weight splits (one kernel)
    wsplit2_kernel<<<(DFF * DM + DM * DFF + 255) / 256, 256>>>(mlp_w1, pb3h, pb3l, DFF * DM,
                                                               mlp_w2, pb4h, pb4l, DM * DFF);
    // 6) dt
    dt_kernel<<<(ROWS * NH) / 256, 256>>>(dt_bias);
    // 7) conv + silu (tiled)
    conv_kernel<<<dim3(17, ROWS / 32), 128>>>(conv_w, conv_b);
    // 8) scan
    scan_kernel<<<256, 128>>>(A_log, Dv);
    // 9) gate + rms -> a2 (bf16 split)
    gate_rms_kernel<<<ROWS, 256>>>(norm_w);
    // 10) out_proj + residual(x) -> x1 (fp32)
    mma_gemm<3><<<dim3(DM / 128, ROWS / 128), 256, GSMEM>>>(pa2h, pa2l, pb2h, pb2l, DM, DI,
                                                            x1, nullptr, x, nullptr, nullptr);
    // 11) LN2 -> a3 (bf16 split)
    ln_kernel<<<ROWS, 256>>>(x1, ln2_w, ln2_b, pa3h, pa3l);
    // 12) MLP up + bias + GELU -> a4 (bf16 split)
    mma_gemm<1><<<dim3(DFF / 128, ROWS / 128), 256, GSMEM>>>(pa3h, pa3l, pb3h, pb3l, DFF, DM,
                                                             nullptr, mlp_b1, nullptr, pa4h, pa4l);
    // 13) MLP down + bias + residual(x1) -> out
    mma_gemm<2><<<dim3(DM / 128, ROWS / 128), 256, GSMEM>>>(pa4h, pa4l, pb4h, pb4l, DM, DFF,
                                                            out, mlp_b2, x1, nullptr, nullptr);
}

// round 8
// speedup vs baseline: 2.2043x; 1.1549x over previous
#include <cuda_runtime.h>
#include <cuda_bf16.h>
#include <math.h>
#include <cstdint>

#define ROWS 4096      // BT * L
#define LSEQ 2048
#define DM   1024
#define DI   2048
#define NH   32
#define DS   64
#define CD   2176      // conv dim = DI + 2*DS
#define DIP  4256      // in_proj out dim
#define DIPP 4352      // padded to 34*128
#define DFF  4096

// ---------------- scratch (device globals; no runtime allocation) -------------
__device__ float g_zx [(size_t)ROWS * DIP];
__device__ float g_xbc[(size_t)ROWS * CD];
__device__ float g_dt [(size_t)ROWS * NH];
__device__ float g_y  [(size_t)ROWS * DI];
__device__ float g_x1 [(size_t)ROWS * DM];

// bf16 split buffers (hi/lo)
__device__ __nv_bfloat16 a1h[(size_t)ROWS * DM],  a1l[(size_t)ROWS * DM];   // LN1 out
__device__ __nv_bfloat16 b1h[(size_t)DIPP * DM],  b1l[(size_t)DIPP * DM];   // in_proj w (padded)
__device__ __nv_bfloat16 a2h[(size_t)ROWS * DI],  a2l[(size_t)ROWS * DI];   // gated/rms y
__device__ __nv_bfloat16 b2h[(size_t)DM * DI],    b2l[(size_t)DM * DI];     // out_proj w
__device__ __nv_bfloat16 a3h[(size_t)ROWS * DM],  a3l[(size_t)ROWS * DM];   // LN2 out
__device__ __nv_bfloat16 b3h[(size_t)DFF * DM],   b3l[(size_t)DFF * DM];    // mlp_w1
__device__ __nv_bfloat16 a4h[(size_t)ROWS * DFF], a4l[(size_t)ROWS * DFF];  // gelu(mid)
__device__ __nv_bfloat16 b4h[(size_t)DM * DFF],   b4l[(size_t)DM * DFF];    // mlp_w2

// ================= helpers =====================================================
__device__ __forceinline__ uint32_t smem_u32(const void* p) {
    uint32_t a;
    asm("{ .reg .u64 t; cvta.to.shared.u64 t, %1; cvt.u32.u64 %0, t; }" : "=r"(a) : "l"(p));
    return a;
}
#define CP_ASYNC16(dst, src) \
    asm volatile("cp.async.cg.shared.global [%0], [%1], 16;" :: "r"(dst), "l"(src) : "memory")
#define CP_COMMIT() asm volatile("cp.async.commit_group;" ::: "memory")
#define CP_WAIT(n)  asm volatile("cp.async.wait_group %0;" :: "n"(n) : "memory")

#define LDSM_X4(r0, r1, r2, r3, addr) \
    asm volatile("ldmatrix.sync.aligned.m8n8.x4.shared.b16 {%0,%1,%2,%3}, [%4];" \
        : "=r"(r0), "=r"(r1), "=r"(r2), "=r"(r3) : "r"(addr))

#define MMA16816(d, a0, a1, a2, a3, b0, b1) \
    asm volatile("mma.sync.aligned.m16n8k16.row.col.f32.bf16.bf16.f32 " \
        "{%0,%1,%2,%3},{%4,%5,%6,%7},{%8,%9},{%0,%1,%2,%3};" \
        : "+f"((d)[0]), "+f"((d)[1]), "+f"((d)[2]), "+f"((d)[3]) \
        : "r"(a0), "r"(a1), "r"(a2), "r"(a3), "r"(b0), "r"(b1))

#define SWZ(off) ((off) ^ (((off) >> 3) & 0x70))

__device__ __forceinline__ void blockReduceSum2(float &a, float &b) {
    __shared__ float sa[8], sb2[8];
    int lane = threadIdx.x & 31, w = threadIdx.x >> 5;
#pragma unroll
    for (int o = 16; o > 0; o >>= 1) {
        a += __shfl_xor_sync(0xffffffffu, a, o);
        b += __shfl_xor_sync(0xffffffffu, b, o);
    }
    if (lane == 0) { sa[w] = a; sb2[w] = b; }
    __syncthreads();
    a = sa[lane & 7]; b = sb2[lane & 7];
#pragma unroll
    for (int o = 4; o > 0; o >>= 1) {
        a += __shfl_xor_sync(0xffffffffu, a, o);
        b += __shfl_xor_sync(0xffffffffu, b, o);
    }
}
__device__ __forceinline__ void split_store(float v, __nv_bfloat16* hi, __nv_bfloat16* lo, size_t off) {
    __nv_bfloat16 h = __float2bfloat16_rn(v);
    hi[off] = h;
    lo[off] = __float2bfloat16_rn(v - __bfloat162float(h));
}

// ---------------- weight split kernel ------------------------------------------
__global__ void wsplit_kernel(const float* __restrict__ src, __nv_bfloat16* __restrict__ hi,
                              __nv_bfloat16* __restrict__ lo, int n, int ntot)
{
    int i = blockIdx.x * 256 + threadIdx.x;
    if (i >= ntot) return;
    float v = (i < n) ? src[i] : 0.f;
    split_store(v, hi, lo, (size_t)i);
}

// dual weight split: two sources back to back (for mlp_w1, mlp_w2)
__global__ void wsplit2_kernel(const float* __restrict__ s1, __nv_bfloat16* __restrict__ h1,
                               __nv_bfloat16* __restrict__ l1, int n1,
                               const float* __restrict__ s2, __nv_bfloat16* __restrict__ h2,
                               __nv_bfloat16* __restrict__ l2, int n2)
{
    int i = blockIdx.x * 256 + threadIdx.x;
    if (i < n1) split_store(s1[i], h1, l1, (size_t)i);
    else if (i < n1 + n2) { int j = i - n1; split_store(s2[j], h2, l2, (size_t)j); }
}

// ---------------- layernorm -> bf16 split --------------------------------------
__global__ void ln_kernel(const float* __restrict__ in, const float* __restrict__ w,
                          const float* __restrict__ bias,
                          __nv_bfloat16* __restrict__ ohi, __nv_bfloat16* __restrict__ olo)
{
    int r = blockIdx.x, tid = threadIdx.x;
    const float* xr = in + (size_t)r * DM;
    float v[4]; float s = 0.f, sq = 0.f;
#pragma unroll
    for (int i = 0; i < 4; i++) {
        v[i] = xr[tid + i * 256];
        s += v[i];
        sq = fmaf(v[i], v[i], sq);
    }
    blockReduceSum2(s, sq);
    float mu  = s * (1.f / DM);
    float var = sq * (1.f / DM) - mu * mu;
    float inv = rsqrtf(var + 1e-5f);
#pragma unroll
    for (int i = 0; i < 4; i++) {
        int c = tid + i * 256;
        float o = (v[i] - mu) * inv * w[c] + bias[c];
        split_store(o, ohi, olo, (size_t)r * DM + c);
    }
}

// ================= mma.sync split-bf16 GEMM, 3-stage, SW128 packed =============
// C[M,N] = A[M,K] @ B[N,K]^T with A ~ Ahi+Alo, B ~ Bhi+Blo (3 MMA terms)
// CTA tile 128x128x32, 256 threads, warp tile 64x32, 2 CTAs/SM.
// SMEM per stage: tile A = 128 rows x [Ah(64B) | Al(64B)] = 16KB, tile B same.
#define TILEB  16384
#define STAGEB (2 * TILEB)               // 32768
#define NSTAGE 3
#define GSMEM  (NSTAGE * STAGEB)         // 98304

template<int EPI>
__global__ void __launch_bounds__(256, 2)
mma_gemm(const __nv_bfloat16* __restrict__ Ahi, const __nv_bfloat16* __restrict__ Alo,
         const __nv_bfloat16* __restrict__ Bhi, const __nv_bfloat16* __restrict__ Blo,
         int N, int K,
         float* __restrict__ C, const float* __restrict__ bias, const float* __restrict__ res,
         __nv_bfloat16* __restrict__ Ohi, __nv_bfloat16* __restrict__ Olo)
{
    extern __shared__ char smem[];
    const uint32_t sbase = smem_u32(smem);
    const int tid = threadIdx.x;
    const int l   = tid & 31;
    const int wid = tid >> 5;
    const int wr  = wid >> 2;           // 0..1 : warp row (64 rows each)
    const int wc  = wid & 3;            // 0..3 : warp col (32 cols each)
    const int bn  = blockIdx.x, bm = blockIdx.y;

    // tile base pointers
    const __nv_bfloat16* base[4];
    base[0] = Ahi + (size_t)(bm * 128) * K;
    base[1] = Alo + (size_t)(bm * 128) * K;
    base[2] = Bhi + (size_t)(bn * 128) * K;
    base[3] = Blo + (size_t)(bn * 128) * K;

    // per-thread cp.async decomposition: 2048 16B-copies per stage, 8 per thread
    // idx -> tile (A/B), row (0..127), ch (0..7): ch<4 = hi k-subchunk, ch>=4 = lo
    const __nv_bfloat16* csrc[8];
    uint32_t cdst[8];
#pragma unroll
    for (int t = 0; t < 8; t++) {
        int idx  = tid + (t << 8);
        int tile = idx >> 10;
        int row  = (idx >> 3) & 127;
        int ch   = idx & 7;
        int hilo = ch >> 2;
        int c    = ch & 3;
        uint32_t off = (uint32_t)tile * TILEB + (uint32_t)row * 128 + (uint32_t)ch * 16;
        cdst[t] = SWZ(off);
        csrc[t] = base[tile * 2 + hilo] + (size_t)row * K + c * 8;
    }

    const int NC = K >> 5;    // k chunks of 32

    // prologue: stages 0,1
#pragma unroll
    for (int t = 0; t < 8; t++) CP_ASYNC16(sbase + cdst[t], csrc[t]);
    CP_COMMIT();
#pragma unroll
    for (int t = 0; t < 8; t++) CP_ASYNC16(sbase + STAGEB + cdst[t], csrc[t] + 32);
    CP_COMMIT();

    float acc[4][4][4];
#pragma unroll
    for (int mi = 0; mi < 4; mi++)
#pragma unroll
        for (int ni = 0; ni < 4; ni++)
#pragma unroll
            for (int c = 0; c < 4; c++) acc[mi][ni][c] = 0.f;

    // unswizzled per-lane logical offsets within a tile (bytes)
    // A: row = wr*64 + mi*16 + (l&15); kbyte = (l>>4)*16 (+kk*32, +64 for lo)
    const uint32_t aBase = ((uint32_t)(wr * 64 + (l & 15))) * 128 + (uint32_t)(l >> 4) * 16;
    // B: row = wc*32 + ni*16 + (l&7) + ((l>>4)<<3); kbyte = ((l>>3)&1)*16
    const uint32_t bBase = ((uint32_t)(wc * 32 + (l & 7) + ((l >> 4) << 3))) * 128
                         + (uint32_t)((l >> 3) & 1) * 16;

    int sc = 0;               // stage of current chunk
    for (int cch = 0; cch < NC; cch++) {
        if (cch < NC - 1) { CP_WAIT(1); } else { CP_WAIT(0); }
        __syncthreads();

        // issue chunk cch+2 into stage (sc+2)%3
        if (cch + 2 < NC) {
            int sn = sc + 2; if (sn >= NSTAGE) sn -= NSTAGE;
            const uint32_t sd = sbase + sn * STAGEB;
            const int k0 = (cch + 2) << 5;
#pragma unroll
            for (int t = 0; t < 8; t++) CP_ASYNC16(sd + cdst[t], csrc[t] + k0);
            CP_COMMIT();
        }

        const uint32_t stA = sbase + sc * STAGEB;
        const uint32_t stB = stA + TILEB;
#pragma unroll
        for (int kk = 0; kk < 2; kk++) {
            const uint32_t kOff = (uint32_t)kk * 32;
            uint32_t ah[4][4], al[4][4], bh[2][4], bl[2][4];
#pragma unroll
            for (int mi = 0; mi < 4; mi++) {
                uint32_t off = aBase + (uint32_t)(mi * 16) * 128 + kOff;
                LDSM_X4(ah[mi][0], ah[mi][1], ah[mi][2], ah[mi][3], stA + SWZ(off));
            }
#pragma unroll
            for (int ni = 0; ni < 2; ni++) {
                uint32_t off = bBase + (uint32_t)(ni * 16) * 128 + kOff;
                LDSM_X4(bh[ni][0], bh[ni][1], bh[ni][2], bh[ni][3], stB + SWZ(off));
            }
#pragma unroll
            for (int mi = 0; mi < 4; mi++)
#pragma unroll
                for (int ni = 0; ni < 4; ni++) {
                    const uint32_t* bq = bh[ni >> 1];
                    int o = (ni & 1) * 2;
                    MMA16816(acc[mi][ni], ah[mi][0], ah[mi][1], ah[mi][2], ah[mi][3], bq[o], bq[o + 1]);
                }
#pragma unroll
            for (int ni = 0; ni < 2; ni++) {
                uint32_t off = bBase + (uint32_t)(ni * 16) * 128 + kOff + 64;   // lo half
                LDSM_X4(bl[ni][0], bl[ni][1], bl[ni][2], bl[ni][3], stB + SWZ(off));
            }
#pragma unroll
            for (int mi = 0; mi < 4; mi++)
#pragma unroll
                for (int ni = 0; ni < 4; ni++) {
                    const uint32_t* bq = bl[ni >> 1];
                    int o = (ni & 1) * 2;
                    MMA16816(acc[mi][ni], ah[mi][0], ah[mi][1], ah[mi][2], ah[mi][3], bq[o], bq[o + 1]);
                }
#pragma unroll
            for (int mi = 0; mi < 4; mi++) {
                uint32_t off = aBase + (uint32_t)(mi * 16) * 128 + kOff + 64;   // lo half
                LDSM_X4(al[mi][0], al[mi][1], al[mi][2], al[mi][3], stA + SWZ(off));
            }
#pragma unroll
            for (int mi = 0; mi < 4; mi++)
#pragma unroll
                for (int ni = 0; ni < 4; ni++) {
                    const uint32_t* bq = bh[ni >> 1];
                    int o = (ni & 1) * 2;
                    MMA16816(acc[mi][ni], al[mi][0], al[mi][1], al[mi][2], al[mi][3], bq[o], bq[o + 1]);
                }
        }
        sc++; if (sc >= NSTAGE) sc = 0;
    }

    // ---- epilogue: registers -> global directly ----
    const int rowb = bm * 128 + wr * 64 + (l >> 2);
    const int colb = bn * 128 + wc * 32 + (l & 3) * 2;
#pragma unroll
    for (int mi = 0; mi < 4; mi++) {
#pragma unroll
        for (int ni = 0; ni < 4; ni++) {
            int cc = colb + ni * 8;
            if (cc < N) {
#pragma unroll
                for (int h = 0; h < 2; h++) {
                    int rr = rowb + mi * 16 + h * 8;
                    size_t off = (size_t)rr * N + cc;
                    float v0 = acc[mi][ni][h * 2 + 0];
                    float v1 = acc[mi][ni][h * 2 + 1];
                    if (EPI == 0) {
                        *(float2*)(C + off) = make_float2(v0, v1);
                    } else if (EPI == 3) {
                        *(float2*)(C + off) = make_float2(v0 + res[off], v1 + res[off + 1]);
                    } else if (EPI == 2) {
                        *(float2*)(C + off) = make_float2(v0 + bias[cc] + res[off],
                                                          v1 + bias[cc + 1] + res[off + 1]);
                    } else {
                        v0 += bias[cc];
                        v1 += bias[cc + 1];
                        v0 = 0.5f * v0 * (1.f + erff(v0 * 0.70710678118654752f));
                        v1 = 0.5f * v1 * (1.f + erff(v1 * 0.70710678118654752f));
                        __nv_bfloat16 h0 = __float2bfloat16_rn(v0);
                        __nv_bfloat16 h1 = __float2bfloat16_rn(v1);
                        __nv_bfloat16 l0 = __float2bfloat16_rn(v0 - __bfloat162float(h0));
                        __nv_bfloat16 l1 = __float2bfloat16_rn(v1 - __bfloat162float(h1));
                        *(__nv_bfloat162*)(Ohi + off) = __nv_bfloat162(h0, h1);
                        *(__nv_bfloat162*)(Olo + off) = __nv_bfloat162(l0, l1);
                    }
                }
            }
        }
    }
}

// ---------------- dt = softplus(raw + dt_bias) ---------------------------------
__global__ void dt_kernel(const float* __restrict__ dtb)
{
    int idx = blockIdx.x * 256 + threadIdx.x;
    if (idx >= ROWS * NH) return;
    int r = idx >> 5, h = idx & 31;
    float u = g_zx[(size_t)r * DIP + (DI + CD) + h] + dtb[h];
    g_dt[idx] = (u > 20.f) ? u : log1pf(__expf(u));
}

// ---------------- tiled causal depthwise conv (width 4) + SiLU -----------------
__global__ void __launch_bounds__(128)
conv_kernel(const float* __restrict__ cw, const float* __restrict__ cb)
{
    __shared__ float sx[35][128];
    const int tid = threadIdx.x;
    const int c   = blockIdx.x * 128 + tid;     // 0..2175
    const int r0  = blockIdx.y * 32;            // global row base

    for (int idx = tid; idx < 35 * 128; idx += 128) {
        int i   = idx >> 7;
        int col = idx & 127;
        int g   = r0 - 3 + i;
        sx[i][col] = (g >= 0) ? g_zx[(size_t)g * DIP + DI + blockIdx.x * 128 + col] : 0.f;
    }
    __syncthreads();

    const float w0 = cw[c * 4 + 0], w1 = cw[c * 4 + 1], w2 = cw[c * 4 + 2], w3 = cw[c * 4 + 3];
    const float bias = cb[c];
#pragma unroll 4
    for (int i = 0; i < 32; i++) {
        int row = r0 + i;
        int l = row & (LSEQ - 1);
        float acc = bias;
        acc = fmaf(sx[i + 3][tid], w3, acc);
        if (l >= 1) acc = fmaf(sx[i + 2][tid], w2, acc);
        if (l >= 2) acc = fmaf(sx[i + 1][tid], w1, acc);
        if (l >= 3) acc = fmaf(sx[i + 0][tid], w0, acc);
        g_xbc[(size_t)row * CD + c] = acc / (1.f + __expf(-acc));
    }
}

// ---------------- sequential SSM scan ------------------------------------------
__global__ void __launch_bounds__(128)
scan_kernel(const float* __restrict__ A_log, const float* __restrict__ Dvec)
{
    const int blk = blockIdx.x;
    const int b   = blk >> 7;
    const int rem = blk & 127;
    const int h   = rem >> 2;
    const int pc  = rem & 3;
    const int p0  = pc * 16;
    const int tid = threadIdx.x;
    const int q   = tid & 7;
    const int pl  = tid >> 3;

    const float Ah = -__expf(A_log[h]);
    const float Dh = Dvec[h];

    __shared__ float sB[32][64];
    __shared__ float sC[32][64];
    __shared__ float sX[32][16];
    __shared__ float sDt[32];
    __shared__ float sDA[32];
    __shared__ float sY[32][16];

    float hh[8];
#pragma unroll
    for (int i = 0; i < 8; i++) hh[i] = 0.f;

    const size_t rowBase = (size_t)b * LSEQ;

    for (int t0 = 0; t0 < LSEQ; t0 += 32) {
        for (int idx = tid; idx < 2048; idx += 128) {
            int t = idx >> 6, n = idx & 63;
            size_t ro = (rowBase + t0 + t) * (size_t)CD;
            sB[t][n] = g_xbc[ro + DI + n];
            sC[t][n] = g_xbc[ro + DI + DS + n];
        }
        for (int idx = tid; idx < 512; idx += 128) {
            int t = idx >> 4, p = idx & 15;
            sX[t][p] = g_xbc[(rowBase + t0 + t) * (size_t)CD + h * 64 + p0 + p];
        }
        if (tid < 32) {
            float d = g_dt[(rowBase + t0 + tid) * NH + h];
            sDt[tid] = d;
            sDA[tid] = __expf(d * Ah);
        }
        __syncthreads();

#pragma unroll 8
        for (int t = 0; t < 32; t++) {
            float dtv = sDt[t];
            float dav = sDA[t];
            float xv  = sX[t][pl];
            float s   = dtv * xv;
            float4 b0 = *(const float4*)&sB[t][q * 8];
            float4 b1 = *(const float4*)&sB[t][q * 8 + 4];
            float4 c0 = *(const float4*)&sC[t][q * 8];
            float4 c1 = *(const float4*)&sC[t][q * 8 + 4];
            float yv = 0.f;
            hh[0] = fmaf(hh[0], dav, s * b0.x); yv = fmaf(hh[0], c0.x, yv);
            hh[1] = fmaf(hh[1], dav, s * b0.y); yv = fmaf(hh[1], c0.y, yv);
            hh[2] = fmaf(hh[2], dav, s * b0.z); yv = fmaf(hh[2], c0.z, yv);
            hh[3] = fmaf(hh[3], dav, s * b0.w); yv = fmaf(hh[3], c0.w, yv);
            hh[4] = fmaf(hh[4], dav, s * b1.x); yv = fmaf(hh[4], c1.x, yv);
            hh[5] = fmaf(hh[5], dav, s * b1.y); yv = fmaf(hh[5], c1.y, yv);
            hh[6] = fmaf(hh[6], dav, s * b1.z); yv = fmaf(hh[6], c1.z, yv);
            hh[7] = fmaf(hh[7], dav, s * b1.w); yv = fmaf(hh[7], c1.w, yv);
            yv += __shfl_xor_sync(0xffffffffu, yv, 4);
            yv += __shfl_xor_sync(0xffffffffu, yv, 2);
            yv += __shfl_xor_sync(0xffffffffu, yv, 1);
            if (q == 0) sY[t][pl] = fmaf(Dh, xv, yv);
        }
        __syncthreads();
        for (int idx = tid; idx < 512; idx += 128) {
            int t = idx >> 4, p = idx & 15;
            g_y[(rowBase + t0 + t) * (size_t)DI + h * 64 + p0 + p] = sY[t][p];
        }
    }
}

// ---------------- y *= silu(z); RMSNorm * norm_w -> bf16 split -----------------
__global__ void gate_rms_kernel(const float* __restrict__ nw)
{
    int r = blockIdx.x, tid = threadIdx.x;
    const float* yr = g_y + (size_t)r * DI;
    const float* zr = g_zx + (size_t)r * DIP;
    float v[8]; float ss = 0.f;
#pragma unroll
    for (int i = 0; i < 8; i++) {
        int c = tid + i * 256;
        float z = zr[c];
        float t = yr[c] * (z / (1.f + __expf(-z)));
        v[i] = t;
        ss = fmaf(t, t, ss);
    }
    float dummy = 0.f;
    blockReduceSum2(ss, dummy);
    float scale = rsqrtf(ss * (1.f / 2048.f) + 1e-5f);
#pragma unroll
    for (int i = 0; i < 8; i++) {
        int c = tid + i * 256;
        split_store(v[i] * scale * nw[c], a2h, a2l, (size_t)r * DI + c);
    }
}

// ---------------- launch --------------------------------------------------------
extern "C" void kernel_launch(void* const* d_in, const int* in_sizes, int n_in,
                              void* d_out, int out_size)
{
    const float* x       = (const float*)d_in[0];
    const float* ln1_w   = (const float*)d_in[1];
    const float* ln1_b   = (const float*)d_in[2];
    const float* in_proj = (const float*)d_in[3];
    const float* conv_w  = (const float*)d_in[4];
    const float* conv_b  = (const float*)d_in[5];
    const float* dt_bias = (const float*)d_in[6];
    const float* A_log   = (const float*)d_in[7];
    const float* Dv      = (const float*)d_in[8];
    const float* norm_w  = (const float*)d_in[9];
    const float* out_w   = (const float*)d_in[10];
    const float* ln2_w   = (const float*)d_in[11];
    const float* ln2_b   = (const float*)d_in[12];
    const float* mlp_w1  = (const float*)d_in[13];
    const float* mlp_b1  = (const float*)d_in[14];
    const float* mlp_w2  = (const float*)d_in[15];
    const float* mlp_b2  = (const float*)d_in[16];
    float* out = (float*)d_out;

    static bool attr_done = false;
    if (!attr_done) {
        cudaFuncSetAttribute(mma_gemm<0>, cudaFuncAttributeMaxDynamicSharedMemorySize, GSMEM);
        cudaFuncSetAttribute(mma_gemm<1>, cudaFuncAttributeMaxDynamicSharedMemorySize, GSMEM);
        cudaFuncSetAttribute(mma_gemm<2>, cudaFuncAttributeMaxDynamicSharedMemorySize, GSMEM);
        cudaFuncSetAttribute(mma_gemm<3>, cudaFuncAttributeMaxDynamicSharedMemorySize, GSMEM);
        attr_done = true;
    }

    float *zx, *x1;
    cudaGetSymbolAddress((void**)&zx,  g_zx);
    cudaGetSymbolAddress((void**)&x1,  g_x1);
    __nv_bfloat16 *pa1h, *pa1l, *pb1h, *pb1l, *pa2h, *pa2l, *pb2h, *pb2l;
    __nv_bfloat16 *pa3h, *pa3l, *pb3h, *pb3l, *pa4h, *pa4l, *pb4h, *pb4l;
    cudaGetSymbolAddress((void**)&pa1h, a1h); cudaGetSymbolAddress((void**)&pa1l, a1l);
    cudaGetSymbolAddress((void**)&pb1h, b1h); cudaGetSymbolAddress((void**)&pb1l, b1l);
    cudaGetSymbolAddress((void**)&pa2h, a2h); cudaGetSymbolAddress((void**)&pa2l, a2l);
    cudaGetSymbolAddress((void**)&pb2h, b2h); cudaGetSymbolAddress((void**)&pb2l, b2l);
    cudaGetSymbolAddress((void**)&pa3h, a3h); cudaGetSymbolAddress((void**)&pa3l, a3l);
    cudaGetSymbolAddress((void**)&pb3h, b3h); cudaGetSymbolAddress((void**)&pb3l, b3l);
    cudaGetSymbolAddress((void**)&pa4h, a4h); cudaGetSymbolAddress((void**)&pa4l, a4l);
    cudaGetSymbolAddress((void**)&pb4h, b4h); cudaGetSymbolAddress((void**)&pb4l, b4l);

    // 1) in_proj weight split
    wsplit_kernel<<<(DIPP * DM + 255) / 256, 256>>>(in_proj, pb1h, pb1l, DIP * DM, DIPP * DM);
    // 2) LN1 -> a1 (bf16 split)
    ln_kernel<<<ROWS, 256>>>(x, ln1_w, ln1_b, pa1h, pa1l);
    // 3) out_proj weight split
    wsplit_kernel<<<(DM * DI + 255) / 256, 256>>>(out_w, pb2h, pb2l, DM * DI, DM * DI);
    // 4) in_proj GEMM -> zx (fp32)   <-- ncu capture slot
    mma_gemm<0><<<dim3(DIPP / 128, ROWS / 128), 256, GSMEM>>>(pa1h, pa1l, pb1h, pb1l, DIP, DM,
                                                              zx, nullptr, nullptr, nullptr, nullptr);
    // 5) mlp weight splits (one kernel)
    wsplit2_kernel<<<(DFF * DM + DM * DFF + 255) / 256, 256>>>(mlp_w1, pb3h, pb3l, DFF * DM,
                                                               mlp_w2, pb4h, pb4l, DM * DFF);
    // 6) dt
    dt_kernel<<<(ROWS * NH) / 256, 256>>>(dt_bias);
    // 7) conv + silu (tiled)
    conv_kernel<<<dim3(17, ROWS / 32), 128>>>(conv_w, conv_b);
    // 8) scan
    scan_kernel<<<256, 128>>>(A_log, Dv);
    // 9) gate + rms -> a2 (bf16 split)
    gate_rms_kernel<<<ROWS, 256>>>(norm_w);
    // 10) out_proj + residual(x) -> x1 (fp32)
    mma_gemm<3><<<dim3(DM / 128, ROWS / 128), 256, GSMEM>>>(pa2h, pa2l, pb2h, pb2l, DM, DI,
                                                            x1, nullptr, x, nullptr, nullptr);
    // 11) LN2 -> a3 (bf16 split)
    ln_kernel<<<ROWS, 256>>>(x1, ln2_w, ln2_b, pa3h, pa3l);
    // 12) MLP up + bias + GELU -> a4 (bf16 split)
    mma_gemm<1><<<dim3(DFF / 128, ROWS / 128), 256, GSMEM>>>(pa3h, pa3l, pb3h, pb3l, DFF, DM,
                                                             nullptr, mlp_b1, nullptr, pa4h, pa4l);
    // 13) MLP down + bias + residual(x1) -> out
    mma_gemm<2><<<dim3(DM / 128, ROWS / 128), 256, GSMEM>>>(pa4h, pa4l, pb4h, pb4l, DM, DFF,
                                                            out, mlp_b2, x1, nullptr, nullptr);
}

// round 11
// speedup vs baseline: 2.2424x; 1.0173x over previous
#include <cuda_runtime.h>
#include <cuda_bf16.h>
#include <math.h>
#include <cstdint>

#define ROWS 4096      // BT * L
#define LSEQ 2048
#define DM   1024
#define DI   2048
#define NH   32
#define DS   64
#define CD   2176      // conv dim = DI + 2*DS
#define DIP  4256      // in_proj out dim
#define DIPP 4352      // padded to 34*128
#define DFF  4096

// ---------------- scratch (device globals; no runtime allocation) -------------
__device__ float g_zx [(size_t)ROWS * DIP];
__device__ float g_xbc[(size_t)ROWS * CD];
__device__ float g_dt [(size_t)ROWS * NH];
__device__ float g_y  [(size_t)ROWS * DI];
__device__ float g_x1 [(size_t)ROWS * DM];

// bf16 split buffers (hi/lo)
__device__ __nv_bfloat16 a1h[(size_t)ROWS * DM],  a1l[(size_t)ROWS * DM];   // LN1 out
__device__ __nv_bfloat16 b1h[(size_t)DIPP * DM],  b1l[(size_t)DIPP * DM];   // in_proj w (padded)
__device__ __nv_bfloat16 a2h[(size_t)ROWS * DI],  a2l[(size_t)ROWS * DI];   // gated/rms y
__device__ __nv_bfloat16 b2h[(size_t)DM * DI],    b2l[(size_t)DM * DI];     // out_proj w
__device__ __nv_bfloat16 a3h[(size_t)ROWS * DM],  a3l[(size_t)ROWS * DM];   // LN2 out
__device__ __nv_bfloat16 b3h[(size_t)DFF * DM],   b3l[(size_t)DFF * DM];    // mlp_w1
__device__ __nv_bfloat16 a4h[(size_t)ROWS * DFF], a4l[(size_t)ROWS * DFF];  // gelu(mid)
__device__ __nv_bfloat16 b4h[(size_t)DM * DFF],   b4l[(size_t)DM * DFF];    // mlp_w2

// ================= helpers =====================================================
__device__ __forceinline__ uint32_t smem_u32(const void* p) {
    uint32_t a;
    asm("{ .reg .u64 t; cvta.to.shared.u64 t, %1; cvt.u32.u64 %0, t; }" : "=r"(a) : "l"(p));
    return a;
}
#define CP_ASYNC16(dst, src) \
    asm volatile("cp.async.cg.shared.global [%0], [%1], 16;" :: "r"(dst), "l"(src) : "memory")
#define CP_COMMIT() asm volatile("cp.async.commit_group;" ::: "memory")
#define CP_WAIT(n)  asm volatile("cp.async.wait_group %0;" :: "n"(n) : "memory")

#define LDSM_X4(r0, r1, r2, r3, addr) \
    asm volatile("ldmatrix.sync.aligned.m8n8.x4.shared.b16 {%0,%1,%2,%3}, [%4];" \
        : "=r"(r0), "=r"(r1), "=r"(r2), "=r"(r3) : "r"(addr))

#define MMA16816(d, a0, a1, a2, a3, b0, b1) \
    asm volatile("mma.sync.aligned.m16n8k16.row.col.f32.bf16.bf16.f32 " \
        "{%0,%1,%2,%3},{%4,%5,%6,%7},{%8,%9},{%0,%1,%2,%3};" \
        : "+f"((d)[0]), "+f"((d)[1]), "+f"((d)[2]), "+f"((d)[3]) \
        : "r"(a0), "r"(a1), "r"(a2), "r"(a3), "r"(b0), "r"(b1))

#define SWZ(off) ((off) ^ (((off) >> 3) & 0x70))

__device__ __forceinline__ void blockReduceSum2(float &a, float &b) {
    __shared__ float sa[8], sb2[8];
    int lane = threadIdx.x & 31, w = threadIdx.x >> 5;
#pragma unroll
    for (int o = 16; o > 0; o >>= 1) {
        a += __shfl_xor_sync(0xffffffffu, a, o);
        b += __shfl_xor_sync(0xffffffffu, b, o);
    }
    if (lane == 0) { sa[w] = a; sb2[w] = b; }
    __syncthreads();
    a = sa[lane & 7]; b = sb2[lane & 7];
#pragma unroll
    for (int o = 4; o > 0; o >>= 1) {
        a += __shfl_xor_sync(0xffffffffu, a, o);
        b += __shfl_xor_sync(0xffffffffu, b, o);
    }
}
// pack two floats into bf16x2 (hi) and return; residuals for lo
__device__ __forceinline__ uint32_t pack_hi2(float a, float b, float &ra, float &rb) {
    __nv_bfloat162 h = __floats2bfloat162_rn(a, b);
    ra = a - __low2float(h);
    rb = b - __high2float(h);
    uint32_t u; __builtin_memcpy(&u, &h, 4);
    return u;
}
__device__ __forceinline__ uint32_t pack2(float a, float b) {
    __nv_bfloat162 h = __floats2bfloat162_rn(a, b);
    uint32_t u; __builtin_memcpy(&u, &h, 4);
    return u;
}
__device__ __forceinline__ void split_store(float v, __nv_bfloat16* hi, __nv_bfloat16* lo, size_t off) {
    __nv_bfloat16 h = __float2bfloat16_rn(v);
    hi[off] = h;
    lo[off] = __float2bfloat16_rn(v - __bfloat162float(h));
}

// ---------------- weight split kernel (vectorized, float4 granules) ------------
__global__ void wsplit_kernel(const float4* __restrict__ src, uint2* __restrict__ hi,
                              uint2* __restrict__ lo, int n4, int ntot4)
{
    int i = blockIdx.x * 256 + threadIdx.x;
    if (i >= ntot4) return;
    float4 v = (i < n4) ? src[i] : make_float4(0.f, 0.f, 0.f, 0.f);
    float r0, r1, r2, r3;
    uint2 h, l;
    h.x = pack_hi2(v.x, v.y, r0, r1);
    h.y = pack_hi2(v.z, v.w, r2, r3);
    l.x = pack2(r0, r1);
    l.y = pack2(r2, r3);
    hi[i] = h;
    lo[i] = l;
}

// dual weight split (mlp_w1, mlp_w2), vectorized
__global__ void wsplit2_kernel(const float4* __restrict__ s1, uint2* __restrict__ h1,
                               uint2* __restrict__ l1, int n41,
                               const float4* __restrict__ s2, uint2* __restrict__ h2,
                               uint2* __restrict__ l2, int n42)
{
    int i = blockIdx.x * 256 + threadIdx.x;
    const float4* s; uint2 *ph, *pl; int j;
    if (i < n41) { s = s1; ph = h1; pl = l1; j = i; }
    else if (i < n41 + n42) { s = s2; ph = h2; pl = l2; j = i - n41; }
    else return;
    float4 v = s[j];
    float r0, r1, r2, r3;
    uint2 h, l;
    h.x = pack_hi2(v.x, v.y, r0, r1);
    h.y = pack_hi2(v.z, v.w, r2, r3);
    l.x = pack2(r0, r1);
    l.y = pack2(r2, r3);
    ph[j] = h;
    pl[j] = l;
}

// ---------------- layernorm -> bf16 split (vectorized) -------------------------
__global__ void ln_kernel(const float* __restrict__ in, const float* __restrict__ w,
                          const float* __restrict__ bias,
                          __nv_bfloat16* __restrict__ ohi, __nv_bfloat16* __restrict__ olo)
{
    int r = blockIdx.x, tid = threadIdx.x;
    const int c0 = tid * 4;
    float4 v = *(const float4*)(in + (size_t)r * DM + c0);
    float s  = v.x + v.y + v.z + v.w;
    float sq = fmaf(v.x, v.x, fmaf(v.y, v.y, fmaf(v.z, v.z, v.w * v.w)));
    blockReduceSum2(s, sq);
    float mu  = s * (1.f / DM);
    float var = sq * (1.f / DM) - mu * mu;
    float inv = rsqrtf(var + 1e-5f);
    float4 wv = *(const float4*)(w + c0);
    float4 bv = *(const float4*)(bias + c0);
    float o0 = (v.x - mu) * inv * wv.x + bv.x;
    float o1 = (v.y - mu) * inv * wv.y + bv.y;
    float o2 = (v.z - mu) * inv * wv.z + bv.z;
    float o3 = (v.w - mu) * inv * wv.w + bv.w;
    float r0, r1, r2, r3;
    uint2 h, l;
    h.x = pack_hi2(o0, o1, r0, r1);
    h.y = pack_hi2(o2, o3, r2, r3);
    l.x = pack2(r0, r1);
    l.y = pack2(r2, r3);
    size_t off = (size_t)r * DM + c0;
    *(uint2*)(ohi + off) = h;
    *(uint2*)(olo + off) = l;
}

// ================= mma.sync split-bf16 GEMM, 3-stage, SW128 packed =============
// C[M,N] = A[M,K] @ B[N,K]^T with A ~ Ahi+Alo, B ~ Bhi+Blo (3 MMA terms)
// CTA tile 128x128x32, 256 threads, warp tile 64x32, 2 CTAs/SM.
#define TILEB  16384
#define STAGEB (2 * TILEB)               // 32768
#define NSTAGE 3
#define GSMEM  (NSTAGE * STAGEB)         // 98304

template<int EPI>
__global__ void __launch_bounds__(256, 2)
mma_gemm(const __nv_bfloat16* __restrict__ Ahi, const __nv_bfloat16* __restrict__ Alo,
         const __nv_bfloat16* __restrict__ Bhi, const __nv_bfloat16* __restrict__ Blo,
         int N, int K,
         float* __restrict__ C, const float* __restrict__ bias, const float* __restrict__ res,
         __nv_bfloat16* __restrict__ Ohi, __nv_bfloat16* __restrict__ Olo)
{
    extern __shared__ char smem[];
    const uint32_t sbase = smem_u32(smem);
    const int tid = threadIdx.x;
    const int l   = tid & 31;
    const int wid = tid >> 5;
    const int wr  = wid >> 2;           // 0..1 : warp row (64 rows each)
    const int wc  = wid & 3;            // 0..3 : warp col (32 cols each)
    const int bn  = blockIdx.x, bm = blockIdx.y;

    // tile base pointers
    const __nv_bfloat16* base[4];
    base[0] = Ahi + (size_t)(bm * 128) * K;
    base[1] = Alo + (size_t)(bm * 128) * K;
    base[2] = Bhi + (size_t)(bn * 128) * K;
    base[3] = Blo + (size_t)(bn * 128) * K;

    // per-thread cp.async decomposition: 2048 16B-copies per stage, 8 per thread
    const __nv_bfloat16* csrc[8];
    uint32_t cdst[8];
#pragma unroll
    for (int t = 0; t < 8; t++) {
        int idx  = tid + (t << 8);
        int tile = idx >> 10;
        int row  = (idx >> 3) & 127;
        int ch   = idx & 7;
        int hilo = ch >> 2;
        int c    = ch & 3;
        uint32_t off = (uint32_t)tile * TILEB + (uint32_t)row * 128 + (uint32_t)ch * 16;
        cdst[t] = SWZ(off);
        csrc[t] = base[tile * 2 + hilo] + (size_t)row * K + c * 8;
    }

    const int NC = K >> 5;    // k chunks of 32

    // prologue: stages 0,1
#pragma unroll
    for (int t = 0; t < 8; t++) CP_ASYNC16(sbase + cdst[t], csrc[t]);
    CP_COMMIT();
#pragma unroll
    for (int t = 0; t < 8; t++) CP_ASYNC16(sbase + STAGEB + cdst[t], csrc[t] + 32);
    CP_COMMIT();

    float acc[4][4][4];
#pragma unroll
    for (int mi = 0; mi < 4; mi++)
#pragma unroll
        for (int ni = 0; ni < 4; ni++)
#pragma unroll
            for (int c = 0; c < 4; c++) acc[mi][ni][c] = 0.f;

    // unswizzled per-lane logical offsets within a tile (bytes)
    const uint32_t aBase = ((uint32_t)(wr * 64 + (l & 15))) * 128 + (uint32_t)(l >> 4) * 16;
    const uint32_t bBase = ((uint32_t)(wc * 32 + (l & 7) + ((l >> 4) << 3))) * 128
                         + (uint32_t)((l >> 3) & 1) * 16;

    int sc = 0;               // stage of current chunk
    for (int cch = 0; cch < NC; cch++) {
        if (cch < NC - 1) { CP_WAIT(1); } else { CP_WAIT(0); }
        __syncthreads();

        // issue chunk cch+2 into stage (sc+2)%3
        if (cch + 2 < NC) {
            int sn = sc + 2; if (sn >= NSTAGE) sn -= NSTAGE;
            const uint32_t sd = sbase + sn * STAGEB;
            const int k0 = (cch + 2) << 5;
#pragma unroll
            for (int t = 0; t < 8; t++) CP_ASYNC16(sd + cdst[t], csrc[t] + k0);
            CP_COMMIT();
        }

        const uint32_t stA = sbase + sc * STAGEB;
        const uint32_t stB = stA + TILEB;
#pragma unroll
        for (int kk = 0; kk < 2; kk++) {
            const uint32_t kOff = (uint32_t)kk * 32;
            uint32_t ah[4][4], bh[2][4];
#pragma unroll
            for (int mi = 0; mi < 4; mi++) {
                uint32_t off = aBase + (uint32_t)(mi * 16) * 128 + kOff;
                LDSM_X4(ah[mi][0], ah[mi][1], ah[mi][2], ah[mi][3], stA + SWZ(off));
            }
#pragma unroll
            for (int ni = 0; ni < 2; ni++) {
                uint32_t off = bBase + (uint32_t)(ni * 16) * 128 + kOff;
                LDSM_X4(bh[ni][0], bh[ni][1], bh[ni][2], bh[ni][3], stB + SWZ(off));
            }
            // term 1: Ahi * Bhi
#pragma unroll
            for (int mi = 0; mi < 4; mi++)
#pragma unroll
                for (int ni = 0; ni < 4; ni++) {
                    const uint32_t* bq = bh[ni >> 1];
                    int o = (ni & 1) * 2;
                    MMA16816(acc[mi][ni], ah[mi][0], ah[mi][1], ah[mi][2], ah[mi][3], bq[o], bq[o + 1]);
                }
            // term 2: Ahi * Blo  (stream B-lo fragments per ni-pair, 4 regs live)
#pragma unroll
            for (int nb = 0; nb < 2; nb++) {
                uint32_t b0, b1, b2, b3;
                uint32_t off = bBase + (uint32_t)(nb * 16) * 128 + kOff + 64;
                LDSM_X4(b0, b1, b2, b3, stB + SWZ(off));
#pragma unroll
                for (int mi = 0; mi < 4; mi++) {
                    MMA16816(acc[mi][nb * 2 + 0], ah[mi][0], ah[mi][1], ah[mi][2], ah[mi][3], b0, b1);
                    MMA16816(acc[mi][nb * 2 + 1], ah[mi][0], ah[mi][1], ah[mi][2], ah[mi][3], b2, b3);
                }
            }
            // term 3: Alo * Bhi  (stream A-lo fragments per mi, 4 regs live)
#pragma unroll
            for (int mi = 0; mi < 4; mi++) {
                uint32_t a0, a1, a2, a3;
                uint32_t off = aBase + (uint32_t)(mi * 16) * 128 + kOff + 64;
                LDSM_X4(a0, a1, a2, a3, stA + SWZ(off));
#pragma unroll
                for (int ni = 0; ni < 4; ni++) {
                    const uint32_t* bq = bh[ni >> 1];
                    int o = (ni & 1) * 2;
                    MMA16816(acc[mi][ni], a0, a1, a2, a3, bq[o], bq[o + 1]);
                }
            }
        }
        sc++; if (sc >= NSTAGE) sc = 0;
    }

    // ---- epilogue: registers -> global directly ----
    const int rowb = bm * 128 + wr * 64 + (l >> 2);
    const int colb = bn * 128 + wc * 32 + (l & 3) * 2;
#pragma unroll
    for (int mi = 0; mi < 4; mi++) {
#pragma unroll
        for (int ni = 0; ni < 4; ni++) {
            int cc = colb + ni * 8;
            if (cc < N) {
#pragma unroll
                for (int h = 0; h < 2; h++) {
                    int rr = rowb + mi * 16 + h * 8;
                    size_t off = (size_t)rr * N + cc;
                    float v0 = acc[mi][ni][h * 2 + 0];
                    float v1 = acc[mi][ni][h * 2 + 1];
                    if (EPI == 0) {
                        *(float2*)(C + off) = make_float2(v0, v1);
                    } else if (EPI == 3) {
                        *(float2*)(C + off) = make_float2(v0 + res[off], v1 + res[off + 1]);
                    } else if (EPI == 2) {
                        *(float2*)(C + off) = make_float2(v0 + bias[cc] + res[off],
                                                          v1 + bias[cc + 1] + res[off + 1]);
                    } else {
                        v0 += bias[cc];
                        v1 += bias[cc + 1];
                        v0 = 0.5f * v0 * (1.f + erff(v0 * 0.70710678118654752f));
                        v1 = 0.5f * v1 * (1.f + erff(v1 * 0.70710678118654752f));
                        float r0, r1;
                        uint32_t h2 = pack_hi2(v0, v1, r0, r1);
                        uint32_t l2 = pack2(r0, r1);
                        *(uint32_t*)(Ohi + off) = h2;
                        *(uint32_t*)(Olo + off) = l2;
                    }
                }
            }
        }
    }
}

// ---------------- dt = softplus(raw + dt_bias) ---------------------------------
__global__ void dt_kernel(const float* __restrict__ dtb)
{
    int idx = blockIdx.x * 256 + threadIdx.x;
    if (idx >= ROWS * NH) return;
    int r = idx >> 5, h = idx & 31;
    float u = g_zx[(size_t)r * DIP + (DI + CD) + h] + dtb[h];
    g_dt[idx] = (u > 20.f) ? u : log1pf(__expf(u));
}

// ---------------- tiled causal depthwise conv (width 4) + SiLU -----------------
__global__ void __launch_bounds__(128)
conv_kernel(const float* __restrict__ cw, const float* __restrict__ cb)
{
    __shared__ float sx[35][128];
    const int tid = threadIdx.x;
    const int c   = blockIdx.x * 128 + tid;     // 0..2175
    const int r0  = blockIdx.y * 32;            // global row base

    for (int idx = tid; idx < 35 * 128; idx += 128) {
        int i   = idx >> 7;
        int col = idx & 127;
        int g   = r0 - 3 + i;
        sx[i][col] = (g >= 0) ? g_zx[(size_t)g * DIP + DI + blockIdx.x * 128 + col] : 0.f;
    }
    __syncthreads();

    const float w0 = cw[c * 4 + 0], w1 = cw[c * 4 + 1], w2 = cw[c * 4 + 2], w3 = cw[c * 4 + 3];
    const float bias = cb[c];
#pragma unroll 4
    for (int i = 0; i < 32; i++) {
        int row = r0 + i;
        int l = row & (LSEQ - 1);
        float acc = bias;
        acc = fmaf(sx[i + 3][tid], w3, acc);
        if (l >= 1) acc = fmaf(sx[i + 2][tid], w2, acc);
        if (l >= 2) acc = fmaf(sx[i + 1][tid], w1, acc);
        if (l >= 3) acc = fmaf(sx[i + 0][tid], w0, acc);
        g_xbc[(size_t)row * CD + c] = acc / (1.f + __expf(-acc));
    }
}

// ---------------- sequential SSM scan ------------------------------------------
__global__ void __launch_bounds__(128)
scan_kernel(const float* __restrict__ A_log, const float* __restrict__ Dvec)
{
    const int blk = blockIdx.x;
    const int b   = blk >> 7;
    const int rem = blk & 127;
    const int h   = rem >> 2;
    const int pc  = rem & 3;
    const int p0  = pc * 16;
    const int tid = threadIdx.x;
    const int q   = tid & 7;
    const int pl  = tid >> 3;

    const float Ah = -__expf(A_log[h]);
    const float Dh = Dvec[h];

    __shared__ float sB[32][64];
    __shared__ float sC[32][64];
    __shared__ float sX[32][16];
    __shared__ float sDt[32];
    __shared__ float sDA[32];
    __shared__ float sY[32][16];

    float hh[8];
#pragma unroll
    for (int i = 0; i < 8; i++) hh[i] = 0.f;

    const size_t rowBase = (size_t)b * LSEQ;

    for (int t0 = 0; t0 < LSEQ; t0 += 32) {
        for (int idx = tid; idx < 2048; idx += 128) {
            int t = idx >> 6, n = idx & 63;
            size_t ro = (rowBase + t0 + t) * (size_t)CD;
            sB[t][n] = g_xbc[ro + DI + n];
            sC[t][n] = g_xbc[ro + DI + DS + n];
        }
        for (int idx = tid; idx < 512; idx += 128) {
            int t = idx >> 4, p = idx & 15;
            sX[t][p] = g_xbc[(rowBase + t0 + t) * (size_t)CD + h * 64 + p0 + p];
        }
        if (tid < 32) {
            float d = g_dt[(rowBase + t0 + tid) * NH + h];
            sDt[tid] = d;
            sDA[tid] = __expf(d * Ah);
        }
        __syncthreads();

#pragma unroll 8
        for (int t = 0; t < 32; t++) {
            float dtv = sDt[t];
            float dav = sDA[t];
            float xv  = sX[t][pl];
            float s   = dtv * xv;
            float4 b0 = *(const float4*)&sB[t][q * 8];
            float4 b1 = *(const float4*)&sB[t][q * 8 + 4];
            float4 c0 = *(const float4*)&sC[t][q * 8];
            float4 c1 = *(const float4*)&sC[t][q * 8 + 4];
            float yv = 0.f;
            hh[0] = fmaf(hh[0], dav, s * b0.x); yv = fmaf(hh[0], c0.x, yv);
            hh[1] = fmaf(hh[1], dav, s * b0.y); yv = fmaf(hh[1], c0.y, yv);
            hh[2] = fmaf(hh[2], dav, s * b0.z); yv = fmaf(hh[2], c0.z, yv);
            hh[3] = fmaf(hh[3], dav, s * b0.w); yv = fmaf(hh[3], c0.w, yv);
            hh[4] = fmaf(hh[4], dav, s * b1.x); yv = fmaf(hh[4], c1.x, yv);
            hh[5] = fmaf(hh[5], dav, s * b1.y); yv = fmaf(hh[5], c1.y, yv);
            hh[6] = fmaf(hh[6], dav, s * b1.z); yv = fmaf(hh[6], c1.z, yv);
            hh[7] = fmaf(hh[7], dav, s * b1.w); yv = fmaf(hh[7], c1.w, yv);
            yv += __shfl_xor_sync(0xffffffffu, yv, 4);
            yv += __shfl_xor_sync(0xffffffffu, yv, 2);
            yv += __shfl_xor_sync(0xffffffffu, yv, 1);
            if (q == 0) sY[t][pl] = fmaf(Dh, xv, yv);
        }
        __syncthreads();
        for (int idx = tid; idx < 512; idx += 128) {
            int t = idx >> 4, p = idx & 15;
            g_y[(rowBase + t0 + t) * (size_t)DI + h * 64 + p0 + p] = sY[t][p];
        }
    }
}

// ---------------- y *= silu(z); RMSNorm * norm_w -> bf16 split (vectorized) ----
__global__ void gate_rms_kernel(const float* __restrict__ nw)
{
    int r = blockIdx.x, tid = threadIdx.x;
    const float* yr = g_y + (size_t)r * DI;
    const float* zr = g_zx + (size_t)r * DIP;
    const int c0 = tid * 8;
    float4 y0 = *(const float4*)(yr + c0);
    float4 y1 = *(const float4*)(yr + c0 + 4);
    float4 z0 = *(const float4*)(zr + c0);
    float4 z1 = *(const float4*)(zr + c0 + 4);
    float v[8];
    v[0] = y0.x * (z0.x / (1.f + __expf(-z0.x)));
    v[1] = y0.y * (z0.y / (1.f + __expf(-z0.y)));
    v[2] = y0.z * (z0.z / (1.f + __expf(-z0.z)));
    v[3] = y0.w * (z0.w / (1.f + __expf(-z0.w)));
    v[4] = y1.x * (z1.x / (1.f + __expf(-z1.x)));
    v[5] = y1.y * (z1.y / (1.f + __expf(-z1.y)));
    v[6] = y1.z * (z1.z / (1.f + __expf(-z1.z)));
    v[7] = y1.w * (z1.w / (1.f + __expf(-z1.w)));
    float ss = 0.f;
#pragma unroll
    for (int i = 0; i < 8; i++) ss = fmaf(v[i], v[i], ss);
    float dummy = 0.f;
    blockReduceSum2(ss, dummy);
    float scale = rsqrtf(ss * (1.f / 2048.f) + 1e-5f);
    const float4 w0 = *(const float4*)(nw + c0);
    const float4 w1 = *(const float4*)(nw + c0 + 4);
    float o[8];
    o[0] = v[0] * scale * w0.x; o[1] = v[1] * scale * w0.y;
    o[2] = v[2] * scale * w0.z; o[3] = v[3] * scale * w0.w;
    o[4] = v[4] * scale * w1.x; o[5] = v[5] * scale * w1.y;
    o[6] = v[6] * scale * w1.z; o[7] = v[7] * scale * w1.w;
    uint4 hs, ls;
    float ra, rb, rc, rd;
    hs.x = pack_hi2(o[0], o[1], ra, rb); hs.y = pack_hi2(o[2], o[3], rc, rd);
    ls.x = pack2(ra, rb);                ls.y = pack2(rc, rd);
    hs.z = pack_hi2(o[4], o[5], ra, rb); hs.w = pack_hi2(o[6], o[7], rc, rd);
    ls.z = pack2(ra, rb);                ls.w = pack2(rc, rd);
    size_t off = (size_t)r * DI + c0;
    __nv_bfloat16* ph; __nv_bfloat16* plo;
    // direct symbol access (a2h/a2l)
    ph = a2h; plo = a2l;
    *(uint4*)(ph + off) = hs;
    *(uint4*)(plo + off) = ls;
}

// ---------------- launch --------------------------------------------------------
extern "C" void kernel_launch(void* const* d_in, const int* in_sizes, int n_in,
                              void* d_out, int out_size)
{
    const float* x       = (const float*)d_in[0];
    const float* ln1_w   = (const float*)d_in[1];
    const float* ln1_b   = (const float*)d_in[2];
    const float* in_proj = (const float*)d_in[3];
    const float* conv_w  = (const float*)d_in[4];
    const float* conv_b  = (const float*)d_in[5];
    const float* dt_bias = (const float*)d_in[6];
    const float* A_log   = (const float*)d_in[7];
    const float* Dv      = (const float*)d_in[8];
    const float* norm_w  = (const float*)d_in[9];
    const float* out_w   = (const float*)d_in[10];
    const float* ln2_w   = (const float*)d_in[11];
    const float* ln2_b   = (const float*)d_in[12];
    const float* mlp_w1  = (const float*)d_in[13];
    const float* mlp_b1  = (const float*)d_in[14];
    const float* mlp_w2  = (const float*)d_in[15];
    const float* mlp_b2  = (const float*)d_in[16];
    float* out = (float*)d_out;

    static bool attr_done = false;
    if (!attr_done) {
        cudaFuncSetAttribute(mma_gemm<0>, cudaFuncAttributeMaxDynamicSharedMemorySize, GSMEM);
        cudaFuncSetAttribute(mma_gemm<1>, cudaFuncAttributeMaxDynamicSharedMemorySize, GSMEM);
        cudaFuncSetAttribute(mma_gemm<2>, cudaFuncAttributeMaxDynamicSharedMemorySize, GSMEM);
        cudaFuncSetAttribute(mma_gemm<3>, cudaFuncAttributeMaxDynamicSharedMemorySize, GSMEM);
        attr_done = true;
    }

    float *zx, *x1;
    cudaGetSymbolAddress((void**)&zx,  g_zx);
    cudaGetSymbolAddress((void**)&x1,  g_x1);
    __nv_bfloat16 *pa1h, *pa1l, *pb1h, *pb1l, *pa2h, *pa2l, *pb2h, *pb2l;
    __nv_bfloat16 *pa3h, *pa3l, *pb3h, *pb3l, *pa4h, *pa4l, *pb4h, *pb4l;
    cudaGetSymbolAddress((void**)&pa1h, a1h); cudaGetSymbolAddress((void**)&pa1l, a1l);
    cudaGetSymbolAddress((void**)&pb1h, b1h); cudaGetSymbolAddress((void**)&pb1l, b1l);
    cudaGetSymbolAddress((void**)&pa2h, a2h); cudaGetSymbolAddress((void**)&pa2l, a2l);
    cudaGetSymbolAddress((void**)&pb2h, b2h); cudaGetSymbolAddress((void**)&pb2l, b2l);
    cudaGetSymbolAddress((void**)&pa3h, a3h); cudaGetSymbolAddress((void**)&pa3l, a3l);
    cudaGetSymbolAddress((void**)&pb3h, b3h); cudaGetSymbolAddress((void**)&pb3l, b3l);
    cudaGetSymbolAddress((void**)&pa4h, a4h); cudaGetSymbolAddress((void**)&pa4l, a4l);
    cudaGetSymbolAddress((void**)&pb4h, b4h); cudaGetSymbolAddress((void**)&pb4l, b4l);

    // 1) in_proj weight split (vectorized)
    wsplit_kernel<<<(DIPP * DM / 4 + 255) / 256, 256>>>((const float4*)in_proj, (uint2*)pb1h,
                                                        (uint2*)pb1l, DIP * DM / 4, DIPP * DM / 4);
    // 2) LN1 -> a1 (bf16 split)
    ln_kernel<<<ROWS, 256>>>(x, ln1_w, ln1_b, pa1h, pa1l);
    // 3) out_proj weight split
    wsplit_kernel<<<(DM * DI / 4 + 255) / 256, 256>>>((const float4*)out_w, (uint2*)pb2h,
                                                      (uint2*)pb2l, DM * DI / 4, DM * DI / 4);
    // 4) in_proj GEMM -> zx (fp32)   <-- ncu capture slot
    mma_gemm<0><<<dim3(DIPP / 128, ROWS / 128), 256, GSMEM>>>(pa1h, pa1l, pb1h, pb1l, DIP, DM,
                                                              zx, nullptr, nullptr, nullptr, nullptr);
    // 5) mlp weight splits (one kernel, vectorized)
    wsplit2_kernel<<<((DFF * DM + DM * DFF) / 4 + 255) / 256, 256>>>(
        (const float4*)mlp_w1, (uint2*)pb3h, (uint2*)pb3l, DFF * DM / 4,
        (const float4*)mlp_w2, (uint2*)pb4h, (uint2*)pb4l, DM * DFF / 4);
    // 6) dt
    dt_kernel<<<(ROWS * NH) / 256, 256>>>(dt_bias);
    // 7) conv + silu (tiled)
    conv_kernel<<<dim3(17, ROWS / 32), 128>>>(conv_w, conv_b);
    // 8) scan
    scan_kernel<<<256, 128>>>(A_log, Dv);
    // 9) gate + rms -> a2 (bf16 split)
    gate_rms_kernel<<<ROWS, 256>>>(norm_w);
    // 10) out_proj + residual(x) -> x1 (fp32)
    mma_gemm<3><<<dim3(DM / 128, ROWS / 128), 256, GSMEM>>>(pa2h, pa2l, pb2h, pb2l, DM, DI,
                                                            x1, nullptr, x, nullptr, nullptr);
    // 11) LN2 -> a3 (bf16 split)
    ln_kernel<<<ROWS, 256>>>(x1, ln2_w, ln2_b, pa3h, pa3l);
    // 12) MLP up + bias + GELU -> a4 (bf16 split)
    mma_gemm<1><<<dim3(DFF / 128, ROWS / 128), 256, GSMEM>>>(pa3h, pa3l, pb3h, pb3l, DFF, DM,
                                                             nullptr, mlp_b1, nullptr, pa4h, pa4l);
    // 13) MLP down + bias + residual(x1) -> out
    mma_gemm<2><<<dim3(DM / 128, ROWS / 128), 256, GSMEM>>>(pa4h, pa4l, pb4h, pb4l, DM, DFF,
                                                            out, mlp_b2, x1, nullptr, nullptr);
}

// round 13
// speedup vs baseline: 2.8712x; 1.2804x over previous
#include <cuda_runtime.h>
#include <cuda_fp16.h>
#include <math.h>
#include <cstdint>

#define ROWS 4096      // BT * L
#define LSEQ 2048
#define DM   1024
#define DI   2048
#define NH   32
#define DS   64
#define CD   2176      // conv dim = DI + 2*DS
#define DIP  4256      // in_proj out dim
#define DIPP 4352      // padded to 34*128
#define DFF  4096

// ---------------- scratch (device globals; no runtime allocation) -------------
__device__ float g_zx [(size_t)ROWS * DIP];
__device__ float g_xbc[(size_t)ROWS * CD];
__device__ float g_dt [(size_t)ROWS * NH];
__device__ float g_y  [(size_t)ROWS * DI];
__device__ float g_x1 [(size_t)ROWS * DM];

// fp16 buffers: activations hi-only; weights hi+lo
__device__ __half a1h[(size_t)ROWS * DM];                                 // LN1 out
__device__ __half b1h[(size_t)DIPP * DM], b1l[(size_t)DIPP * DM];         // in_proj w
__device__ __half a2h[(size_t)ROWS * DI];                                 // gated/rms y
__device__ __half b2h[(size_t)DM * DI],   b2l[(size_t)DM * DI];           // out_proj w
__device__ __half a3h[(size_t)ROWS * DM];                                 // LN2 out
__device__ __half b3h[(size_t)DFF * DM],  b3l[(size_t)DFF * DM];          // mlp_w1
__device__ __half a4h[(size_t)ROWS * DFF];                                // gelu(mid)
__device__ __half b4h[(size_t)DM * DFF],  b4l[(size_t)DM * DFF];          // mlp_w2

// ================= helpers =====================================================
__device__ __forceinline__ uint32_t smem_u32(const void* p) {
    uint32_t a;
    asm("{ .reg .u64 t; cvta.to.shared.u64 t, %1; cvt.u32.u64 %0, t; }" : "=r"(a) : "l"(p));
    return a;
}
#define CP_ASYNC16(dst, src) \
    asm volatile("cp.async.cg.shared.global [%0], [%1], 16;" :: "r"(dst), "l"(src) : "memory")
#define CP_COMMIT() asm volatile("cp.async.commit_group;" ::: "memory")
#define CP_WAIT(n)  asm volatile("cp.async.wait_group %0;" :: "n"(n) : "memory")

#define LDSM_X4(r0, r1, r2, r3, addr) \
    asm volatile("ldmatrix.sync.aligned.m8n8.x4.shared.b16 {%0,%1,%2,%3}, [%4];" \
        : "=r"(r0), "=r"(r1), "=r"(r2), "=r"(r3) : "r"(addr))

#define MMA16816(d, a0, a1, a2, a3, b0, b1) \
    asm volatile("mma.sync.aligned.m16n8k16.row.col.f32.f16.f16.f32 " \
        "{%0,%1,%2,%3},{%4,%5,%6,%7},{%8,%9},{%0,%1,%2,%3};" \
        : "+f"((d)[0]), "+f"((d)[1]), "+f"((d)[2]), "+f"((d)[3]) \
        : "r"(a0), "r"(a1), "r"(a2), "r"(a3), "r"(b0), "r"(b1))

#define SWZ(off) ((off) ^ (((off) >> 3) & 0x70))

__device__ __forceinline__ void blockReduceSum2(float &a, float &b) {
    __shared__ float sa[8], sb2[8];
    int lane = threadIdx.x & 31, w = threadIdx.x >> 5;
#pragma unroll
    for (int o = 16; o > 0; o >>= 1) {
        a += __shfl_xor_sync(0xffffffffu, a, o);
        b += __shfl_xor_sync(0xffffffffu, b, o);
    }
    if (lane == 0) { sa[w] = a; sb2[w] = b; }
    __syncthreads();
    a = sa[lane & 7]; b = sb2[lane & 7];
#pragma unroll
    for (int o = 4; o > 0; o >>= 1) {
        a += __shfl_xor_sync(0xffffffffu, a, o);
        b += __shfl_xor_sync(0xffffffffu, b, o);
    }
}
// pack two floats into half2 (hi), residuals out
__device__ __forceinline__ uint32_t packh_hi2(float a, float b, float &ra, float &rb) {
    __half2 h = __floats2half2_rn(a, b);
    ra = a - __low2float(h);
    rb = b - __high2float(h);
    uint32_t u; __builtin_memcpy(&u, &h, 4);
    return u;
}
__device__ __forceinline__ uint32_t packh2(float a, float b) {
    __half2 h = __floats2half2_rn(a, b);
    uint32_t u; __builtin_memcpy(&u, &h, 4);
    return u;
}

// ---------------- weight split kernel (vectorized) ------------------------------
__global__ void wsplit_kernel(const float4* __restrict__ src, uint2* __restrict__ hi,
                              uint2* __restrict__ lo, int n4, int ntot4)
{
    int i = blockIdx.x * 256 + threadIdx.x;
    if (i >= ntot4) return;
    float4 v = (i < n4) ? src[i] : make_float4(0.f, 0.f, 0.f, 0.f);
    float r0, r1, r2, r3;
    uint2 h, l;
    h.x = packh_hi2(v.x, v.y, r0, r1);
    h.y = packh_hi2(v.z, v.w, r2, r3);
    l.x = packh2(r0, r1);
    l.y = packh2(r2, r3);
    hi[i] = h;
    lo[i] = l;
}

// dual weight split (mlp_w1, mlp_w2)
__global__ void wsplit2_kernel(const float4* __restrict__ s1, uint2* __restrict__ h1,
                               uint2* __restrict__ l1, int n41,
                               const float4* __restrict__ s2, uint2* __restrict__ h2,
                               uint2* __restrict__ l2, int n42)
{
    int i = blockIdx.x * 256 + threadIdx.x;
    const float4* s; uint2 *ph, *pl; int j;
    if (i < n41) { s = s1; ph = h1; pl = l1; j = i; }
    else if (i < n41 + n42) { s = s2; ph = h2; pl = l2; j = i - n41; }
    else return;
    float4 v = s[j];
    float r0, r1, r2, r3;
    uint2 h, l;
    h.x = packh_hi2(v.x, v.y, r0, r1);
    h.y = packh_hi2(v.z, v.w, r2, r3);
    l.x = packh2(r0, r1);
    l.y = packh2(r2, r3);
    ph[j] = h;
    pl[j] = l;
}

// ---------------- layernorm -> fp16 (hi only) ----------------------------------
__global__ void ln_kernel(const float* __restrict__ in, const float* __restrict__ w,
                          const float* __restrict__ bias, __half* __restrict__ ohi)
{
    int r = blockIdx.x, tid = threadIdx.x;
    const int c0 = tid * 4;
    float4 v = *(const float4*)(in + (size_t)r * DM + c0);
    float s  = v.x + v.y + v.z + v.w;
    float sq = fmaf(v.x, v.x, fmaf(v.y, v.y, fmaf(v.z, v.z, v.w * v.w)));
    blockReduceSum2(s, sq);
    float mu  = s * (1.f / DM);
    float var = sq * (1.f / DM) - mu * mu;
    float inv = rsqrtf(var + 1e-5f);
    float4 wv = *(const float4*)(w + c0);
    float4 bv = *(const float4*)(bias + c0);
    uint2 h;
    h.x = packh2((v.x - mu) * inv * wv.x + bv.x, (v.y - mu) * inv * wv.y + bv.y);
    h.y = packh2((v.z - mu) * inv * wv.z + bv.z, (v.w - mu) * inv * wv.w + bv.w);
    *(uint2*)(ohi + (size_t)r * DM + c0) = h;
}

// ================= mma.sync fp16 GEMM (2-term weight split), 4-stage ===========
// C[M,N] = A[M,K] @ (Bh+Bl)[N,K]^T, A single fp16.
// CTA tile 128x128x32, 256 threads, warp tile 64x32, 2 CTAs/SM.
// SMEM per stage: A tile 8KB (paired rows: row r at (r>>1)*128+(r&1)*64),
//                 B tile 16KB (row n: [Bh 64B | Bl 64B]).
#define ATILEB 8192
#define BTILEB 16384
#define STAGEB (ATILEB + BTILEB)         // 24576
#define NSTAGE 4
#define GSMEM  (NSTAGE * STAGEB)         // 98304

template<int EPI>
__global__ void __launch_bounds__(256, 2)
mma_gemm(const __half* __restrict__ Ah, const __half* __restrict__ Bhi,
         const __half* __restrict__ Blo, int N, int K,
         float* __restrict__ C, const float* __restrict__ bias, const float* __restrict__ res,
         __half* __restrict__ Ohi)
{
    extern __shared__ char smem[];
    const uint32_t sbase = smem_u32(smem);
    const int tid = threadIdx.x;
    const int l   = tid & 31;
    const int wid = tid >> 5;
    const int wr  = wid >> 2;           // 0..1 : warp row (64 rows each)
    const int wc  = wid & 3;            // 0..3 : warp col (32 cols each)
    const int bn  = blockIdx.x, bm = blockIdx.y;

    const __half* baseA  = Ah  + (size_t)(bm * 128) * K;
    const __half* baseBh = Bhi + (size_t)(bn * 128) * K;
    const __half* baseBl = Blo + (size_t)(bn * 128) * K;

    // per-thread cp.async decomposition: 1536 granules/stage, 6 per thread
    const __half* csrc[6];
    uint32_t cdst[6];
#pragma unroll
    for (int t = 0; t < 6; t++) {
        int g = tid + (t << 8);          // 0..1535
        if (g < 512) {                   // A: row=g>>2, ch=g&3
            int row = g >> 2, ch = g & 3;
            uint32_t off = (uint32_t)(row >> 1) * 128 + (uint32_t)(row & 1) * 64 + ch * 16;
            cdst[t] = SWZ(off);
            csrc[t] = baseA + (size_t)row * K + ch * 8;
        } else {                         // B: row=(g-512)>>3, ch 0..7 (hi 0-3, lo 4-7)
            int gb = g - 512;
            int row = gb >> 3, ch = gb & 7;
            int hilo = ch >> 2, c = ch & 3;
            uint32_t off = ATILEB + (uint32_t)row * 128 + (uint32_t)ch * 16;
            cdst[t] = SWZ(off);
            csrc[t] = (hilo ? baseBl : baseBh) + (size_t)row * K + c * 8;
        }
    }

    const int NC = K >> 5;

    // prologue: chunks 0,1,2 -> stages 0,1,2
#pragma unroll
    for (int s = 0; s < 3; s++) {
        const uint32_t sd = sbase + s * STAGEB;
        const int k0 = s << 5;
#pragma unroll
        for (int t = 0; t < 6; t++) CP_ASYNC16(sd + cdst[t], csrc[t] + k0);
        CP_COMMIT();
    }

    float acc[4][4][4];
#pragma unroll
    for (int mi = 0; mi < 4; mi++)
#pragma unroll
        for (int ni = 0; ni < 4; ni++)
#pragma unroll
            for (int c = 0; c < 4; c++) acc[mi][ni][c] = 0.f;

    // per-lane logical offsets (bytes, unswizzled)
    const int rowA = wr * 64 + (l & 15);
    const uint32_t aBase0 = (uint32_t)(rowA >> 1) * 128 + (uint32_t)(rowA & 1) * 64
                          + (uint32_t)(l >> 4) * 16;
    const uint32_t bBase = ((uint32_t)(wc * 32 + (l & 7) + ((l >> 4) << 3))) * 128
                         + (uint32_t)((l >> 3) & 1) * 16;

    int sc = 0;
    for (int cch = 0; cch < NC; cch++) {
        if (cch < NC - 2) { CP_WAIT(2); } else { CP_WAIT(0); }
        __syncthreads();

        // issue chunk cch+3 into stage (sc+3)&3 (consumed in chunk cch-1)
        if (cch + 3 < NC) {
            const uint32_t sd = sbase + ((sc + 3) & 3) * STAGEB;
            const int k0 = (cch + 3) << 5;
#pragma unroll
            for (int t = 0; t < 6; t++) CP_ASYNC16(sd + cdst[t], csrc[t] + k0);
            CP_COMMIT();
        }

        const uint32_t stA = sbase + sc * STAGEB;
        const uint32_t stB = stA + ATILEB;
#pragma unroll
        for (int kk = 0; kk < 2; kk++) {
            const uint32_t kOff = (uint32_t)kk * 32;
            uint32_t ah[4][4], bh[2][4];
#pragma unroll
            for (int mi = 0; mi < 4; mi++) {
                uint32_t off = aBase0 + (uint32_t)mi * 1024 + kOff;
                LDSM_X4(ah[mi][0], ah[mi][1], ah[mi][2], ah[mi][3], stA + SWZ(off));
            }
#pragma unroll
            for (int ni = 0; ni < 2; ni++) {
                uint32_t off = bBase + (uint32_t)(ni * 16) * 128 + kOff;
                LDSM_X4(bh[ni][0], bh[ni][1], bh[ni][2], bh[ni][3], stB + SWZ(off));
            }
            // term 1: A * Bh
#pragma unroll
            for (int mi = 0; mi < 4; mi++)
#pragma unroll
                for (int ni = 0; ni < 4; ni++) {
                    const uint32_t* bq = bh[ni >> 1];
                    int o = (ni & 1) * 2;
                    MMA16816(acc[mi][ni], ah[mi][0], ah[mi][1], ah[mi][2], ah[mi][3], bq[o], bq[o + 1]);
                }
            // term 2: A * Bl (stream)
#pragma unroll
            for (int nb = 0; nb < 2; nb++) {
                uint32_t b0, b1, b2, b3;
                uint32_t off = bBase + (uint32_t)(nb * 16) * 128 + kOff + 64;
                LDSM_X4(b0, b1, b2, b3, stB + SWZ(off));
#pragma unroll
                for (int mi = 0; mi < 4; mi++) {
                    MMA16816(acc[mi][nb * 2 + 0], ah[mi][0], ah[mi][1], ah[mi][2], ah[mi][3], b0, b1);
                    MMA16816(acc[mi][nb * 2 + 1], ah[mi][0], ah[mi][1], ah[mi][2], ah[mi][3], b2, b3);
                }
            }
        }
        sc = (sc + 1) & 3;
    }

    // ---- epilogue ----
    const int rowb = bm * 128 + wr * 64 + (l >> 2);
    const int colb = bn * 128 + wc * 32 + (l & 3) * 2;
#pragma unroll
    for (int mi = 0; mi < 4; mi++) {
#pragma unroll
        for (int ni = 0; ni < 4; ni++) {
            int cc = colb + ni * 8;
            if (cc < N) {
#pragma unroll
                for (int h = 0; h < 2; h++) {
                    int rr = rowb + mi * 16 + h * 8;
                    size_t off = (size_t)rr * N + cc;
                    float v0 = acc[mi][ni][h * 2 + 0];
                    float v1 = acc[mi][ni][h * 2 + 1];
                    if (EPI == 0) {
                        *(float2*)(C + off) = make_float2(v0, v1);
                    } else if (EPI == 3) {
                        *(float2*)(C + off) = make_float2(v0 + res[off], v1 + res[off + 1]);
                    } else if (EPI == 2) {
                        *(float2*)(C + off) = make_float2(v0 + bias[cc] + res[off],
                                                          v1 + bias[cc + 1] + res[off + 1]);
                    } else {
                        v0 += bias[cc];
                        v1 += bias[cc + 1];
                        v0 = 0.5f * v0 * (1.f + erff(v0 * 0.70710678118654752f));
                        v1 = 0.5f * v1 * (1.f + erff(v1 * 0.70710678118654752f));
                        *(uint32_t*)(Ohi + off) = packh2(v0, v1);
                    }
                }
            }
        }
    }
}

// ---------------- dt = softplus(raw + dt_bias) ---------------------------------
__global__ void dt_kernel(const float* __restrict__ dtb)
{
    int idx = blockIdx.x * 256 + threadIdx.x;
    if (idx >= ROWS * NH) return;
    int r = idx >> 5, h = idx & 31;
    float u = g_zx[(size_t)r * DIP + (DI + CD) + h] + dtb[h];
    g_dt[idx] = (u > 20.f) ? u : log1pf(__expf(u));
}

// ---------------- tiled causal depthwise conv (width 4) + SiLU -----------------
__global__ void __launch_bounds__(128)
conv_kernel(const float* __restrict__ cw, const float* __restrict__ cb)
{
    __shared__ float sx[35][128];
    const int tid = threadIdx.x;
    const int c   = blockIdx.x * 128 + tid;     // 0..2175
    const int r0  = blockIdx.y * 32;

    for (int idx = tid; idx < 35 * 128; idx += 128) {
        int i   = idx >> 7;
        int col = idx & 127;
        int g   = r0 - 3 + i;
        sx[i][col] = (g >= 0) ? g_zx[(size_t)g * DIP + DI + blockIdx.x * 128 + col] : 0.f;
    }
    __syncthreads();

    const float w0 = cw[c * 4 + 0], w1 = cw[c * 4 + 1], w2 = cw[c * 4 + 2], w3 = cw[c * 4 + 3];
    const float bias = cb[c];
#pragma unroll 4
    for (int i = 0; i < 32; i++) {
        int row = r0 + i;
        int l = row & (LSEQ - 1);
        float acc = bias;
        acc = fmaf(sx[i + 3][tid], w3, acc);
        if (l >= 1) acc = fmaf(sx[i + 2][tid], w2, acc);
        if (l >= 2) acc = fmaf(sx[i + 1][tid], w1, acc);
        if (l >= 3) acc = fmaf(sx[i + 0][tid], w0, acc);
        g_xbc[(size_t)row * CD + c] = acc / (1.f + __expf(-acc));
    }
}

// ---------------- sequential SSM scan ------------------------------------------
__global__ void __launch_bounds__(128)
scan_kernel(const float* __restrict__ A_log, const float* __restrict__ Dvec)
{
    const int blk = blockIdx.x;
    const int b   = blk >> 7;
    const int rem = blk & 127;
    const int h   = rem >> 2;
    const int pc  = rem & 3;
    const int p0  = pc * 16;
    const int tid = threadIdx.x;
    const int q   = tid & 7;
    const int pl  = tid >> 3;

    const float Ah = -__expf(A_log[h]);
    const float Dh = Dvec[h];

    __shared__ float sB[32][64];
    __shared__ float sC[32][64];
    __shared__ float sX[32][16];
    __shared__ float sDt[32];
    __shared__ float sDA[32];
    __shared__ float sY[32][16];

    float hh[8];
#pragma unroll
    for (int i = 0; i < 8; i++) hh[i] = 0.f;

    const size_t rowBase = (size_t)b * LSEQ;

    for (int t0 = 0; t0 < LSEQ; t0 += 32) {
        for (int idx = tid; idx < 2048; idx += 128) {
            int t = idx >> 6, n = idx & 63;
            size_t ro = (rowBase + t0 + t) * (size_t)CD;
            sB[t][n] = g_xbc[ro + DI + n];
            sC[t][n] = g_xbc[ro + DI + DS + n];
        }
        for (int idx = tid; idx < 512; idx += 128) {
            int t = idx >> 4, p = idx & 15;
            sX[t][p] = g_xbc[(rowBase + t0 + t) * (size_t)CD + h * 64 + p0 + p];
        }
        if (tid < 32) {
            float d = g_dt[(rowBase + t0 + tid) * NH + h];
            sDt[tid] = d;
            sDA[tid] = __expf(d * Ah);
        }
        __syncthreads();

#pragma unroll 8
        for (int t = 0; t < 32; t++) {
            float dtv = sDt[t];
            float dav = sDA[t];
            float xv  = sX[t][pl];
            float s   = dtv * xv;
            float4 b0 = *(const float4*)&sB[t][q * 8];
            float4 b1 = *(const float4*)&sB[t][q * 8 + 4];
            float4 c0 = *(const float4*)&sC[t][q * 8];
            float4 c1 = *(const float4*)&sC[t][q * 8 + 4];
            float yv = 0.f;
            hh[0] = fmaf(hh[0], dav, s * b0.x); yv = fmaf(hh[0], c0.x, yv);
            hh[1] = fmaf(hh[1], dav, s * b0.y); yv = fmaf(hh[1], c0.y, yv);
            hh[2] = fmaf(hh[2], dav, s * b0.z); yv = fmaf(hh[2], c0.z, yv);
            hh[3] = fmaf(hh[3], dav, s * b0.w); yv = fmaf(hh[3], c0.w, yv);
            hh[4] = fmaf(hh[4], dav, s * b1.x); yv = fmaf(hh[4], c1.x, yv);
            hh[5] = fmaf(hh[5], dav, s * b1.y); yv = fmaf(hh[5], c1.y, yv);
            hh[6] = fmaf(hh[6], dav, s * b1.z); yv = fmaf(hh[6], c1.z, yv);
            hh[7] = fmaf(hh[7], dav, s * b1.w); yv = fmaf(hh[7], c1.w, yv);
            yv += __shfl_xor_sync(0xffffffffu, yv, 4);
            yv += __shfl_xor_sync(0xffffffffu, yv, 2);
            yv += __shfl_xor_sync(0xffffffffu, yv, 1);
            if (q == 0) sY[t][pl] = fmaf(Dh, xv, yv);
        }
        __syncthreads();
        for (int idx = tid; idx < 512; idx += 128) {
            int t = idx >> 4, p = idx & 15;
            g_y[(rowBase + t0 + t) * (size_t)DI + h * 64 + p0 + p] = sY[t][p];
        }
    }
}

// ---------------- y *= silu(z); RMSNorm * norm_w -> fp16 (hi only) -------------
__global__ void gate_rms_kernel(const float* __restrict__ nw)
{
    int r = blockIdx.x, tid = threadIdx.x;
    const float* yr = g_y + (size_t)r * DI;
    const float* zr = g_zx + (size_t)r * DIP;
    const int c0 = tid * 8;
    float4 y0 = *(const float4*)(yr + c0);
    float4 y1 = *(const float4*)(yr + c0 + 4);
    float4 z0 = *(const float4*)(zr + c0);
    float4 z1 = *(const float4*)(zr + c0 + 4);
    float v[8];
    v[0] = y0.x * (z0.x / (1.f + __expf(-z0.x)));
    v[1] = y0.y * (z0.y / (1.f + __expf(-z0.y)));
    v[2] = y0.z * (z0.z / (1.f + __expf(-z0.z)));
    v[3] = y0.w * (z0.w / (1.f + __expf(-z0.w)));
    v[4] = y1.x * (z1.x / (1.f + __expf(-z1.x)));
    v[5] = y1.y * (z1.y / (1.f + __expf(-z1.y)));
    v[6] = y1.z * (z1.z / (1.f + __expf(-z1.z)));
    v[7] = y1.w * (z1.w / (1.f + __expf(-z1.w)));
    float ss = 0.f;
#pragma unroll
    for (int i = 0; i < 8; i++) ss = fmaf(v[i], v[i], ss);
    float dummy = 0.f;
    blockReduceSum2(ss, dummy);
    float scale = rsqrtf(ss * (1.f / 2048.f) + 1e-5f);
    const float4 w0 = *(const float4*)(nw + c0);
    const float4 w1 = *(const float4*)(nw + c0 + 4);
    uint4 hs;
    hs.x = packh2(v[0] * scale * w0.x, v[1] * scale * w0.y);
    hs.y = packh2(v[2] * scale * w0.z, v[3] * scale * w0.w);
    hs.z = packh2(v[4] * scale * w1.x, v[5] * scale * w1.y);
    hs.w = packh2(v[6] * scale * w1.z, v[7] * scale * w1.w);
    *(uint4*)(a2h + (size_t)r * DI + c0) = hs;
}

// ---------------- launch --------------------------------------------------------
extern "C" void kernel_launch(void* const* d_in, const int* in_sizes, int n_in,
                              void* d_out, int out_size)
{
    const float* x       = (const float*)d_in[0];
    const float* ln1_w   = (const float*)d_in[1];
    const float* ln1_b   = (const float*)d_in[2];
    const float* in_proj = (const float*)d_in[3];
    const float* conv_w  = (const float*)d_in[4];
    const float* conv_b  = (const float*)d_in[5];
    const float* dt_bias = (const float*)d_in[6];
    const float* A_log   = (const float*)d_in[7];
    const float* Dv      = (const float*)d_in[8];
    const float* norm_w  = (const float*)d_in[9];
    const float* out_w   = (const float*)d_in[10];
    const float* ln2_w   = (const float*)d_in[11];
    const float* ln2_b   = (const float*)d_in[12];
    const float* mlp_w1  = (const float*)d_in[13];
    const float* mlp_b1  = (const float*)d_in[14];
    const float* mlp_w2  = (const float*)d_in[15];
    const float* mlp_b2  = (const float*)d_in[16];
    float* out = (float*)d_out;

    static bool attr_done = false;
    if (!attr_done) {
        cudaFuncSetAttribute(mma_gemm<0>, cudaFuncAttributeMaxDynamicSharedMemorySize, GSMEM);
        cudaFuncSetAttribute(mma_gemm<1>, cudaFuncAttributeMaxDynamicSharedMemorySize, GSMEM);
        cudaFuncSetAttribute(mma_gemm<2>, cudaFuncAttributeMaxDynamicSharedMemorySize, GSMEM);
        cudaFuncSetAttribute(mma_gemm<3>, cudaFuncAttributeMaxDynamicSharedMemorySize, GSMEM);
        attr_done = true;
    }

    float *zx, *x1;
    cudaGetSymbolAddress((void**)&zx,  g_zx);
    cudaGetSymbolAddress((void**)&x1,  g_x1);
    __half *pa1h, *pb1h, *pb1l, *pa2h, *pb2h, *pb2l;
    __half *pa3h, *pb3h, *pb3l, *pa4h, *pb4h, *pb4l;
    cudaGetSymbolAddress((void**)&pa1h, a1h);
    cudaGetSymbolAddress((void**)&pb1h, b1h); cudaGetSymbolAddress((void**)&pb1l, b1l);
    cudaGetSymbolAddress((void**)&pa2h, a2h);
    cudaGetSymbolAddress((void**)&pb2h, b2h); cudaGetSymbolAddress((void**)&pb2l, b2l);
    cudaGetSymbolAddress((void**)&pa3h, a3h);
    cudaGetSymbolAddress((void**)&pb3h, b3h); cudaGetSymbolAddress((void**)&pb3l, b3l);
    cudaGetSymbolAddress((void**)&pa4h, a4h);
    cudaGetSymbolAddress((void**)&pb4h, b4h); cudaGetSymbolAddress((void**)&pb4l, b4l);

    // 1) in_proj weight split
    wsplit_kernel<<<(DIPP * DM / 4 + 255) / 256, 256>>>((const float4*)in_proj, (uint2*)pb1h,
                                                        (uint2*)pb1l, DIP * DM / 4, DIPP * DM / 4);
    // 2) LN1 -> a1 (fp16)
    ln_kernel<<<ROWS, 256>>>(x, ln1_w, ln1_b, pa1h);
    // 3) out_proj weight split
    wsplit_kernel<<<(DM * DI / 4 + 255) / 256, 256>>>((const float4*)out_w, (uint2*)pb2h,
                                                      (uint2*)pb2l, DM * DI / 4, DM * DI / 4);
    // 4) in_proj GEMM -> zx (fp32)   <-- ncu capture slot
    mma_gemm<0><<<dim3(DIPP / 128, ROWS / 128), 256, GSMEM>>>(pa1h, pb1h, pb1l, DIP, DM,
                                                              zx, nullptr, nullptr, nullptr);
    // 5) mlp weight splits
    wsplit2_kernel<<<((DFF * DM + DM * DFF) / 4 + 255) / 256, 256>>>(
        (const float4*)mlp_w1, (uint2*)pb3h, (uint2*)pb3l, DFF * DM / 4,
        (const float4*)mlp_w2, (uint2*)pb4h, (uint2*)pb4l, DM * DFF / 4);
    // 6) dt
    dt_kernel<<<(ROWS * NH) / 256, 256>>>(dt_bias);
    // 7) conv + silu (tiled)
    conv_kernel<<<dim3(17, ROWS / 32), 128>>>(conv_w, conv_b);
    // 8) scan
    scan_kernel<<<256, 128>>>(A_log, Dv);
    // 9) gate + rms -> a2 (fp16)
    gate_rms_kernel<<<ROWS, 256>>>(norm_w);
    // 10) out_proj + residual(x) -> x1 (fp32)
    mma_gemm<3><<<dim3(DM / 128, ROWS / 128), 256, GSMEM>>>(pa2h, pb2h, pb2l, DM, DI,
                                                            x1, nullptr, x, nullptr);
    // 11) LN2 -> a3 (fp16)
    ln_kernel<<<ROWS, 256>>>(x1, ln2_w, ln2_b, pa3h);
    // 12) MLP up + bias + GELU -> a4 (fp16)
    mma_gemm<1><<<dim3(DFF / 128, ROWS / 128), 256, GSMEM>>>(pa3h, pb3h, pb3l, DFF, DM,
                                                             nullptr, mlp_b1, nullptr, pa4h);
    // 13) MLP down + bias + residual(x1) -> out
    mma_gemm<2><<<dim3(DM / 128, ROWS / 128), 256, GSMEM>>>(pa4h, pb4h, pb4l, DM, DFF,
                                                            out, mlp_b2, x1, nullptr);
}

// round 14
// speedup vs baseline: 3.2731x; 1.1400x over previous
#include <cuda_runtime.h>
#include <cuda_fp16.h>
#include <math.h>
#include <cstdint>

#define ROWS 4096      // BT * L
#define LSEQ 2048
#define DM   1024
#define DI   2048
#define NH   32
#define DS   64
#define CD   2176      // conv dim = DI + 2*DS
#define DIP  4256      // in_proj out dim
#define DIPP 4352      // padded to 34*128
#define DFF  4096

// ---------------- scratch (device globals; no runtime allocation) -------------
__device__ float g_zx [(size_t)ROWS * DIP];
__device__ float g_xbc[(size_t)ROWS * CD];
__device__ float g_dt [(size_t)ROWS * NH];
__device__ float g_y  [(size_t)ROWS * DI];
__device__ float g_x1 [(size_t)ROWS * DM];

// fp16 buffers: activations hi-only; weights hi+lo
__device__ __half a1h[(size_t)ROWS * DM];                                 // LN1 out
__device__ __half b1h[(size_t)DIPP * DM], b1l[(size_t)DIPP * DM];         // in_proj w
__device__ __half a2h[(size_t)ROWS * DI];                                 // gated/rms y
__device__ __half b2h[(size_t)DM * DI],   b2l[(size_t)DM * DI];           // out_proj w
__device__ __half a3h[(size_t)ROWS * DM];                                 // LN2 out
__device__ __half b3h[(size_t)DFF * DM],  b3l[(size_t)DFF * DM];          // mlp_w1
__device__ __half a4h[(size_t)ROWS * DFF];                                // gelu(mid)
__device__ __half b4h[(size_t)DM * DFF],  b4l[(size_t)DM * DFF];          // mlp_w2

// ================= helpers =====================================================
__device__ __forceinline__ uint32_t smem_u32(const void* p) {
    uint32_t a;
    asm("{ .reg .u64 t; cvta.to.shared.u64 t, %1; cvt.u32.u64 %0, t; }" : "=r"(a) : "l"(p));
    return a;
}
#define CP_ASYNC16(dst, src) \
    asm volatile("cp.async.cg.shared.global [%0], [%1], 16;" :: "r"(dst), "l"(src) : "memory")
#define CP_COMMIT() asm volatile("cp.async.commit_group;" ::: "memory")
#define CP_WAIT(n)  asm volatile("cp.async.wait_group %0;" :: "n"(n) : "memory")

#define LDSM_X4(r0, r1, r2, r3, addr) \
    asm volatile("ldmatrix.sync.aligned.m8n8.x4.shared.b16 {%0,%1,%2,%3}, [%4];" \
        : "=r"(r0), "=r"(r1), "=r"(r2), "=r"(r3) : "r"(addr))

#define MMA16816(d, a0, a1, a2, a3, b0, b1) \
    asm volatile("mma.sync.aligned.m16n8k16.row.col.f32.f16.f16.f32 " \
        "{%0,%1,%2,%3},{%4,%5,%6,%7},{%8,%9},{%0,%1,%2,%3};" \
        : "+f"((d)[0]), "+f"((d)[1]), "+f"((d)[2]), "+f"((d)[3]) \
        : "r"(a0), "r"(a1), "r"(a2), "r"(a3), "r"(b0), "r"(b1))

#define SWZ(off) ((off) ^ (((off) >> 3) & 0x70))

__device__ __forceinline__ void blockReduceSum2(float &a, float &b) {
    __shared__ float sa[8], sb2[8];
    int lane = threadIdx.x & 31, w = threadIdx.x >> 5;
#pragma unroll
    for (int o = 16; o > 0; o >>= 1) {
        a += __shfl_xor_sync(0xffffffffu, a, o);
        b += __shfl_xor_sync(0xffffffffu, b, o);
    }
    if (lane == 0) { sa[w] = a; sb2[w] = b; }
    __syncthreads();
    a = sa[lane & 7]; b = sb2[lane & 7];
#pragma unroll
    for (int o = 4; o > 0; o >>= 1) {
        a += __shfl_xor_sync(0xffffffffu, a, o);
        b += __shfl_xor_sync(0xffffffffu, b, o);
    }
}
__device__ __forceinline__ uint32_t packh_hi2(float a, float b, float &ra, float &rb) {
    __half2 h = __floats2half2_rn(a, b);
    ra = a - __low2float(h);
    rb = b - __high2float(h);
    uint32_t u; __builtin_memcpy(&u, &h, 4);
    return u;
}
__device__ __forceinline__ uint32_t packh2(float a, float b) {
    __half2 h = __floats2half2_rn(a, b);
    uint32_t u; __builtin_memcpy(&u, &h, 4);
    return u;
}

// ---------------- weight split kernel (vectorized) ------------------------------
__global__ void wsplit_kernel(const float4* __restrict__ src, uint2* __restrict__ hi,
                              uint2* __restrict__ lo, int n4, int ntot4)
{
    int i = blockIdx.x * 256 + threadIdx.x;
    if (i >= ntot4) return;
    float4 v = (i < n4) ? src[i] : make_float4(0.f, 0.f, 0.f, 0.f);
    float r0, r1, r2, r3;
    uint2 h, l;
    h.x = packh_hi2(v.x, v.y, r0, r1);
    h.y = packh_hi2(v.z, v.w, r2, r3);
    l.x = packh2(r0, r1);
    l.y = packh2(r2, r3);
    hi[i] = h;
    lo[i] = l;
}

__global__ void wsplit2_kernel(const float4* __restrict__ s1, uint2* __restrict__ h1,
                               uint2* __restrict__ l1, int n41,
                               const float4* __restrict__ s2, uint2* __restrict__ h2,
                               uint2* __restrict__ l2, int n42)
{
    int i = blockIdx.x * 256 + threadIdx.x;
    const float4* s; uint2 *ph, *pl; int j;
    if (i < n41) { s = s1; ph = h1; pl = l1; j = i; }
    else if (i < n41 + n42) { s = s2; ph = h2; pl = l2; j = i - n41; }
    else return;
    float4 v = s[j];
    float r0, r1, r2, r3;
    uint2 h, l;
    h.x = packh_hi2(v.x, v.y, r0, r1);
    h.y = packh_hi2(v.z, v.w, r2, r3);
    l.x = packh2(r0, r1);
    l.y = packh2(r2, r3);
    ph[j] = h;
    pl[j] = l;
}

// ---------------- layernorm -> fp16 (hi only) ----------------------------------
__global__ void ln_kernel(const float* __restrict__ in, const float* __restrict__ w,
                          const float* __restrict__ bias, __half* __restrict__ ohi)
{
    int r = blockIdx.x, tid = threadIdx.x;
    const int c0 = tid * 4;
    float4 v = *(const float4*)(in + (size_t)r * DM + c0);
    float s  = v.x + v.y + v.z + v.w;
    float sq = fmaf(v.x, v.x, fmaf(v.y, v.y, fmaf(v.z, v.z, v.w * v.w)));
    blockReduceSum2(s, sq);
    float mu  = s * (1.f / DM);
    float var = sq * (1.f / DM) - mu * mu;
    float inv = rsqrtf(var + 1e-5f);
    float4 wv = *(const float4*)(w + c0);
    float4 bv = *(const float4*)(bias + c0);
    uint2 h;
    h.x = packh2((v.x - mu) * inv * wv.x + bv.x, (v.y - mu) * inv * wv.y + bv.y);
    h.y = packh2((v.z - mu) * inv * wv.z + bv.z, (v.w - mu) * inv * wv.w + bv.w);
    *(uint2*)(ohi + (size_t)r * DM + c0) = h;
}

// ================= mma.sync fp16 GEMM (2-term weight split) ====================
// Pair-wise 4-stage pipeline: 2 K-chunks per wait/sync pair.
#define ATILEB 8192
#define BTILEB 16384
#define STAGEB (ATILEB + BTILEB)         // 24576
#define GSMEM  (4 * STAGEB)              // 98304

template<int EPI>
__global__ void __launch_bounds__(256, 2)
mma_gemm(const __half* __restrict__ Ah, const __half* __restrict__ Bhi,
         const __half* __restrict__ Blo, int N, int K,
         float* __restrict__ C, const float* __restrict__ bias, const float* __restrict__ res,
         __half* __restrict__ Ohi)
{
    extern __shared__ char smem[];
    const uint32_t sbase = smem_u32(smem);
    const int tid = threadIdx.x;
    const int l   = tid & 31;
    const int wid = tid >> 5;
    const int wr  = wid >> 2;
    const int wc  = wid & 3;
    const int bn  = blockIdx.x, bm = blockIdx.y;

    const __half* baseA  = Ah  + (size_t)(bm * 128) * K;
    const __half* baseBh = Bhi + (size_t)(bn * 128) * K;
    const __half* baseBl = Blo + (size_t)(bn * 128) * K;

    // per-thread cp.async decomposition: 1536 granules/stage, 6 per thread
    const __half* csrc[6];
    uint32_t cdst[6];
#pragma unroll
    for (int t = 0; t < 6; t++) {
        int g = tid + (t << 8);
        if (g < 512) {
            int row = g >> 2, ch = g & 3;
            uint32_t off = (uint32_t)(row >> 1) * 128 + (uint32_t)(row & 1) * 64 + ch * 16;
            cdst[t] = SWZ(off);
            csrc[t] = baseA + (size_t)row * K + ch * 8;
        } else {
            int gb = g - 512;
            int row = gb >> 3, ch = gb & 7;
            int hilo = ch >> 2, c = ch & 3;
            uint32_t off = ATILEB + (uint32_t)row * 128 + (uint32_t)ch * 16;
            cdst[t] = SWZ(off);
            csrc[t] = (hilo ? baseBl : baseBh) + (size_t)row * K + c * 8;
        }
    }

    const int NP = K >> 6;   // pairs of 32-chunks

    // prologue: chunks 0..3 into stages 0..3, two commit groups (pairs)
#pragma unroll
    for (int pp = 0; pp < 2; pp++) {
#pragma unroll
        for (int ch = 0; ch < 2; ch++) {
            const uint32_t sd = sbase + (pp * 2 + ch) * STAGEB;
            const int k0 = (pp * 2 + ch) << 5;
#pragma unroll
            for (int t = 0; t < 6; t++) CP_ASYNC16(sd + cdst[t], csrc[t] + k0);
        }
        CP_COMMIT();
    }

    float acc[4][4][4];
#pragma unroll
    for (int mi = 0; mi < 4; mi++)
#pragma unroll
        for (int ni = 0; ni < 4; ni++)
#pragma unroll
            for (int c = 0; c < 4; c++) acc[mi][ni][c] = 0.f;

    const int rowA = wr * 64 + (l & 15);
    const uint32_t aBase0 = (uint32_t)(rowA >> 1) * 128 + (uint32_t)(rowA & 1) * 64
                          + (uint32_t)(l >> 4) * 16;
    const uint32_t bBase = ((uint32_t)(wc * 32 + (l & 7) + ((l >> 4) << 3))) * 128
                         + (uint32_t)((l >> 3) & 1) * 16;

    for (int p = 0; p < NP; p++) {
        if (p < NP - 1) { CP_WAIT(1); } else { CP_WAIT(0); }
        __syncthreads();

        const uint32_t sb0 = (uint32_t)((p & 1) * 2);
#pragma unroll
        for (int ch = 0; ch < 2; ch++) {
            const uint32_t stA = sbase + (sb0 + ch) * STAGEB;
            const uint32_t stB = stA + ATILEB;
#pragma unroll
            for (int kk = 0; kk < 2; kk++) {
                const uint32_t kOff = (uint32_t)kk * 32;
                uint32_t ah[4][4], bh[2][4], bl[2][4];
#pragma unroll
                for (int mi = 0; mi < 4; mi++) {
                    uint32_t off = aBase0 + (uint32_t)mi * 1024 + kOff;
                    LDSM_X4(ah[mi][0], ah[mi][1], ah[mi][2], ah[mi][3], stA + SWZ(off));
                }
#pragma unroll
                for (int ni = 0; ni < 2; ni++) {
                    uint32_t off = bBase + (uint32_t)(ni * 16) * 128 + kOff;
                    LDSM_X4(bh[ni][0], bh[ni][1], bh[ni][2], bh[ni][3], stB + SWZ(off));
                }
#pragma unroll
                for (int ni = 0; ni < 2; ni++) {
                    uint32_t off = bBase + (uint32_t)(ni * 16) * 128 + kOff + 64;
                    LDSM_X4(bl[ni][0], bl[ni][1], bl[ni][2], bl[ni][3], stB + SWZ(off));
                }
                // term 1: A * Bh
#pragma unroll
                for (int mi = 0; mi < 4; mi++)
#pragma unroll
                    for (int ni = 0; ni < 4; ni++) {
                        const uint32_t* bq = bh[ni >> 1];
                        int o = (ni & 1) * 2;
                        MMA16816(acc[mi][ni], ah[mi][0], ah[mi][1], ah[mi][2], ah[mi][3], bq[o], bq[o + 1]);
                    }
                // term 2: A * Bl
#pragma unroll
                for (int mi = 0; mi < 4; mi++)
#pragma unroll
                    for (int ni = 0; ni < 4; ni++) {
                        const uint32_t* bq = bl[ni >> 1];
                        int o = (ni & 1) * 2;
                        MMA16816(acc[mi][ni], ah[mi][0], ah[mi][1], ah[mi][2], ah[mi][3], bq[o], bq[o + 1]);
                    }
            }
        }
        __syncthreads();   // all consumers done before refilling these stages

        if (p + 2 < NP) {
#pragma unroll
            for (int ch = 0; ch < 2; ch++) {
                const uint32_t sd = sbase + (sb0 + ch) * STAGEB;
                const int k0 = ((p + 2) * 2 + ch) << 5;
#pragma unroll
                for (int t = 0; t < 6; t++) CP_ASYNC16(sd + cdst[t], csrc[t] + k0);
            }
            CP_COMMIT();
        }
    }

    // ---- epilogue ----
    const int rowb = bm * 128 + wr * 64 + (l >> 2);
    const int colb = bn * 128 + wc * 32 + (l & 3) * 2;
#pragma unroll
    for (int mi = 0; mi < 4; mi++) {
#pragma unroll
        for (int ni = 0; ni < 4; ni++) {
            int cc = colb + ni * 8;
            if (cc < N) {
#pragma unroll
                for (int h = 0; h < 2; h++) {
                    int rr = rowb + mi * 16 + h * 8;
                    size_t off = (size_t)rr * N + cc;
                    float v0 = acc[mi][ni][h * 2 + 0];
                    float v1 = acc[mi][ni][h * 2 + 1];
                    if (EPI == 0) {
                        *(float2*)(C + off) = make_float2(v0, v1);
                    } else if (EPI == 3) {
                        *(float2*)(C + off) = make_float2(v0 + res[off], v1 + res[off + 1]);
                    } else if (EPI == 2) {
                        *(float2*)(C + off) = make_float2(v0 + bias[cc] + res[off],
                                                          v1 + bias[cc + 1] + res[off + 1]);
                    } else {
                        v0 += bias[cc];
                        v1 += bias[cc + 1];
                        v0 = 0.5f * v0 * (1.f + erff(v0 * 0.70710678118654752f));
                        v1 = 0.5f * v1 * (1.f + erff(v1 * 0.70710678118654752f));
                        *(uint32_t*)(Ohi + off) = packh2(v0, v1);
                    }
                }
            }
        }
    }
}

// ---------------- tiled causal conv + SiLU, with dt fused into x-block 16 ------
__global__ void __launch_bounds__(128)
conv_kernel(const float* __restrict__ cw, const float* __restrict__ cb,
            const float* __restrict__ dtb)
{
    __shared__ float sx[35][128];
    const int tid = threadIdx.x;
    const int c   = blockIdx.x * 128 + tid;
    const int r0  = blockIdx.y * 32;

    // fused dt (softplus) for this row range, done by channel-block 16
    if (blockIdx.x == 16) {
#pragma unroll
        for (int k = 0; k < 8; k++) {
            int idx = tid + k * 128;
            int r = r0 + (idx >> 5);
            int hh = idx & 31;
            float u = g_zx[(size_t)r * DIP + (DI + CD) + hh] + dtb[hh];
            g_dt[(size_t)r * NH + hh] = (u > 20.f) ? u : log1pf(__expf(u));
        }
    }

    for (int idx = tid; idx < 35 * 128; idx += 128) {
        int i   = idx >> 7;
        int col = idx & 127;
        int g   = r0 - 3 + i;
        sx[i][col] = (g >= 0) ? g_zx[(size_t)g * DIP + DI + blockIdx.x * 128 + col] : 0.f;
    }
    __syncthreads();

    const float w0 = cw[c * 4 + 0], w1 = cw[c * 4 + 1], w2 = cw[c * 4 + 2], w3 = cw[c * 4 + 3];
    const float bias = cb[c];
#pragma unroll 4
    for (int i = 0; i < 32; i++) {
        int row = r0 + i;
        int l = row & (LSEQ - 1);
        float acc = bias;
        acc = fmaf(sx[i + 3][tid], w3, acc);
        if (l >= 1) acc = fmaf(sx[i + 2][tid], w2, acc);
        if (l >= 2) acc = fmaf(sx[i + 1][tid], w1, acc);
        if (l >= 3) acc = fmaf(sx[i + 0][tid], w0, acc);
        g_xbc[(size_t)row * CD + c] = acc / (1.f + __expf(-acc));
    }
}

// ---------------- SSM scan with register-prefetch double buffer ----------------
__global__ void __launch_bounds__(128)
scan_kernel(const float* __restrict__ A_log, const float* __restrict__ Dvec)
{
    const int blk = blockIdx.x;
    const int b   = blk >> 7;
    const int rem = blk & 127;
    const int h   = rem >> 2;
    const int pc  = rem & 3;
    const int p0  = pc * 16;
    const int tid = threadIdx.x;
    const int q   = tid & 7;
    const int pl  = tid >> 3;

    const float Ah = -__expf(A_log[h]);
    const float Dh = Dvec[h];

    __shared__ float sB[2][32][64];
    __shared__ float sC[2][32][64];
    __shared__ float sX[2][32][16];
    __shared__ float sDt[2][32];
    __shared__ float sDA[2][32];

    float hh[8];
#pragma unroll
    for (int i = 0; i < 8; i++) hh[i] = 0.f;

    const size_t rowBase = (size_t)b * LSEQ;
    const int NT = LSEQ / 32;

    float rB[16], rC[16], rX[4], rD = 0.f;

    // prefetch tile 0
#pragma unroll
    for (int k = 0; k < 16; k++) {
        int idx = tid + (k << 7);
        int t = idx >> 6, n = idx & 63;
        size_t ro = (rowBase + t) * (size_t)CD;
        rB[k] = g_xbc[ro + DI + n];
        rC[k] = g_xbc[ro + DI + DS + n];
    }
#pragma unroll
    for (int k = 0; k < 4; k++) {
        int idx = tid + (k << 7);
        int t = idx >> 4, p = idx & 15;
        rX[k] = g_xbc[(rowBase + t) * (size_t)CD + h * 64 + p0 + p];
    }
    if (tid < 32) rD = g_dt[(rowBase + tid) * NH + h];

    for (int it = 0; it < NT; it++) {
        const int d = it & 1;
        // store prefetched tile into smem buffer d
#pragma unroll
        for (int k = 0; k < 16; k++) {
            int idx = tid + (k << 7);
            int t = idx >> 6, n = idx & 63;
            sB[d][t][n] = rB[k];
            sC[d][t][n] = rC[k];
        }
#pragma unroll
        for (int k = 0; k < 4; k++) {
            int idx = tid + (k << 7);
            int t = idx >> 4, p = idx & 15;
            sX[d][t][p] = rX[k];
        }
        if (tid < 32) {
            sDt[d][tid] = rD;
            sDA[d][tid] = __expf(rD * Ah);
        }
        __syncthreads();

        // prefetch tile it+1 into registers (overlaps compute below)
        if (it + 1 < NT) {
            const size_t tb = rowBase + (size_t)(it + 1) * 32;
#pragma unroll
            for (int k = 0; k < 16; k++) {
                int idx = tid + (k << 7);
                int t = idx >> 6, n = idx & 63;
                size_t ro = (tb + t) * (size_t)CD;
                rB[k] = g_xbc[ro + DI + n];
                rC[k] = g_xbc[ro + DI + DS + n];
            }
#pragma unroll
            for (int k = 0; k < 4; k++) {
                int idx = tid + (k << 7);
                int t = idx >> 4, p = idx & 15;
                rX[k] = g_xbc[(tb + t) * (size_t)CD + h * 64 + p0 + p];
            }
            if (tid < 32) rD = g_dt[(tb + tid) * NH + h];
        }

        const size_t ybase = (rowBase + (size_t)it * 32) * (size_t)DI + h * 64 + p0 + pl;
#pragma unroll 8
        for (int t = 0; t < 32; t++) {
            float dtv = sDt[d][t];
            float dav = sDA[d][t];
            float xv  = sX[d][t][pl];
            float s   = dtv * xv;
            float4 b0 = *(const float4*)&sB[d][t][q * 8];
            float4 b1 = *(const float4*)&sB[d][t][q * 8 + 4];
            float4 c0 = *(const float4*)&sC[d][t][q * 8];
            float4 c1 = *(const float4*)&sC[d][t][q * 8 + 4];
            float yv = 0.f;
            hh[0] = fmaf(hh[0], dav, s * b0.x); yv = fmaf(hh[0], c0.x, yv);
            hh[1] = fmaf(hh[1], dav, s * b0.y); yv = fmaf(hh[1], c0.y, yv);
            hh[2] = fmaf(hh[2], dav, s * b0.z); yv = fmaf(hh[2], c0.z, yv);
            hh[3] = fmaf(hh[3], dav, s * b0.w); yv = fmaf(hh[3], c0.w, yv);
            hh[4] = fmaf(hh[4], dav, s * b1.x); yv = fmaf(hh[4], c1.x, yv);
            hh[5] = fmaf(hh[5], dav, s * b1.y); yv = fmaf(hh[5], c1.y, yv);
            hh[6] = fmaf(hh[6], dav, s * b1.z); yv = fmaf(hh[6], c1.z, yv);
            hh[7] = fmaf(hh[7], dav, s * b1.w); yv = fmaf(hh[7], c1.w, yv);
            yv += __shfl_xor_sync(0xffffffffu, yv, 4);
            yv += __shfl_xor_sync(0xffffffffu, yv, 2);
            yv += __shfl_xor_sync(0xffffffffu, yv, 1);
            if (q == 0) g_y[ybase + (size_t)t * DI] = fmaf(Dh, xv, yv);
        }
    }
}

// ---------------- y *= silu(z); RMSNorm * norm_w -> fp16 -----------------------
__global__ void gate_rms_kernel(const float* __restrict__ nw)
{
    int r = blockIdx.x, tid = threadIdx.x;
    const float* yr = g_y + (size_t)r * DI;
    const float* zr = g_zx + (size_t)r * DIP;
    const int c0 = tid * 8;
    float4 y0 = *(const float4*)(yr + c0);
    float4 y1 = *(const float4*)(yr + c0 + 4);
    float4 z0 = *(const float4*)(zr + c0);
    float4 z1 = *(const float4*)(zr + c0 + 4);
    float v[8];
    v[0] = y0.x * (z0.x / (1.f + __expf(-z0.x)));
    v[1] = y0.y * (z0.y / (1.f + __expf(-z0.y)));
    v[2] = y0.z * (z0.z / (1.f + __expf(-z0.z)));
    v[3] = y0.w * (z0.w / (1.f + __expf(-z0.w)));
    v[4] = y1.x * (z1.x / (1.f + __expf(-z1.x)));
    v[5] = y1.y * (z1.y / (1.f + __expf(-z1.y)));
    v[6] = y1.z * (z1.z / (1.f + __expf(-z1.z)));
    v[7] = y1.w * (z1.w / (1.f + __expf(-z1.w)));
    float ss = 0.f;
#pragma unroll
    for (int i = 0; i < 8; i++) ss = fmaf(v[i], v[i], ss);
    float dummy = 0.f;
    blockReduceSum2(ss, dummy);
    float scale = rsqrtf(ss * (1.f / 2048.f) + 1e-5f);
    const float4 w0 = *(const float4*)(nw + c0);
    const float4 w1 = *(const float4*)(nw + c0 + 4);
    uint4 hs;
    hs.x = packh2(v[0] * scale * w0.x, v[1] * scale * w0.y);
    hs.y = packh2(v[2] * scale * w0.z, v[3] * scale * w0.w);
    hs.z = packh2(v[4] * scale * w1.x, v[5] * scale * w1.y);
    hs.w = packh2(v[6] * scale * w1.z, v[7] * scale * w1.w);
    *(uint4*)(a2h + (size_t)r * DI + c0) = hs;
}

// ---------------- launch --------------------------------------------------------
extern "C" void kernel_launch(void* const* d_in, const int* in_sizes, int n_in,
                              void* d_out, int out_size)
{
    const float* x       = (const float*)d_in[0];
    const float* ln1_w   = (const float*)d_in[1];
    const float* ln1_b   = (const float*)d_in[2];
    const float* in_proj = (const float*)d_in[3];
    const float* conv_w  = (const float*)d_in[4];
    const float* conv_b  = (const float*)d_in[5];
    const float* dt_bias = (const float*)d_in[6];
    const float* A_log   = (const float*)d_in[7];
    const float* Dv      = (const float*)d_in[8];
    const float* norm_w  = (const float*)d_in[9];
    const float* out_w   = (const float*)d_in[10];
    const float* ln2_w   = (const float*)d_in[11];
    const float* ln2_b   = (const float*)d_in[12];
    const float* mlp_w1  = (const float*)d_in[13];
    const float* mlp_b1  = (const float*)d_in[14];
    const float* mlp_w2  = (const float*)d_in[15];
    const float* mlp_b2  = (const float*)d_in[16];
    float* out = (float*)d_out;

    static bool init_done = false;
    static cudaStream_t s2;
    static cudaEvent_t e0, e1;
    if (!init_done) {
        cudaFuncSetAttribute(mma_gemm<0>, cudaFuncAttributeMaxDynamicSharedMemorySize, GSMEM);
        cudaFuncSetAttribute(mma_gemm<1>, cudaFuncAttributeMaxDynamicSharedMemorySize, GSMEM);
        cudaFuncSetAttribute(mma_gemm<2>, cudaFuncAttributeMaxDynamicSharedMemorySize, GSMEM);
        cudaFuncSetAttribute(mma_gemm<3>, cudaFuncAttributeMaxDynamicSharedMemorySize, GSMEM);
        cudaStreamCreateWithFlags(&s2, cudaStreamNonBlocking);
        cudaEventCreateWithFlags(&e0, cudaEventDisableTiming);
        cudaEventCreateWithFlags(&e1, cudaEventDisableTiming);
        init_done = true;
    }

    float *zx, *x1;
    cudaGetSymbolAddress((void**)&zx,  g_zx);
    cudaGetSymbolAddress((void**)&x1,  g_x1);
    __half *pa1h, *pb1h, *pb1l, *pa2h, *pb2h, *pb2l;
    __half *pa3h, *pb3h, *pb3l, *pa4h, *pb4h, *pb4l;
    cudaGetSymbolAddress((void**)&pa1h, a1h);
    cudaGetSymbolAddress((void**)&pb1h, b1h); cudaGetSymbolAddress((void**)&pb1l, b1l);
    cudaGetSymbolAddress((void**)&pa2h, a2h);
    cudaGetSymbolAddress((void**)&pb2h, b2h); cudaGetSymbolAddress((void**)&pb2l, b2l);
    cudaGetSymbolAddress((void**)&pa3h, a3h);
    cudaGetSymbolAddress((void**)&pb3h, b3h); cudaGetSymbolAddress((void**)&pb3l, b3l);
    cudaGetSymbolAddress((void**)&pa4h, a4h);
    cudaGetSymbolAddress((void**)&pb4h, b4h); cudaGetSymbolAddress((void**)&pb4l, b4l);

    // L1: in_proj weight split (stream 0)
    wsplit_kernel<<<(DIPP * DM / 4 + 255) / 256, 256>>>((const float4*)in_proj, (uint2*)pb1h,
                                                        (uint2*)pb1l, DIP * DM / 4, DIPP * DM / 4);
    // L2: LN1 -> a1 (fp16)
    ln_kernel<<<ROWS, 256>>>(x, ln1_w, ln1_b, pa1h);

    // fork side stream for the remaining weight splits
    cudaEventRecord(e0, 0);
    cudaStreamWaitEvent(s2, e0, 0);
    // L3 (s2): out_proj weight split
    wsplit_kernel<<<(DM * DI / 4 + 255) / 256, 256, 0, s2>>>((const float4*)out_w, (uint2*)pb2h,
                                                             (uint2*)pb2l, DM * DI / 4, DM * DI / 4);
    // L4: in_proj GEMM -> zx (fp32)   <-- ncu capture slot
    mma_gemm<0><<<dim3(DIPP / 128, ROWS / 128), 256, GSMEM>>>(pa1h, pb1h, pb1l, DIP, DM,
                                                              zx, nullptr, nullptr, nullptr);
    // L5 (s2): mlp weight splits
    wsplit2_kernel<<<((DFF * DM + DM * DFF) / 4 + 255) / 256, 256, 0, s2>>>(
        (const float4*)mlp_w1, (uint2*)pb3h, (uint2*)pb3l, DFF * DM / 4,
        (const float4*)mlp_w2, (uint2*)pb4h, (uint2*)pb4l, DM * DFF / 4);
    cudaEventRecord(e1, s2);

    // L6: conv + silu + fused dt
    conv_kernel<<<dim3(17, ROWS / 32), 128>>>(conv_w, conv_b, dt_bias);
    // L7: scan
    scan_kernel<<<256, 128>>>(A_log, Dv);
    // L8: gate + rms -> a2 (fp16)
    gate_rms_kernel<<<ROWS, 256>>>(norm_w);

    // join side stream before weight-consuming GEMMs
    cudaStreamWaitEvent(0, e1, 0);

    // L9: out_proj + residual(x) -> x1 (fp32)
    mma_gemm<3><<<dim3(DM / 128, ROWS / 128), 256, GSMEM>>>(pa2h, pb2h, pb2l, DM, DI,
                                                            x1, nullptr, x, nullptr);
    // L10: LN2 -> a3 (fp16)
    ln_kernel<<<ROWS, 256>>>(x1, ln2_w, ln2_b, pa3h);
    // L11: MLP up + bias + GELU -> a4 (fp16)
    mma_gemm<1><<<dim3(DFF / 128, ROWS / 128), 256, GSMEM>>>(pa3h, pb3h, pb3l, DFF, DM,
                                                             nullptr, mlp_b1, nullptr, pa4h);
    // L12: MLP down + bias + residual(x1) -> out
    mma_gemm<2><<<dim3(DM / 128, ROWS / 128), 256, GSMEM>>>(pa4h, pb4h, pb4l, DM, DFF,
                                                            out, mlp_b2, x1, nullptr);
}

// round 16
// speedup vs baseline: 4.4498x; 1.3595x over previous
#include <cuda_runtime.h>
#include <cuda_fp16.h>
#include <math.h>
#include <cstdint>

#define ROWS 4096      // BT * L
#define LSEQ 2048
#define DM   1024
#define DI   2048
#define NH   32
#define DS   64
#define CD   2176      // conv dim = DI + 2*DS
#define DIP  4256      // in_proj out dim
#define DIPP 4352      // padded to 34*128
#define DFF  4096

// ---------------- scratch (device globals; no runtime allocation) -------------
__device__ float g_zx [(size_t)ROWS * DIP];
__device__ float g_xbc[(size_t)ROWS * CD];
__device__ float g_dt [(size_t)ROWS * NH];
__device__ float g_y  [(size_t)ROWS * DI];
__device__ float g_x1 [(size_t)ROWS * DM];

// fp16 buffers (single precision term everywhere)
__device__ __half a1h[(size_t)ROWS * DM];          // LN1 out
__device__ __half b1h[(size_t)DIPP * DM];          // in_proj w (padded)
__device__ __half a2h[(size_t)ROWS * DI];          // gated/rms y
__device__ __half b2h[(size_t)DM * DI];            // out_proj w
__device__ __half a3h[(size_t)ROWS * DM];          // LN2 out
__device__ __half b3h[(size_t)DFF * DM];           // mlp_w1
__device__ __half a4h[(size_t)ROWS * DFF];         // gelu(mid)
__device__ __half b4h[(size_t)DM * DFF];           // mlp_w2

// ================= helpers =====================================================
__device__ __forceinline__ uint32_t smem_u32(const void* p) {
    uint32_t a;
    asm("{ .reg .u64 t; cvta.to.shared.u64 t, %1; cvt.u32.u64 %0, t; }" : "=r"(a) : "l"(p));
    return a;
}
#define CP_ASYNC16(dst, src) \
    asm volatile("cp.async.cg.shared.global [%0], [%1], 16;" :: "r"(dst), "l"(src) : "memory")
#define CP_COMMIT() asm volatile("cp.async.commit_group;" ::: "memory")
#define CP_WAIT(n)  asm volatile("cp.async.wait_group %0;" :: "n"(n) : "memory")

#define LDSM_X4(r0, r1, r2, r3, addr) \
    asm volatile("ldmatrix.sync.aligned.m8n8.x4.shared.b16 {%0,%1,%2,%3}, [%4];" \
        : "=r"(r0), "=r"(r1), "=r"(r2), "=r"(r3) : "r"(addr))

#define MMA16816(d, a0, a1, a2, a3, b0, b1) \
    asm volatile("mma.sync.aligned.m16n8k16.row.col.f32.f16.f16.f32 " \
        "{%0,%1,%2,%3},{%4,%5,%6,%7},{%8,%9},{%0,%1,%2,%3};" \
        : "+f"((d)[0]), "+f"((d)[1]), "+f"((d)[2]), "+f"((d)[3]) \
        : "r"(a0), "r"(a1), "r"(a2), "r"(a3), "r"(b0), "r"(b1))

#define SWZ(off) ((off) ^ (((off) >> 3) & 0x70))

__device__ __forceinline__ void blockReduceSum2(float &a, float &b) {
    __shared__ float sa[8], sb2[8];
    int lane = threadIdx.x & 31, w = threadIdx.x >> 5;
#pragma unroll
    for (int o = 16; o > 0; o >>= 1) {
        a += __shfl_xor_sync(0xffffffffu, a, o);
        b += __shfl_xor_sync(0xffffffffu, b, o);
    }
    if (lane == 0) { sa[w] = a; sb2[w] = b; }
    __syncthreads();
    a = sa[lane & 7]; b = sb2[lane & 7];
#pragma unroll
    for (int o = 4; o > 0; o >>= 1) {
        a += __shfl_xor_sync(0xffffffffu, a, o);
        b += __shfl_xor_sync(0xffffffffu, b, o);
    }
}
__device__ __forceinline__ uint32_t packh2(float a, float b) {
    __half2 h = __floats2half2_rn(a, b);
    uint32_t u; __builtin_memcpy(&u, &h, 4);
    return u;
}

// ---------------- weight convert kernels (fp32 -> fp16) ------------------------
__global__ void wconv_kernel(const float4* __restrict__ src, uint2* __restrict__ hi,
                             int n4, int ntot4)
{
    int i = blockIdx.x * 256 + threadIdx.x;
    if (i >= ntot4) return;
    float4 v = (i < n4) ? src[i] : make_float4(0.f, 0.f, 0.f, 0.f);
    uint2 h;
    h.x = packh2(v.x, v.y);
    h.y = packh2(v.z, v.w);
    hi[i] = h;
}

__global__ void wconv2_kernel(const float4* __restrict__ s1, uint2* __restrict__ h1, int n41,
                              const float4* __restrict__ s2, uint2* __restrict__ h2, int n42)
{
    int i = blockIdx.x * 256 + threadIdx.x;
    const float4* s; uint2* ph; int j;
    if (i < n41) { s = s1; ph = h1; j = i; }
    else if (i < n41 + n42) { s = s2; ph = h2; j = i - n41; }
    else return;
    float4 v = s[j];
    uint2 h;
    h.x = packh2(v.x, v.y);
    h.y = packh2(v.z, v.w);
    ph[j] = h;
}

// ---------------- layernorm -> fp16 --------------------------------------------
__global__ void ln_kernel(const float* __restrict__ in, const float* __restrict__ w,
                          const float* __restrict__ bias, __half* __restrict__ ohi)
{
    int r = blockIdx.x, tid = threadIdx.x;
    const int c0 = tid * 4;
    float4 v = *(const float4*)(in + (size_t)r * DM + c0);
    float s  = v.x + v.y + v.z + v.w;
    float sq = fmaf(v.x, v.x, fmaf(v.y, v.y, fmaf(v.z, v.z, v.w * v.w)));
    blockReduceSum2(s, sq);
    float mu  = s * (1.f / DM);
    float var = sq * (1.f / DM) - mu * mu;
    float inv = rsqrtf(var + 1e-5f);
    float4 wv = *(const float4*)(w + c0);
    float4 bv = *(const float4*)(bias + c0);
    uint2 h;
    h.x = packh2((v.x - mu) * inv * wv.x + bv.x, (v.y - mu) * inv * wv.y + bv.y);
    h.y = packh2((v.z - mu) * inv * wv.z + bv.z, (v.w - mu) * inv * wv.w + bv.w);
    *(uint2*)(ohi + (size_t)r * DM + c0) = h;
}

// ================= mma.sync pure-fp16 GEMM, 6-stage pipeline ===================
// C[M,N] = A[M,K] @ B[N,K]^T, both single fp16.
// CTA tile 128x128x32, 256 threads, warp tile 64x32, 2 CTAs/SM.
// SMEM per stage: A 8KB + B 8KB (paired rows: row r at (r>>1)*128+(r&1)*64).
#define ATILEB 8192
#define STAGEB 16384
#define NSTAGE 6
#define GSMEM  (NSTAGE * STAGEB)         // 98304

template<int EPI>
__global__ void __launch_bounds__(256, 2)
mma_gemm(const __half* __restrict__ Ah, const __half* __restrict__ Bh2,
         int N, int K,
         float* __restrict__ C, const float* __restrict__ bias, const float* __restrict__ res,
         __half* __restrict__ Ohi)
{
    extern __shared__ char smem[];
    const uint32_t sbase = smem_u32(smem);
    const int tid = threadIdx.x;
    const int l   = tid & 31;
    const int wid = tid >> 5;
    const int wr  = wid >> 2;
    const int wc  = wid & 3;
    const int bn  = blockIdx.x, bm = blockIdx.y;

    const __half* baseA = Ah  + (size_t)(bm * 128) * K;
    const __half* baseB = Bh2 + (size_t)(bn * 128) * K;

    // per-thread cp.async decomposition: 1024 granules/stage, 4 per thread
    const __half* csrc[4];
    uint32_t cdst[4];
#pragma unroll
    for (int t = 0; t < 4; t++) {
        int g = tid + (t << 8);           // 0..1023
        int isB = g >> 9;                 // 0: A, 1: B
        int gg  = g & 511;
        int row = gg >> 2, ch = gg & 3;
        uint32_t off = (uint32_t)isB * ATILEB
                     + (uint32_t)(row >> 1) * 128 + (uint32_t)(row & 1) * 64 + ch * 16;
        cdst[t] = SWZ(off);
        csrc[t] = (isB ? baseB : baseA) + (size_t)row * K + ch * 8;
    }

    const int NC = K >> 5;

    // prologue: chunks 0..4 -> stages 0..4
#pragma unroll
    for (int s = 0; s < 5; s++) {
        const uint32_t sd = sbase + s * STAGEB;
        const int k0 = s << 5;
#pragma unroll
        for (int t = 0; t < 4; t++) CP_ASYNC16(sd + cdst[t], csrc[t] + k0);
        CP_COMMIT();
    }

    float acc[4][4][4];
#pragma unroll
    for (int mi = 0; mi < 4; mi++)
#pragma unroll
        for (int ni = 0; ni < 4; ni++)
#pragma unroll
            for (int c = 0; c < 4; c++) acc[mi][ni][c] = 0.f;

    const int rowA = wr * 64 + (l & 15);
    const uint32_t aBase0 = (uint32_t)(rowA >> 1) * 128 + (uint32_t)(rowA & 1) * 64
                          + (uint32_t)(l >> 4) * 16;
    const int rowB = wc * 32 + (l & 7) + ((l >> 4) << 3);
    const uint32_t bBase0 = ATILEB + (uint32_t)(rowB >> 1) * 128 + (uint32_t)(rowB & 1) * 64
                          + (uint32_t)((l >> 3) & 1) * 16;

    int sc = 0;
    for (int cch = 0; cch < NC; cch++) {
        if (cch < NC - 4) { CP_WAIT(4); } else { CP_WAIT(0); }
        __syncthreads();

        // refill: chunk cch+5 into stage (sc+5)%6 (consumed at chunk cch-1)
        if (cch + 5 < NC) {
            int sn = sc + 5; if (sn >= NSTAGE) sn -= NSTAGE;
            const uint32_t sd = sbase + sn * STAGEB;
            const int k0 = (cch + 5) << 5;
#pragma unroll
            for (int t = 0; t < 4; t++) CP_ASYNC16(sd + cdst[t], csrc[t] + k0);
            CP_COMMIT();
        }

        const uint32_t st = sbase + sc * STAGEB;
#pragma unroll
        for (int kk = 0; kk < 2; kk++) {
            const uint32_t kOff = (uint32_t)kk * 32;
            uint32_t ah[4][4], bh[2][4];
#pragma unroll
            for (int mi = 0; mi < 4; mi++) {
                uint32_t off = aBase0 + (uint32_t)mi * 1024 + kOff;
                LDSM_X4(ah[mi][0], ah[mi][1], ah[mi][2], ah[mi][3], st + SWZ(off));
            }
#pragma unroll
            for (int ni = 0; ni < 2; ni++) {
                uint32_t off = bBase0 + (uint32_t)ni * 1024 + kOff;
                LDSM_X4(bh[ni][0], bh[ni][1], bh[ni][2], bh[ni][3], st + SWZ(off));
            }
#pragma unroll
            for (int mi = 0; mi < 4; mi++)
#pragma unroll
                for (int ni = 0; ni < 4; ni++) {
                    const uint32_t* bq = bh[ni >> 1];
                    int o = (ni & 1) * 2;
                    MMA16816(acc[mi][ni], ah[mi][0], ah[mi][1], ah[mi][2], ah[mi][3], bq[o], bq[o + 1]);
                }
        }
        sc++; if (sc >= NSTAGE) sc = 0;
    }

    // ---- epilogue ----
    const int rowb = bm * 128 + wr * 64 + (l >> 2);
    const int colb = bn * 128 + wc * 32 + (l & 3) * 2;
#pragma unroll
    for (int mi = 0; mi < 4; mi++) {
#pragma unroll
        for (int ni = 0; ni < 4; ni++) {
            int cc = colb + ni * 8;
            if (cc < N) {
#pragma unroll
                for (int h = 0; h < 2; h++) {
                    int rr = rowb + mi * 16 + h * 8;
                    size_t off = (size_t)rr * N + cc;
                    float v0 = acc[mi][ni][h * 2 + 0];
                    float v1 = acc[mi][ni][h * 2 + 1];
                    if (EPI == 0) {
                        *(float2*)(C + off) = make_float2(v0, v1);
                    } else if (EPI == 3) {
                        *(float2*)(C + off) = make_float2(v0 + res[off], v1 + res[off + 1]);
                    } else if (EPI == 2) {
                        *(float2*)(C + off) = make_float2(v0 + bias[cc] + res[off],
                                                          v1 + bias[cc + 1] + res[off + 1]);
                    } else {
                        v0 += bias[cc];
                        v1 += bias[cc + 1];
                        v0 = 0.5f * v0 * (1.f + erff(v0 * 0.70710678118654752f));
                        v1 = 0.5f * v1 * (1.f + erff(v1 * 0.70710678118654752f));
                        *(uint32_t*)(Ohi + off) = packh2(v0, v1);
                    }
                }
            }
        }
    }
}

// ---------------- tiled causal conv + SiLU, with dt fused into x-block 16 ------
__global__ void __launch_bounds__(128)
conv_kernel(const float* __restrict__ cw, const float* __restrict__ cb,
            const float* __restrict__ dtb)
{
    __shared__ float sx[35][128];
    const int tid = threadIdx.x;
    const int c   = blockIdx.x * 128 + tid;
    const int r0  = blockIdx.y * 32;

    if (blockIdx.x == 16) {
#pragma unroll
        for (int k = 0; k < 8; k++) {
            int idx = tid + k * 128;
            int r = r0 + (idx >> 5);
            int hh = idx & 31;
            float u = g_zx[(size_t)r * DIP + (DI + CD) + hh] + dtb[hh];
            g_dt[(size_t)r * NH + hh] = (u > 20.f) ? u : log1pf(__expf(u));
        }
    }

    for (int idx = tid; idx < 35 * 128; idx += 128) {
        int i   = idx >> 7;
        int col = idx & 127;
        int g   = r0 - 3 + i;
        sx[i][col] = (g >= 0) ? g_zx[(size_t)g * DIP + DI + blockIdx.x * 128 + col] : 0.f;
    }
    __syncthreads();

    const float w0 = cw[c * 4 + 0], w1 = cw[c * 4 + 1], w2 = cw[c * 4 + 2], w3 = cw[c * 4 + 3];
    const float bias = cb[c];
#pragma unroll 4
    for (int i = 0; i < 32; i++) {
        int row = r0 + i;
        int l = row & (LSEQ - 1);
        float acc = bias;
        acc = fmaf(sx[i + 3][tid], w3, acc);
        if (l >= 1) acc = fmaf(sx[i + 2][tid], w2, acc);
        if (l >= 2) acc = fmaf(sx[i + 1][tid], w1, acc);
        if (l >= 3) acc = fmaf(sx[i + 0][tid], w0, acc);
        g_xbc[(size_t)row * CD + c] = acc / (1.f + __expf(-acc));
    }
}

// ---------------- SSM scan with register-prefetch double buffer ----------------
__global__ void __launch_bounds__(128)
scan_kernel(const float* __restrict__ A_log, const float* __restrict__ Dvec)
{
    const int blk = blockIdx.x;
    const int b   = blk >> 7;
    const int rem = blk & 127;
    const int h   = rem >> 2;
    const int pc  = rem & 3;
    const int p0  = pc * 16;
    const int tid = threadIdx.x;
    const int q   = tid & 7;
    const int pl  = tid >> 3;

    const float Ah = -__expf(A_log[h]);
    const float Dh = Dvec[h];

    __shared__ float sB[2][32][64];
    __shared__ float sC[2][32][64];
    __shared__ float sX[2][32][16];
    __shared__ float sDt[2][32];
    __shared__ float sDA[2][32];

    float hh[8];
#pragma unroll
    for (int i = 0; i < 8; i++) hh[i] = 0.f;

    const size_t rowBase = (size_t)b * LSEQ;
    const int NT = LSEQ / 32;

    float rB[16], rC[16], rX[4], rD = 0.f;

#pragma unroll
    for (int k = 0; k < 16; k++) {
        int idx = tid + (k << 7);
        int t = idx >> 6, n = idx & 63;
        size_t ro = (rowBase + t) * (size_t)CD;
        rB[k] = g_xbc[ro + DI + n];
        rC[k] = g_xbc[ro + DI + DS + n];
    }
#pragma unroll
    for (int k = 0; k < 4; k++) {
        int idx = tid + (k << 7);
        int t = idx >> 4, p = idx & 15;
        rX[k] = g_xbc[(rowBase + t) * (size_t)CD + h * 64 + p0 + p];
    }
    if (tid < 32) rD = g_dt[(rowBase + tid) * NH + h];

    for (int it = 0; it < NT; it++) {
        const int d = it & 1;
#pragma unroll
        for (int k = 0; k < 16; k++) {
            int idx = tid + (k << 7);
            int t = idx >> 6, n = idx & 63;
            sB[d][t][n] = rB[k];
            sC[d][t][n] = rC[k];
        }
#pragma unroll
        for (int k = 0; k < 4; k++) {
            int idx = tid + (k << 7);
            int t = idx >> 4, p = idx & 15;
            sX[d][t][p] = rX[k];
        }
        if (tid < 32) {
            sDt[d][tid] = rD;
            sDA[d][tid] = __expf(rD * Ah);
        }
        __syncthreads();

        if (it + 1 < NT) {
            const size_t tb = rowBase + (size_t)(it + 1) * 32;
#pragma unroll
            for (int k = 0; k < 16; k++) {
                int idx = tid + (k << 7);
                int t = idx >> 6, n = idx & 63;
                size_t ro = (tb + t) * (size_t)CD;
                rB[k] = g_xbc[ro + DI + n];
                rC[k] = g_xbc[ro + DI + DS + n];
            }
#pragma unroll
            for (int k = 0; k < 4; k++) {
                int idx = tid + (k << 7);
                int t = idx >> 4, p = idx & 15;
                rX[k] = g_xbc[(tb + t) * (size_t)CD + h * 64 + p0 + p];
            }
            if (tid < 32) rD = g_dt[(tb + tid) * NH + h];
        }

        const size_t ybase = (rowBase + (size_t)it * 32) * (size_t)DI + h * 64 + p0 + pl;
#pragma unroll 8
        for (int t = 0; t < 32; t++) {
            float dtv = sDt[d][t];
            float dav = sDA[d][t];
            float xv  = sX[d][t][pl];
            float s   = dtv * xv;
            float4 b0 = *(const float4*)&sB[d][t][q * 8];
            float4 b1 = *(const float4*)&sB[d][t][q * 8 + 4];
            float4 c0 = *(const float4*)&sC[d][t][q * 8];
            float4 c1 = *(const float4*)&sC[d][t][q * 8 + 4];
            float yv = 0.f;
            hh[0] = fmaf(hh[0], dav, s * b0.x); yv = fmaf(hh[0], c0.x, yv);
            hh[1] = fmaf(hh[1], dav, s * b0.y); yv = fmaf(hh[1], c0.y, yv);
            hh[2] = fmaf(hh[2], dav, s * b0.z); yv = fmaf(hh[2], c0.z, yv);
            hh[3] = fmaf(hh[3], dav, s * b0.w); yv = fmaf(hh[3], c0.w, yv);
            hh[4] = fmaf(hh[4], dav, s * b1.x); yv = fmaf(hh[4], c1.x, yv);
            hh[5] = fmaf(hh[5], dav, s * b1.y); yv = fmaf(hh[5], c1.y, yv);
            hh[6] = fmaf(hh[6], dav, s * b1.z); yv = fmaf(hh[6], c1.z, yv);
            hh[7] = fmaf(hh[7], dav, s * b1.w); yv = fmaf(hh[7], c1.w, yv);
            yv += __shfl_xor_sync(0xffffffffu, yv, 4);
            yv += __shfl_xor_sync(0xffffffffu, yv, 2);
            yv += __shfl_xor_sync(0xffffffffu, yv, 1);
            if (q == 0) g_y[ybase + (size_t)t * DI] = fmaf(Dh, xv, yv);
        }
    }
}

// ---------------- y *= silu(z); RMSNorm * norm_w -> fp16 -----------------------
__global__ void gate_rms_kernel(const float* __restrict__ nw)
{
    int r = blockIdx.x, tid = threadIdx.x;
    const float* yr = g_y + (size_t)r * DI;
    const float* zr = g_zx + (size_t)r * DIP;
    const int c0 = tid * 8;
    float4 y0 = *(const float4*)(yr + c0);
    float4 y1 = *(const float4*)(yr + c0 + 4);
    float4 z0 = *(const float4*)(zr + c0);
    float4 z1 = *(const float4*)(zr + c0 + 4);
    float v[8];
    v[0] = y0.x * (z0.x / (1.f + __expf(-z0.x)));
    v[1] = y0.y * (z0.y / (1.f + __expf(-z0.y)));
    v[2] = y0.z * (z0.z / (1.f + __expf(-z0.z)));
    v[3] = y0.w * (z0.w / (1.f + __expf(-z0.w)));
    v[4] = y1.x * (z1.x / (1.f + __expf(-z1.x)));
    v[5] = y1.y * (z1.y / (1.f + __expf(-z1.y)));
    v[6] = y1.z * (z1.z / (1.f + __expf(-z1.z)));
    v[7] = y1.w * (z1.w / (1.f + __expf(-z1.w)));
    float ss = 0.f;
#pragma unroll
    for (int i = 0; i < 8; i++) ss = fmaf(v[i], v[i], ss);
    float dummy = 0.f;
    blockReduceSum2(ss, dummy);
    float scale = rsqrtf(ss * (1.f / 2048.f) + 1e-5f);
    const float4 w0 = *(const float4*)(nw + c0);
    const float4 w1 = *(const float4*)(nw + c0 + 4);
    uint4 hs;
    hs.x = packh2(v[0] * scale * w0.x, v[1] * scale * w0.y);
    hs.y = packh2(v[2] * scale * w0.z, v[3] * scale * w0.w);
    hs.z = packh2(v[4] * scale * w1.x, v[5] * scale * w1.y);
    hs.w = packh2(v[6] * scale * w1.z, v[7] * scale * w1.w);
    *(uint4*)(a2h + (size_t)r * DI + c0) = hs;
}

// ---------------- launch --------------------------------------------------------
extern "C" void kernel_launch(void* const* d_in, const int* in_sizes, int n_in,
                              void* d_out, int out_size)
{
    const float* x       = (const float*)d_in[0];
    const float* ln1_w   = (const float*)d_in[1];
    const float* ln1_b   = (const float*)d_in[2];
    const float* in_proj = (const float*)d_in[3];
    const float* conv_w  = (const float*)d_in[4];
    const float* conv_b  = (const float*)d_in[5];
    const float* dt_bias = (const float*)d_in[6];
    const float* A_log   = (const float*)d_in[7];
    const float* Dv      = (const float*)d_in[8];
    const float* norm_w  = (const float*)d_in[9];
    const float* out_w   = (const float*)d_in[10];
    const float* ln2_w   = (const float*)d_in[11];
    const float* ln2_b   = (const float*)d_in[12];
    const float* mlp_w1  = (const float*)d_in[13];
    const float* mlp_b1  = (const float*)d_in[14];
    const float* mlp_w2  = (const float*)d_in[15];
    const float* mlp_b2  = (const float*)d_in[16];
    float* out = (float*)d_out;

    static bool init_done = false;
    static cudaStream_t s2;
    static cudaEvent_t e0, e1;
    if (!init_done) {
        cudaFuncSetAttribute(mma_gemm<0>, cudaFuncAttributeMaxDynamicSharedMemorySize, GSMEM);
        cudaFuncSetAttribute(mma_gemm<1>, cudaFuncAttributeMaxDynamicSharedMemorySize, GSMEM);
        cudaFuncSetAttribute(mma_gemm<2>, cudaFuncAttributeMaxDynamicSharedMemorySize, GSMEM);
        cudaFuncSetAttribute(mma_gemm<3>, cudaFuncAttributeMaxDynamicSharedMemorySize, GSMEM);
        cudaStreamCreateWithFlags(&s2, cudaStreamNonBlocking);
        cudaEventCreateWithFlags(&e0, cudaEventDisableTiming);
        cudaEventCreateWithFlags(&e1, cudaEventDisableTiming);
        init_done = true;
    }

    float *zx, *x1;
    cudaGetSymbolAddress((void**)&zx,  g_zx);
    cudaGetSymbolAddress((void**)&x1,  g_x1);
    __half *pa1h, *pb1h, *pa2h, *pb2h, *pa3h, *pb3h, *pa4h, *pb4h;
    cudaGetSymbolAddress((void**)&pa1h, a1h);
    cudaGetSymbolAddress((void**)&pb1h, b1h);
    cudaGetSymbolAddress((void**)&pa2h, a2h);
    cudaGetSymbolAddress((void**)&pb2h, b2h);
    cudaGetSymbolAddress((void**)&pa3h, a3h);
    cudaGetSymbolAddress((void**)&pb3h, b3h);
    cudaGetSymbolAddress((void**)&pa4h, a4h);
    cudaGetSymbolAddress((void**)&pb4h, b4h);

    // L1: in_proj weight convert (stream 0)
    wconv_kernel<<<(DIPP * DM / 4 + 255) / 256, 256>>>((const float4*)in_proj, (uint2*)pb1h,
                                                       DIP * DM / 4, DIPP * DM / 4);
    // L2: LN1 -> a1 (fp16)
    ln_kernel<<<ROWS, 256>>>(x, ln1_w, ln1_b, pa1h);

    // fork side stream for remaining weight converts
    cudaEventRecord(e0, 0);
    cudaStreamWaitEvent(s2, e0, 0);
    // L3 (s2): out_proj weight convert
    wconv_kernel<<<(DM * DI / 4 + 255) / 256, 256, 0, s2>>>((const float4*)out_w, (uint2*)pb2h,
                                                            DM * DI / 4, DM * DI / 4);
    // L4: in_proj GEMM -> zx (fp32)   <-- ncu capture slot
    mma_gemm<0><<<dim3(DIPP / 128, ROWS / 128), 256, GSMEM>>>(pa1h, pb1h, DIP, DM,
                                                              zx, nullptr, nullptr, nullptr);
    // L5 (s2): mlp weight converts
    wconv2_kernel<<<((DFF * DM + DM * DFF) / 4 + 255) / 256, 256, 0, s2>>>(
        (const float4*)mlp_w1, (uint2*)pb3h, DFF * DM / 4,
        (const float4*)mlp_w2, (uint2*)pb4h, DM * DFF / 4);
    cudaEventRecord(e1, s2);

    // L6: conv + silu + fused dt
    conv_kernel<<<dim3(17, ROWS / 32), 128>>>(conv_w, conv_b, dt_bias);
    // L7: scan
    scan_kernel<<<256, 128>>>(A_log, Dv);
    // L8: gate + rms -> a2 (fp16)
    gate_rms_kernel<<<ROWS, 256>>>(norm_w);

    // join side stream before weight-consuming GEMMs
    cudaStreamWaitEvent(0, e1, 0);

    // L9: out_proj + residual(x) -> x1 (fp32)
    mma_gemm<3><<<dim3(DM / 128, ROWS / 128), 256, GSMEM>>>(pa2h, pb2h, DM, DI,
                                                            x1, nullptr, x, nullptr);
    // L10: LN2 -> a3 (fp16)
    ln_kernel<<<ROWS, 256>>>(x1, ln2_w, ln2_b, pa3h);
    // L11: MLP up + bias + GELU -> a4 (fp16)
    mma_gemm<1><<<dim3(DFF / 128, ROWS / 128), 256, GSMEM>>>(pa3h, pb3h, DFF, DM,
                                                             nullptr, mlp_b1, nullptr, pa4h);
    // L12: MLP down + bias + residual(x1) -> out
    mma_gemm<2><<<dim3(DM / 128, ROWS / 128), 256, GSMEM>>>(pa4h, pb4h, DM, DFF,
                                                            out, mlp_b2, x1, nullptr);
}